// round 10
// baseline (speedup 1.0000x reference)
#include <cuda_runtime.h>
#include <cuda_bf16.h>
#include <cuda_fp16.h>
#include <math.h>

// ---------------------------------------------------------------------------
// GPT_3959959847300 round 10: R9 + head GEMM retiled to 128x256 (warp 64x64)
// for a 4:1 MMA:ldmatrix issue mix. Numerics unchanged everywhere.
// ---------------------------------------------------------------------------

#define BSZ    2
#define TLEN   1024
#define CDIM   512
#define NHEAD  8
#define HD     64
#define NLAYER 4
#define VOCAB  50257
#define RANK   8
#define LSCALE 4.0f
#define MTOK   (BSZ*TLEN)
#define NBATCH (BSZ*NHEAD)

// ======================== PTX helpers ========================================
__device__ __forceinline__ unsigned smem_u32(const void* p) {
    unsigned a;
    asm("{ .reg .u64 t; cvta.to.shared.u64 t, %1; cvt.u32.u64 %0, t; }" : "=r"(a) : "l"(p));
    return a;
}
__device__ __forceinline__ void ldmx4(unsigned* r, unsigned addr) {
    asm volatile("ldmatrix.sync.aligned.m8n8.x4.shared.b16 {%0,%1,%2,%3}, [%4];"
                 : "=r"(r[0]), "=r"(r[1]), "=r"(r[2]), "=r"(r[3]) : "r"(addr));
}
__device__ __forceinline__ void mma16816(float* d, const unsigned* a, const unsigned* b) {
    asm volatile(
        "mma.sync.aligned.m16n8k16.row.col.f32.bf16.bf16.f32 "
        "{%0,%1,%2,%3},{%4,%5,%6,%7},{%8,%9},{%0,%1,%2,%3};"
        : "+f"(d[0]), "+f"(d[1]), "+f"(d[2]), "+f"(d[3])
        : "r"(a[0]), "r"(a[1]), "r"(a[2]), "r"(a[3]), "r"(b[0]), "r"(b[1]));
}
__device__ __forceinline__ void mma16816h(float* d, const unsigned* a, const unsigned* b) {
    asm volatile(
        "mma.sync.aligned.m16n8k16.row.col.f32.f16.f16.f32 "
        "{%0,%1,%2,%3},{%4,%5,%6,%7},{%8,%9},{%0,%1,%2,%3};"
        : "+f"(d[0]), "+f"(d[1]), "+f"(d[2]), "+f"(d[3])
        : "r"(a[0]), "r"(a[1]), "r"(a[2]), "r"(a[3]), "r"(b[0]), "r"(b[1]));
}
__device__ __forceinline__ void cp16(unsigned dst, const void* src, bool pred) {
    int sz = pred ? 16 : 0;
    asm volatile("cp.async.cg.shared.global [%0], [%1], 16, %2;"
                 :: "r"(dst), "l"(src), "r"(sz) : "memory");
}
#define CP_COMMIT()  asm volatile("cp.async.commit_group;" ::: "memory")
#define CP_WAIT_1()  asm volatile("cp.async.wait_group 1;" ::: "memory")
#define CP_WAIT_0()  asm volatile("cp.async.wait_group 0;" ::: "memory")

__device__ __forceinline__ void bsplit(float x, __nv_bfloat16& hi, __nv_bfloat16& lo) {
    hi = __float2bfloat16(x);
    lo = __float2bfloat16(x - __bfloat162float(hi));
}
__device__ __forceinline__ unsigned packbf(float a, float b) {
    __nv_bfloat162 t = __floats2bfloat162_rn(a, b);
    return reinterpret_cast<unsigned&>(t);
}

// ======================== scratch ============================================
__device__ float g_X  [MTOK*CDIM];
__device__ float g_YH [NBATCH*TLEN*HD];
__device__ float g_TMP[MTOK*RANK];
__device__ int   g_idx32;

__device__ __nv_bfloat16 g_wqkv_h[NLAYER*3*CDIM*CDIM], g_wqkv_l[NLAYER*3*CDIM*CDIM];
__device__ __nv_bfloat16 g_wproj_h[NLAYER*CDIM*CDIM],  g_wproj_l[NLAYER*CDIM*CDIM];
__device__ __nv_bfloat16 g_wfc_h [NLAYER*4*CDIM*CDIM], g_wfc_l [NLAYER*4*CDIM*CDIM];
__device__ __nv_bfloat16 g_wmp_h [NLAYER*CDIM*4*CDIM], g_wmp_l [NLAYER*CDIM*4*CDIM];
__device__ __half        g_whead16[VOCAB*CDIM];
__device__ __nv_bfloat16 g_Hh[MTOK*CDIM],  g_Hl[MTOK*CDIM];
__device__ __half        g_H16[MTOK*CDIM];
__device__ __nv_bfloat16 g_Yhb[MTOK*CDIM], g_Ylb[MTOK*CDIM];
__device__ __nv_bfloat16 g_FCGh[MTOK*4*CDIM], g_FCGl[MTOK*4*CDIM];
__device__ __nv_bfloat16 g_Qh[NBATCH*TLEN*HD], g_Ql[NBATCH*TLEN*HD];
__device__ __nv_bfloat16 g_Kh[NBATCH*TLEN*HD], g_Kl[NBATCH*TLEN*HD];
__device__ __nv_bfloat16 g_Vth[NBATCH*HD*TLEN], g_Vtl[NBATCH*HD*TLEN];

// ======================== common tile helpers ================================
#define TILE_B    16384                 // 128x64 16-bit tile (128B rows, swizzled)
#define STAGE_B   (4*TILE_B)
#define GEMM_SMEM (2*STAGE_B)           // 131072
#define HSTAGE_B  (3*TILE_B)            // head: A 16K + B 32K (256 rows)
#define GEMM_SMEM_F16 (2*HSTAGE_B)      // 98304

__device__ __forceinline__ unsigned swz(int row, int colB) {
    unsigned o = (unsigned)(row * 128 + colB);
    return o ^ ((unsigned)(row & 7) << 4);
}

__device__ __forceinline__ void stage_load(
    unsigned sbase,
    const __nv_bfloat16* __restrict__ ah, const __nv_bfloat16* __restrict__ al,
    const __nv_bfloat16* __restrict__ bh, const __nv_bfloat16* __restrict__ bl,
    int m0, int n0, int M, int N, int K, int k0, int lr, int lcB)
{
    {
        int gr = m0 + lr; bool ok = (gr < M); int r = ok ? gr : 0;
        const char* pa = (const char*)(ah + (size_t)r * K + k0) + lcB;
        const char* pl = (const char*)(al + (size_t)r * K + k0) + lcB;
        #pragma unroll
        for (int j = 0; j < 4; j++) {
            unsigned o = swz(lr, lcB + 16*j);
            cp16(sbase + o,          pa + 16*j, ok);
            cp16(sbase + TILE_B + o, pl + 16*j, ok);
        }
    }
    {
        int gr = n0 + lr; bool ok = (gr < N); int r = ok ? gr : 0;
        const char* pb = (const char*)(bh + (size_t)r * K + k0) + lcB;
        const char* pl = (const char*)(bl + (size_t)r * K + k0) + lcB;
        #pragma unroll
        for (int j = 0; j < 4; j++) {
            unsigned o = swz(lr, lcB + 16*j);
            cp16(sbase + 2*TILE_B + o, pb + 16*j, ok);
            cp16(sbase + 3*TILE_B + o, pl + 16*j, ok);
        }
    }
}

// ======================== bf16 3-term dense GEMM =============================
// MODE: 1 gelu->bf16 split; 2 residual +=; 3 qkv scatter split
template<int MODE>
__global__ __launch_bounds__(256, 1)
void mma_gemm(const __nv_bfloat16* __restrict__ Ah, const __nv_bfloat16* __restrict__ Al,
              const __nv_bfloat16* __restrict__ Bh, const __nv_bfloat16* __restrict__ Bl,
              const float* __restrict__ bias,
              const float* __restrict__ loraT, const float* __restrict__ loraB,
              float* __restrict__ Cm,
              int M, int N, int K)
{
    extern __shared__ char smem_raw[];
    const int m0 = blockIdx.x * 128;
    const int n0 = blockIdx.y * 128;

    const unsigned sbase = smem_u32(smem_raw);
    const int tid  = threadIdx.x;
    const int lane = tid & 31;
    const int wid  = tid >> 5;
    const int wm   = wid & 1;
    const int wn   = wid >> 1;
    const int lr   = tid >> 1;
    const int lcB  = (tid & 1) << 6;

    float acc[4][4][4];
    #pragma unroll
    for (int i = 0; i < 4; i++)
        #pragma unroll
        for (int j = 0; j < 4; j++)
            #pragma unroll
            for (int t = 0; t < 4; t++) acc[i][j][t] = 0.f;

    const int nc = K >> 6;

    stage_load(sbase, Ah, Al, Bh, Bl, m0, n0, M, N, K, 0, lr, lcB);
    CP_COMMIT();

    const int a_rin  = lane & 15;
    const int a_cB   = (lane >> 4) * 16;
    const int b_sel  = lane >> 3;
    const int b_rin  = (b_sel >> 1) * 8 + (lane & 7);
    const int b_cB   = (b_sel & 1) * 16;

    for (int cI = 0; cI < nc; ++cI) {
        const int s = cI & 1;
        if (cI + 1 < nc) {
            stage_load(sbase + (unsigned)(1 - s) * STAGE_B, Ah, Al, Bh, Bl,
                       m0, n0, M, N, K, (cI + 1) << 6, lr, lcB);
            CP_COMMIT();
            CP_WAIT_1();
        } else {
            CP_WAIT_0();
        }
        __syncthreads();

        const unsigned st = sbase + (unsigned)s * STAGE_B;
        #pragma unroll
        for (int ks = 0; ks < 4; ++ks) {
            unsigned ra_h[4][4], ra_l[4][4], rb_h[4][2], rb_l[4][2];
            #pragma unroll
            for (int i = 0; i < 4; ++i) {
                int row = wm*64 + i*16 + a_rin;
                unsigned o = swz(row, ks*32 + a_cB);
                ldmx4(ra_h[i], st + o);
                ldmx4(ra_l[i], st + TILE_B + o);
            }
            #pragma unroll
            for (int jp = 0; jp < 2; ++jp) {
                int row = wn*32 + jp*16 + b_rin;
                unsigned o = swz(row, ks*32 + b_cB);
                unsigned r[4];
                ldmx4(r, st + 2*TILE_B + o);
                rb_h[2*jp][0] = r[0]; rb_h[2*jp][1] = r[1];
                rb_h[2*jp+1][0] = r[2]; rb_h[2*jp+1][1] = r[3];
                ldmx4(r, st + 3*TILE_B + o);
                rb_l[2*jp][0] = r[0]; rb_l[2*jp][1] = r[1];
                rb_l[2*jp+1][0] = r[2]; rb_l[2*jp+1][1] = r[3];
            }
            #pragma unroll
            for (int i = 0; i < 4; ++i)
                #pragma unroll
                for (int j = 0; j < 4; ++j) {
                    mma16816(acc[i][j], ra_h[i], rb_h[j]);
                    mma16816(acc[i][j], ra_l[i], rb_h[j]);
                    mma16816(acc[i][j], ra_h[i], rb_l[j]);
                }
        }
        __syncthreads();
    }

    const int group = lane >> 2, tig = lane & 3;
    #pragma unroll
    for (int i = 0; i < 4; ++i) {
        int m_lo = m0 + wm*64 + i*16 + group;
        #pragma unroll
        for (int j = 0; j < 4; ++j) {
            int nA = n0 + wn*32 + j*8 + tig*2;
            #pragma unroll
            for (int h = 0; h < 2; ++h) {
                int m = m_lo + h*8;
                if (m >= M) continue;
                #pragma unroll
                for (int e = 0; e < 2; ++e) {
                    int n = nA + e;
                    if (n >= N) continue;
                    float v = acc[i][j][h*2 + e];
                    if (bias)  v += bias[n];
                    if ((MODE == 2 || MODE == 3) && loraT) {
                        const float* t  = loraT + (size_t)m * RANK;
                        const float* bb = loraB + (size_t)n * RANK;
                        float s = 0.f;
                        #pragma unroll
                        for (int r = 0; r < RANK; r++) s += t[r] * bb[r];
                        v += LSCALE * s;
                    }
                    if (MODE == 2) {
                        Cm[(long long)m * N + n] += v;
                    } else if (MODE == 1) {
                        float gv = 0.5f * v * (1.f + tanhf(0.7978845608028654f * (v + 0.044715f * v*v*v)));
                        __nv_bfloat16 hi, lo; bsplit(gv, hi, lo);
                        g_FCGh[(long long)m * N + n] = hi;
                        g_FCGl[(long long)m * N + n] = lo;
                    } else { // MODE 3: qkv scatter split
                        int b  = m >> 10;
                        int t  = m & (TLEN - 1);
                        int sec = n >> 9;
                        int cc  = n & 511;
                        int hh  = cc >> 6, d = cc & 63;
                        __nv_bfloat16 hi, lo; bsplit(v, hi, lo);
                        if (sec == 2) {
                            long long vi = (((long long)(b*NHEAD + hh)) * HD + d) * TLEN + t;
                            g_Vth[vi] = hi; g_Vtl[vi] = lo;
                        } else {
                            long long qi = (((long long)(b*NHEAD + hh)) * TLEN + t) * HD + d;
                            if (sec == 0) { g_Qh[qi] = hi; g_Ql[qi] = lo; }
                            else          { g_Kh[qi] = hi; g_Kl[qi] = lo; }
                        }
                    }
                }
            }
        }
    }
}

// ======================== fp16 1-MMA head GEMM (128x256 tile) ================
// Warp tile 64x64: per k-step 8 ldmatrix + 32 HMMA.
__global__ __launch_bounds__(256, 1)
void mma_gemm_f16(const __half* __restrict__ Am, const __half* __restrict__ Bm,
                  float* __restrict__ Cm, int M, int N, int K)
{
    extern __shared__ char smem_raw[];
    const int m0 = blockIdx.x * 128;
    const int n0 = blockIdx.y * 256;

    const unsigned sbase = smem_u32(smem_raw);
    const int tid  = threadIdx.x;
    const int lane = tid & 31;
    const int wid  = tid >> 5;
    const int wm   = wid & 1;        // M offset 0/64
    const int wn   = wid >> 1;       // N offset 0/64/128/192

    float acc[4][8][4];
    #pragma unroll
    for (int i = 0; i < 4; i++)
        #pragma unroll
        for (int j = 0; j < 8; j++)
            #pragma unroll
            for (int t = 0; t < 4; t++) acc[i][j][t] = 0.f;

    const int nc = K >> 6;

    // loaders: A 128 rows x 128B (2 threads/row, 4x16B each);
    //          B 256 rows x 128B (1 thread/row, 8x16B each)
    const int lrA  = tid >> 1;
    const int lcA  = (tid & 1) << 6;

    auto stage2 = [&](unsigned sb, int k0) {
        {
            int gr = m0 + lrA; bool ok = (gr < M); int r = ok ? gr : 0;
            const char* pa = (const char*)(Am + (size_t)r * K + k0) + lcA;
            #pragma unroll
            for (int j = 0; j < 4; j++) {
                unsigned o = swz(lrA, lcA + 16*j);
                cp16(sb + o, pa + 16*j, ok);
            }
        }
        {
            int gn = n0 + tid; bool ok = (gn < N); int r = ok ? gn : 0;
            const char* pb = (const char*)(Bm + (size_t)r * K + k0);
            #pragma unroll
            for (int j = 0; j < 8; j++) {
                unsigned o = swz(tid, 16*j);
                cp16(sb + TILE_B + o, pb + 16*j, ok);
            }
        }
    };

    stage2(sbase, 0);
    CP_COMMIT();

    const int a_rin  = lane & 15;
    const int a_cB   = (lane >> 4) * 16;
    const int b_sel  = lane >> 3;
    const int b_rin  = (b_sel >> 1) * 8 + (lane & 7);
    const int b_cB   = (b_sel & 1) * 16;

    for (int cI = 0; cI < nc; ++cI) {
        const int s = cI & 1;
        if (cI + 1 < nc) {
            stage2(sbase + (unsigned)(1 - s) * HSTAGE_B, (cI + 1) << 6);
            CP_COMMIT();
            CP_WAIT_1();
        } else {
            CP_WAIT_0();
        }
        __syncthreads();

        const unsigned st = sbase + (unsigned)s * HSTAGE_B;
        #pragma unroll
        for (int ks = 0; ks < 4; ++ks) {
            unsigned ra[4][4], rb[8][2];
            #pragma unroll
            for (int i = 0; i < 4; ++i) {
                int row = wm*64 + i*16 + a_rin;
                unsigned o = swz(row, ks*32 + a_cB);
                ldmx4(ra[i], st + o);
            }
            #pragma unroll
            for (int jp = 0; jp < 4; ++jp) {
                int row = wn*64 + jp*16 + b_rin;
                unsigned o = swz(row, ks*32 + b_cB);
                unsigned r[4];
                ldmx4(r, st + TILE_B + o);
                rb[2*jp][0] = r[0]; rb[2*jp][1] = r[1];
                rb[2*jp+1][0] = r[2]; rb[2*jp+1][1] = r[3];
            }
            #pragma unroll
            for (int i = 0; i < 4; ++i)
                #pragma unroll
                for (int j = 0; j < 8; ++j)
                    mma16816h(acc[i][j], ra[i], rb[j]);
        }
        __syncthreads();
    }

    const int group = lane >> 2, tig = lane & 3;
    #pragma unroll
    for (int i = 0; i < 4; ++i) {
        int m_lo = m0 + wm*64 + i*16 + group;
        #pragma unroll
        for (int j = 0; j < 8; ++j) {
            int nA = n0 + wn*64 + j*8 + tig*2;
            #pragma unroll
            for (int h = 0; h < 2; ++h) {
                int m = m_lo + h*8;
                if (m >= M) continue;
                float* crow = Cm + (long long)m * N;
                #pragma unroll
                for (int e = 0; e < 2; ++e) {
                    int n = nA + e;
                    if (n < N) crow[n] = acc[i][j][h*2 + e];
                }
            }
        }
    }
}

// ======================== fused flash attention ==============================
#define FA_QTILE 16384
#define FA_STAGE 65536
#define FA_SMEM  (2*FA_QTILE + 2*FA_STAGE)   // 163840

__global__ __launch_bounds__(256, 1)
void flash_attn(const __nv_bfloat16* __restrict__ Qh, const __nv_bfloat16* __restrict__ Ql,
                const __nv_bfloat16* __restrict__ Kh, const __nv_bfloat16* __restrict__ Kl,
                const __nv_bfloat16* __restrict__ Vth, const __nv_bfloat16* __restrict__ Vtl,
                float* __restrict__ YH)
{
    extern __shared__ char smem_raw[];
    const unsigned sbase = smem_u32(smem_raw);
    const int m0 = blockIdx.x * 128;
    const int bh = blockIdx.y;
    const int tid = threadIdx.x;
    const int lane = tid & 31;
    const int wid = tid >> 5;

    const __nv_bfloat16* qh  = Qh  + (size_t)bh * TLEN * HD;
    const __nv_bfloat16* ql  = Ql  + (size_t)bh * TLEN * HD;
    const __nv_bfloat16* kh  = Kh  + (size_t)bh * TLEN * HD;
    const __nv_bfloat16* kl  = Kl  + (size_t)bh * TLEN * HD;
    const __nv_bfloat16* vth = Vth + (size_t)bh * HD * TLEN;
    const __nv_bfloat16* vtl = Vtl + (size_t)bh * HD * TLEN;

    const unsigned sQ = sbase;
    const unsigned sStage = sbase + 2*FA_QTILE;

    {
        int lr = tid >> 1, lcB = (tid & 1) << 6;
        const char* pqh = (const char*)(qh + (size_t)(m0 + lr) * HD) + lcB;
        const char* pql = (const char*)(ql + (size_t)(m0 + lr) * HD) + lcB;
        #pragma unroll
        for (int j = 0; j < 4; j++) {
            unsigned o = swz(lr, lcB + 16*j);
            cp16(sQ + o,            pqh + 16*j, true);
            cp16(sQ + FA_QTILE + o, pql + 16*j, true);
        }
    }
    CP_COMMIT();

    const int nkb = blockIdx.x + 1;

    auto load_stage = [&](int kb, int s) {
        unsigned st = sStage + (unsigned)s * FA_STAGE;
        int lr = tid >> 1, lcB = (tid & 1) << 6;
        const char* pkh = (const char*)(kh + (size_t)(kb*128 + lr) * HD) + lcB;
        const char* pkl = (const char*)(kl + (size_t)(kb*128 + lr) * HD) + lcB;
        #pragma unroll
        for (int j = 0; j < 4; j++) {
            unsigned o = swz(lr, lcB + 16*j);
            cp16(st + o,         pkh + 16*j, true);
            cp16(st + 16384 + o, pkl + 16*j, true);
        }
        int vr = tid >> 2, vc = (tid & 3) << 5;
        #pragma unroll
        for (int c = 0; c < 2; c++) {
            const char* pvh = (const char*)(vth + (size_t)vr * TLEN + kb*128 + c*64) + vc;
            const char* pvl = (const char*)(vtl + (size_t)vr * TLEN + kb*128 + c*64) + vc;
            unsigned vb = st + 32768 + (unsigned)c * 8192;
            #pragma unroll
            for (int j = 0; j < 2; j++) {
                unsigned o = swz(vr, vc + 16*j);
                cp16(vb + o,         pvh + 16*j, true);
                cp16(vb + 16384 + o, pvl + 16*j, true);
            }
        }
    };

    load_stage(0, 0);
    CP_COMMIT();
    CP_WAIT_1();
    __syncthreads();

    unsigned qfh[4][4], qfl[4][4];
    const int a_rin = lane & 15, a_cB = (lane >> 4) * 16;
    #pragma unroll
    for (int ks = 0; ks < 4; ks++) {
        unsigned o = swz(wid*16 + a_rin, ks*32 + a_cB);
        ldmx4(qfh[ks], sQ + o);
        ldmx4(qfl[ks], sQ + FA_QTILE + o);
    }

    float O[8][4];
    #pragma unroll
    for (int i = 0; i < 8; i++)
        #pragma unroll
        for (int t = 0; t < 4; t++) O[i][t] = 0.f;
    float mrun0 = -1e30f, mrun1 = -1e30f, lrun0 = 0.f, lrun1 = 0.f;

    const int b_sel = lane >> 3;
    const int b_rin = (b_sel >> 1)*8 + (lane & 7);
    const int b_cB  = (b_sel & 1)*16;
    const int g = lane >> 2, tig = lane & 3;

    for (int kb = 0; kb < nkb; kb++) {
        if (kb + 1 < nkb) { load_stage(kb + 1, (kb + 1) & 1); CP_COMMIT(); CP_WAIT_1(); }
        else CP_WAIT_0();
        __syncthreads();
        const unsigned st = sStage + (unsigned)(kb & 1) * FA_STAGE;

        float S[16][4];
        #pragma unroll
        for (int j = 0; j < 16; j++)
            #pragma unroll
            for (int t = 0; t < 4; t++) S[j][t] = 0.f;

        #pragma unroll
        for (int ks = 0; ks < 4; ks++) {
            #pragma unroll
            for (int jp = 0; jp < 8; jp++) {
                unsigned o = swz(jp*16 + b_rin, ks*32 + b_cB);
                unsigned rh[4], rl[4];
                ldmx4(rh, st + o);
                ldmx4(rl, st + 16384 + o);
                unsigned bh0[2] = {rh[0], rh[1]}, bh1[2] = {rh[2], rh[3]};
                unsigned bl0[2] = {rl[0], rl[1]}, bl1[2] = {rl[2], rl[3]};
                mma16816(S[2*jp],   qfh[ks], bh0);
                mma16816(S[2*jp],   qfl[ks], bh0);
                mma16816(S[2*jp],   qfh[ks], bl0);
                mma16816(S[2*jp+1], qfh[ks], bh1);
                mma16816(S[2*jp+1], qfl[ks], bh1);
                mma16816(S[2*jp+1], qfh[ks], bl1);
            }
        }
        #pragma unroll
        for (int j = 0; j < 16; j++)
            #pragma unroll
            for (int t = 0; t < 4; t++) S[j][t] *= 0.125f;

        if (kb == nkb - 1) {
            int row0 = m0 + wid*16 + g;
            int row1 = row0 + 8;
            #pragma unroll
            for (int j = 0; j < 16; j++) {
                int col = kb*128 + j*8 + tig*2;
                if (col     > row0) S[j][0] = -1e30f;
                if (col + 1 > row0) S[j][1] = -1e30f;
                if (col     > row1) S[j][2] = -1e30f;
                if (col + 1 > row1) S[j][3] = -1e30f;
            }
        }

        float mx0 = -1e30f, mx1 = -1e30f;
        #pragma unroll
        for (int j = 0; j < 16; j++) {
            mx0 = fmaxf(mx0, fmaxf(S[j][0], S[j][1]));
            mx1 = fmaxf(mx1, fmaxf(S[j][2], S[j][3]));
        }
        mx0 = fmaxf(mx0, __shfl_xor_sync(0xffffffffu, mx0, 1));
        mx0 = fmaxf(mx0, __shfl_xor_sync(0xffffffffu, mx0, 2));
        mx1 = fmaxf(mx1, __shfl_xor_sync(0xffffffffu, mx1, 1));
        mx1 = fmaxf(mx1, __shfl_xor_sync(0xffffffffu, mx1, 2));
        float nm0 = fmaxf(mrun0, mx0), nm1 = fmaxf(mrun1, mx1);
        float f0 = expf(mrun0 - nm0), f1 = expf(mrun1 - nm1);
        mrun0 = nm0; mrun1 = nm1;
        float rs0 = 0.f, rs1 = 0.f;
        #pragma unroll
        for (int j = 0; j < 16; j++) {
            S[j][0] = expf(S[j][0] - nm0);
            S[j][1] = expf(S[j][1] - nm0);
            S[j][2] = expf(S[j][2] - nm1);
            S[j][3] = expf(S[j][3] - nm1);
            rs0 += S[j][0] + S[j][1];
            rs1 += S[j][2] + S[j][3];
        }
        rs0 += __shfl_xor_sync(0xffffffffu, rs0, 1);
        rs0 += __shfl_xor_sync(0xffffffffu, rs0, 2);
        rs1 += __shfl_xor_sync(0xffffffffu, rs1, 1);
        rs1 += __shfl_xor_sync(0xffffffffu, rs1, 2);
        lrun0 = lrun0 * f0 + rs0;
        lrun1 = lrun1 * f1 + rs1;
        #pragma unroll
        for (int i = 0; i < 8; i++) {
            O[i][0] *= f0; O[i][1] *= f0;
            O[i][2] *= f1; O[i][3] *= f1;
        }

        #pragma unroll
        for (int c2 = 0; c2 < 2; c2++) {
            const unsigned vst = st + 32768 + (unsigned)c2 * 8192;
            #pragma unroll
            for (int ks = 0; ks < 4; ks++) {
                const int sI = c2*4 + ks;
                const float* e0 = S[2*sI];
                const float* e1 = S[2*sI + 1];
                unsigned ah[4], al[4];
                ah[0] = packbf(e0[0], e0[1]);
                ah[1] = packbf(e0[2], e0[3]);
                ah[2] = packbf(e1[0], e1[1]);
                ah[3] = packbf(e1[2], e1[3]);
                al[0] = packbf(e0[0] - __bfloat162float(__float2bfloat16(e0[0])),
                               e0[1] - __bfloat162float(__float2bfloat16(e0[1])));
                al[1] = packbf(e0[2] - __bfloat162float(__float2bfloat16(e0[2])),
                               e0[3] - __bfloat162float(__float2bfloat16(e0[3])));
                al[2] = packbf(e1[0] - __bfloat162float(__float2bfloat16(e1[0])),
                               e1[1] - __bfloat162float(__float2bfloat16(e1[1])));
                al[3] = packbf(e1[2] - __bfloat162float(__float2bfloat16(e1[2])),
                               e1[3] - __bfloat162float(__float2bfloat16(e1[3])));
                #pragma unroll
                for (int jp = 0; jp < 4; jp++) {
                    unsigned o = swz(jp*16 + b_rin, ks*32 + b_cB);
                    unsigned rh[4], rl[4];
                    ldmx4(rh, vst + o);
                    ldmx4(rl, vst + 16384 + o);
                    unsigned bh0[2] = {rh[0], rh[1]}, bh1[2] = {rh[2], rh[3]};
                    unsigned bl0[2] = {rl[0], rl[1]}, bl1[2] = {rl[2], rl[3]};
                    mma16816(O[2*jp],   ah, bh0);
                    mma16816(O[2*jp],   al, bh0);
                    mma16816(O[2*jp],   ah, bl0);
                    mma16816(O[2*jp+1], ah, bh1);
                    mma16816(O[2*jp+1], al, bh1);
                    mma16816(O[2*jp+1], ah, bl1);
                }
            }
        }
        __syncthreads();
    }

    float inv0 = 1.f / lrun0, inv1 = 1.f / lrun1;
    float* y0 = YH + ((size_t)bh * TLEN + m0 + wid*16 + g) * HD;
    float* y1 = y0 + 8 * HD;
    #pragma unroll
    for (int i = 0; i < 8; i++) {
        int d = i*8 + tig*2;
        y0[d]     = O[i][0] * inv0;
        y0[d + 1] = O[i][1] * inv0;
        y1[d]     = O[i][2] * inv1;
        y1[d + 1] = O[i][3] * inv1;
    }
}

// ======================== small kernels ======================================
__global__ void detect_idx_kernel(const unsigned int* w) {
    __shared__ unsigned int s;
    if (threadIdx.x == 0) s = 0u;
    __syncthreads();
    unsigned int v = 0u;
    for (int i = threadIdx.x; i < 1024; i += blockDim.x) v |= w[2*i + 1];
    atomicOr(&s, v);
    __syncthreads();
    if (threadIdx.x == 0) g_idx32 = (s != 0u) ? 1 : 0;
}

__global__ void embed_kernel(const void* idx, const float* __restrict__ wte,
                             const float* __restrict__ wpe, float* __restrict__ x) {
    int i = blockIdx.x * blockDim.x + threadIdx.x;
    if (i >= MTOK*CDIM) return;
    int c  = i % CDIM;
    int bt = i / CDIM;
    int t  = bt % TLEN;
    long long tok;
    if (g_idx32) tok = (long long)((const int*)idx)[bt];
    else         tok = ((const long long*)idx)[bt];
    x[i] = wte[tok*CDIM + c] + wpe[(long long)t*CDIM + c];
}

__global__ void ln_lora_kernel(const float* __restrict__ x, const float* __restrict__ g,
                               const float* __restrict__ b,
                               const float* __restrict__ lA,
                               __nv_bfloat16* __restrict__ oh, __nv_bfloat16* __restrict__ ol,
                               float* __restrict__ tmp) {
    const int row = blockIdx.x;
    const float* xr = x + (long long)row * CDIM;
    __shared__ float sx[CDIM];
    __shared__ float red[128];
    __shared__ float s_mean, s_rstd;
    int tid = threadIdx.x;
    float s = 0.f;
    for (int c = tid; c < CDIM; c += 128) { float v = xr[c]; sx[c] = v; s += v; }
    red[tid] = s; __syncthreads();
    for (int st = 64; st > 0; st >>= 1) { if (tid < st) red[tid] += red[tid+st]; __syncthreads(); }
    if (tid == 0) s_mean = red[0] / (float)CDIM;
    __syncthreads();
    float mean = s_mean;
    float sq = 0.f;
    for (int c = tid; c < CDIM; c += 128) { float d = sx[c] - mean; sq += d*d; }
    red[tid] = sq; __syncthreads();
    for (int st = 64; st > 0; st >>= 1) { if (tid < st) red[tid] += red[tid+st]; __syncthreads(); }
    if (tid == 0) s_rstd = rsqrtf(red[0] / (float)CDIM + 1e-5f);
    __syncthreads();
    float mean2 = s_mean, rstd = s_rstd;
    for (int c = tid; c < CDIM; c += 128) {
        float v = (sx[c] - mean2) * rstd * g[c] + b[c];
        long long o = (long long)row*CDIM + c;
        __nv_bfloat16 hi, lo; bsplit(v, hi, lo);
        oh[o] = hi; ol[o] = lo;
        sx[c] = v;
    }
    __syncthreads();
    if (lA) {
        int w = tid >> 5, lane = tid & 31;
        #pragma unroll
        for (int rr = 0; rr < 2; ++rr) {
            int r = w*2 + rr;
            const float* Ar = lA + (long long)r * CDIM;
            float acc = 0.f;
            for (int c = lane; c < CDIM; c += 32) acc += sx[c] * Ar[c];
            #pragma unroll
            for (int off = 16; off > 0; off >>= 1) acc += __shfl_down_sync(0xffffffffu, acc, off);
            if (lane == 0) tmp[row*RANK + r] = acc;
        }
    }
}

__global__ void ln_f16_kernel(const float* __restrict__ x, const float* __restrict__ g,
                              const float* __restrict__ b, __half* __restrict__ oh) {
    const int row = blockIdx.x;
    const float* xr = x + (long long)row * CDIM;
    __shared__ float sx[CDIM];
    __shared__ float red[128];
    __shared__ float s_mean, s_rstd;
    int tid = threadIdx.x;
    float s = 0.f;
    for (int c = tid; c < CDIM; c += 128) { float v = xr[c]; sx[c] = v; s += v; }
    red[tid] = s; __syncthreads();
    for (int st = 64; st > 0; st >>= 1) { if (tid < st) red[tid] += red[tid+st]; __syncthreads(); }
    if (tid == 0) s_mean = red[0] / (float)CDIM;
    __syncthreads();
    float mean = s_mean;
    float sq = 0.f;
    for (int c = tid; c < CDIM; c += 128) { float d = sx[c] - mean; sq += d*d; }
    red[tid] = sq; __syncthreads();
    for (int st = 64; st > 0; st >>= 1) { if (tid < st) red[tid] += red[tid+st]; __syncthreads(); }
    if (tid == 0) s_rstd = rsqrtf(red[0] / (float)CDIM + 1e-5f);
    __syncthreads();
    float mean2 = s_mean, rstd = s_rstd;
    for (int c = tid; c < CDIM; c += 128) {
        float v = (sx[c] - mean2) * rstd * g[c] + b[c];
        oh[(long long)row*CDIM + c] = __float2half(v);
    }
}

__global__ void wsplitA_kernel(const float* __restrict__ wq, const float* __restrict__ wp,
                               const float* __restrict__ wf, const float* __restrict__ wm,
                               __nv_bfloat16* __restrict__ qh, __nv_bfloat16* __restrict__ ql,
                               __nv_bfloat16* __restrict__ ph, __nv_bfloat16* __restrict__ pl,
                               __nv_bfloat16* __restrict__ fh, __nv_bfloat16* __restrict__ fl,
                               __nv_bfloat16* __restrict__ mh, __nv_bfloat16* __restrict__ ml) {
    const int NQ = NLAYER*3*CDIM*CDIM, NP = NLAYER*CDIM*CDIM,
              NF = NLAYER*4*CDIM*CDIM, NM = NLAYER*CDIM*4*CDIM;
    int i4 = (blockIdx.x * 256 + threadIdx.x) * 4;
    const float* src; __nv_bfloat16 *dh, *dl; int k;
    if (i4 < NQ)                { src = wq; dh = qh; dl = ql; k = i4; }
    else if (i4 < NQ+NP)        { src = wp; dh = ph; dl = pl; k = i4 - NQ; }
    else if (i4 < NQ+NP+NF)     { src = wf; dh = fh; dl = fl; k = i4 - NQ - NP; }
    else if (i4 < NQ+NP+NF+NM)  { src = wm; dh = mh; dl = ml; k = i4 - NQ - NP - NF; }
    else return;
    float4 v = *reinterpret_cast<const float4*>(src + k);
    __nv_bfloat16 h0, l0, h1, l1, h2, l2, h3, l3;
    bsplit(v.x, h0, l0); bsplit(v.y, h1, l1);
    bsplit(v.z, h2, l2); bsplit(v.w, h3, l3);
    uint2 hv, lv;
    hv.x = ((unsigned)__bfloat16_as_ushort(h1) << 16) | __bfloat16_as_ushort(h0);
    hv.y = ((unsigned)__bfloat16_as_ushort(h3) << 16) | __bfloat16_as_ushort(h2);
    lv.x = ((unsigned)__bfloat16_as_ushort(l1) << 16) | __bfloat16_as_ushort(l0);
    lv.y = ((unsigned)__bfloat16_as_ushort(l3) << 16) | __bfloat16_as_ushort(l2);
    *reinterpret_cast<uint2*>(dh + k) = hv;
    *reinterpret_cast<uint2*>(dl + k) = lv;
}

__global__ void wsplit_f16_kernel(const float* __restrict__ w, __half* __restrict__ h, int n) {
    int i4 = (blockIdx.x * 256 + threadIdx.x) * 4;
    if (i4 >= n) return;
    float4 v = *reinterpret_cast<const float4*>(w + i4);
    __half2 a = __floats2half2_rn(v.x, v.y);
    __half2 b = __floats2half2_rn(v.z, v.w);
    uint2 o;
    o.x = reinterpret_cast<unsigned&>(a);
    o.y = reinterpret_cast<unsigned&>(b);
    *reinterpret_cast<uint2*>(h + i4) = o;
}

__global__ void merge_lora_kernel(const float* __restrict__ yh,
                                  const float* __restrict__ lA,
                                  __nv_bfloat16* __restrict__ oh, __nv_bfloat16* __restrict__ ol,
                                  float* __restrict__ tmp) {
    const int row = blockIdx.x;
    const int t = row & (TLEN - 1);
    const int b = row >> 10;
    __shared__ float sy[CDIM];
    int tid = threadIdx.x;
    for (int c = tid; c < CDIM; c += 128) {
        int h = c >> 6, d = c & 63;
        sy[c] = yh[(((long long)(b*NHEAD + h) * TLEN) + t) * HD + d];
    }
    __syncthreads();
    for (int c = tid; c < CDIM; c += 128) {
        long long o = (long long)row*CDIM + c;
        __nv_bfloat16 hi, lo; bsplit(sy[c], hi, lo);
        oh[o] = hi; ol[o] = lo;
    }
    int w = tid >> 5, lane = tid & 31;
    #pragma unroll
    for (int rr = 0; rr < 2; ++rr) {
        int r = w*2 + rr;
        const float* Ar = lA + (long long)r * CDIM;
        float acc = 0.f;
        for (int c = lane; c < CDIM; c += 32) acc += sy[c] * Ar[c];
        #pragma unroll
        for (int off = 16; off > 0; off >>= 1) acc += __shfl_down_sync(0xffffffffu, acc, off);
        if (lane == 0) tmp[row*RANK + r] = acc;
    }
}

// ======================== host driver ========================================
template<int MODE>
static void launch_gemm(dim3 grid,
                        const __nv_bfloat16* Ah, const __nv_bfloat16* Al,
                        const __nv_bfloat16* Bh, const __nv_bfloat16* Bl,
                        const float* bias, const float* loraT, const float* loraB,
                        float* Cm, int M, int N, int K) {
    cudaFuncSetAttribute(mma_gemm<MODE>,
                         cudaFuncAttributeMaxDynamicSharedMemorySize, GEMM_SMEM);
    mma_gemm<MODE><<<grid, 256, GEMM_SMEM>>>(
        Ah, Al, Bh, Bl, bias, loraT, loraB, Cm, M, N, K);
}

extern "C" void kernel_launch(void* const* d_in, const int* in_sizes, int n_in,
                              void* d_out, int out_size) {
    (void)in_sizes; (void)n_in; (void)out_size;
    const void*  idx     = d_in[0];
    const float* wte     = (const float*)d_in[1];
    const float* wpe     = (const float*)d_in[2];
    const float* ln1_g   = (const float*)d_in[3];
    const float* ln1_b   = (const float*)d_in[4];
    const float* attn_w  = (const float*)d_in[5];
    const float* attn_lA = (const float*)d_in[6];
    const float* attn_lB = (const float*)d_in[7];
    const float* proj_w  = (const float*)d_in[8];
    const float* proj_lA = (const float*)d_in[9];
    const float* proj_lB = (const float*)d_in[10];
    const float* ln2_g   = (const float*)d_in[11];
    const float* ln2_b   = (const float*)d_in[12];
    const float* fc_w    = (const float*)d_in[13];
    const float* fc_b    = (const float*)d_in[14];
    const float* mproj_w = (const float*)d_in[15];
    const float* mproj_b = (const float*)d_in[16];
    const float* lnf_g   = (const float*)d_in[17];
    const float* lnf_b   = (const float*)d_in[18];
    const float* head_w  = (const float*)d_in[19];
    float* out = (float*)d_out;

    float *X, *YH, *TMP;
    cudaGetSymbolAddress((void**)&X,   g_X);
    cudaGetSymbolAddress((void**)&YH,  g_YH);
    cudaGetSymbolAddress((void**)&TMP, g_TMP);

    __nv_bfloat16 *wqkv_h, *wqkv_l, *wproj_h, *wproj_l, *wfc_h, *wfc_l, *wmp_h, *wmp_l,
                  *Hh, *Hl, *Yh, *Yl, *FCGh, *FCGl,
                  *Qh, *Ql, *Kh, *Kl, *Vth, *Vtl;
    __half *whead16, *H16;
    cudaGetSymbolAddress((void**)&wqkv_h,  g_wqkv_h);  cudaGetSymbolAddress((void**)&wqkv_l,  g_wqkv_l);
    cudaGetSymbolAddress((void**)&wproj_h, g_wproj_h); cudaGetSymbolAddress((void**)&wproj_l, g_wproj_l);
    cudaGetSymbolAddress((void**)&wfc_h,   g_wfc_h);   cudaGetSymbolAddress((void**)&wfc_l,   g_wfc_l);
    cudaGetSymbolAddress((void**)&wmp_h,   g_wmp_h);   cudaGetSymbolAddress((void**)&wmp_l,   g_wmp_l);
    cudaGetSymbolAddress((void**)&whead16, g_whead16);
    cudaGetSymbolAddress((void**)&H16,  g_H16);
    cudaGetSymbolAddress((void**)&Hh,   g_Hh);   cudaGetSymbolAddress((void**)&Hl,   g_Hl);
    cudaGetSymbolAddress((void**)&Yh,   g_Yhb);  cudaGetSymbolAddress((void**)&Yl,   g_Ylb);
    cudaGetSymbolAddress((void**)&FCGh, g_FCGh); cudaGetSymbolAddress((void**)&FCGl, g_FCGl);
    cudaGetSymbolAddress((void**)&Qh,   g_Qh);   cudaGetSymbolAddress((void**)&Ql,   g_Ql);
    cudaGetSymbolAddress((void**)&Kh,   g_Kh);   cudaGetSymbolAddress((void**)&Kl,   g_Kl);
    cudaGetSymbolAddress((void**)&Vth,  g_Vth);  cudaGetSymbolAddress((void**)&Vtl,  g_Vtl);

    cudaFuncSetAttribute(flash_attn, cudaFuncAttributeMaxDynamicSharedMemorySize, FA_SMEM);

    detect_idx_kernel<<<1, 256>>>((const unsigned int*)idx);
    embed_kernel<<<(MTOK*CDIM + 255)/256, 256>>>(idx, wte, wpe, X);
    {
        int nA = NLAYER*(3*CDIM*CDIM + CDIM*CDIM + 4*CDIM*CDIM + 4*CDIM*CDIM);
        wsplitA_kernel<<<(nA/4 + 255)/256, 256>>>(attn_w, proj_w, fc_w, mproj_w,
            wqkv_h, wqkv_l, wproj_h, wproj_l, wfc_h, wfc_l, wmp_h, wmp_l);
        int nB = VOCAB*CDIM;
        wsplit_f16_kernel<<<(nB/4 + 255)/256, 256>>>(head_w, whead16, nB);
    }

    for (int l = 0; l < NLAYER; l++) {
        long long oq = (long long)l * 3*CDIM*CDIM;
        long long op = (long long)l * CDIM*CDIM;
        long long of = (long long)l * 4*CDIM*CDIM;
        long long om = (long long)l * CDIM*4*CDIM;
        const float* lA_q = attn_lA + (long long)l * RANK*CDIM;
        const float* lB_q = attn_lB + (long long)l * 3*CDIM*RANK;
        const float* lA_p = proj_lA + (long long)l * RANK*CDIM;
        const float* lB_p = proj_lB + (long long)l * CDIM*RANK;

        // ---- attention ----
        ln_lora_kernel<<<MTOK, 128>>>(X, ln1_g + l*CDIM, ln1_b + l*CDIM, lA_q, Hh, Hl, TMP);
        launch_gemm<3>(dim3(MTOK/128, 3*CDIM/128),
            Hh, Hl, wqkv_h + oq, wqkv_l + oq, nullptr, TMP, lB_q, nullptr,
            MTOK, 3*CDIM, CDIM);

        flash_attn<<<dim3(TLEN/128, NBATCH), 256, FA_SMEM>>>(Qh, Ql, Kh, Kl, Vth, Vtl, YH);
        merge_lora_kernel<<<MTOK, 128>>>(YH, lA_p, Yh, Yl, TMP);

        launch_gemm<2>(dim3(MTOK/128, CDIM/128),
            Yh, Yl, wproj_h + op, wproj_l + op, nullptr, TMP, lB_p, X,
            MTOK, CDIM, CDIM);

        // ---- MLP ----
        ln_lora_kernel<<<MTOK, 128>>>(X, ln2_g + l*CDIM, ln2_b + l*CDIM, nullptr, Hh, Hl, TMP);
        launch_gemm<1>(dim3(MTOK/128, 4*CDIM/128),
            Hh, Hl, wfc_h + of, wfc_l + of, fc_b + (long long)l*4*CDIM, nullptr, nullptr, nullptr,
            MTOK, 4*CDIM, CDIM);
        launch_gemm<2>(dim3(MTOK/128, CDIM/128),
            FCGh, FCGl, wmp_h + om, wmp_l + om, mproj_b + (long long)l*CDIM, nullptr, nullptr, X,
            MTOK, CDIM, 4*CDIM);
    }

    // ---- final layernorm + fp16 1-MMA vocab head (128x256 tile) ----
    ln_f16_kernel<<<MTOK, 128>>>(X, lnf_g, lnf_b, H16);
    cudaFuncSetAttribute(mma_gemm_f16, cudaFuncAttributeMaxDynamicSharedMemorySize, GEMM_SMEM_F16);
    mma_gemm_f16<<<dim3(MTOK/128, (VOCAB + 255)/256), 256, GEMM_SMEM_F16>>>(
        H16, whead16, out, MTOK, VOCAB, CDIM);
}

// round 11
// speedup vs baseline: 1.0990x; 1.0990x over previous
#include <cuda_runtime.h>
#include <cuda_bf16.h>
#include <cuda_fp16.h>
#include <math.h>

// ---------------------------------------------------------------------------
// GPT_3959959847300 round 11: revert head to R9's 128x128 tile (the measured
// best) and pin it to 2 CTAs/SM via __launch_bounds__(256,2).
// ---------------------------------------------------------------------------

#define BSZ    2
#define TLEN   1024
#define CDIM   512
#define NHEAD  8
#define HD     64
#define NLAYER 4
#define VOCAB  50257
#define RANK   8
#define LSCALE 4.0f
#define MTOK   (BSZ*TLEN)
#define NBATCH (BSZ*NHEAD)

// ======================== PTX helpers ========================================
__device__ __forceinline__ unsigned smem_u32(const void* p) {
    unsigned a;
    asm("{ .reg .u64 t; cvta.to.shared.u64 t, %1; cvt.u32.u64 %0, t; }" : "=r"(a) : "l"(p));
    return a;
}
__device__ __forceinline__ void ldmx4(unsigned* r, unsigned addr) {
    asm volatile("ldmatrix.sync.aligned.m8n8.x4.shared.b16 {%0,%1,%2,%3}, [%4];"
                 : "=r"(r[0]), "=r"(r[1]), "=r"(r[2]), "=r"(r[3]) : "r"(addr));
}
__device__ __forceinline__ void mma16816(float* d, const unsigned* a, const unsigned* b) {
    asm volatile(
        "mma.sync.aligned.m16n8k16.row.col.f32.bf16.bf16.f32 "
        "{%0,%1,%2,%3},{%4,%5,%6,%7},{%8,%9},{%0,%1,%2,%3};"
        : "+f"(d[0]), "+f"(d[1]), "+f"(d[2]), "+f"(d[3])
        : "r"(a[0]), "r"(a[1]), "r"(a[2]), "r"(a[3]), "r"(b[0]), "r"(b[1]));
}
__device__ __forceinline__ void mma16816h(float* d, const unsigned* a, const unsigned* b) {
    asm volatile(
        "mma.sync.aligned.m16n8k16.row.col.f32.f16.f16.f32 "
        "{%0,%1,%2,%3},{%4,%5,%6,%7},{%8,%9},{%0,%1,%2,%3};"
        : "+f"(d[0]), "+f"(d[1]), "+f"(d[2]), "+f"(d[3])
        : "r"(a[0]), "r"(a[1]), "r"(a[2]), "r"(a[3]), "r"(b[0]), "r"(b[1]));
}
__device__ __forceinline__ void cp16(unsigned dst, const void* src, bool pred) {
    int sz = pred ? 16 : 0;
    asm volatile("cp.async.cg.shared.global [%0], [%1], 16, %2;"
                 :: "r"(dst), "l"(src), "r"(sz) : "memory");
}
#define CP_COMMIT()  asm volatile("cp.async.commit_group;" ::: "memory")
#define CP_WAIT_1()  asm volatile("cp.async.wait_group 1;" ::: "memory")
#define CP_WAIT_0()  asm volatile("cp.async.wait_group 0;" ::: "memory")

__device__ __forceinline__ void bsplit(float x, __nv_bfloat16& hi, __nv_bfloat16& lo) {
    hi = __float2bfloat16(x);
    lo = __float2bfloat16(x - __bfloat162float(hi));
}
__device__ __forceinline__ unsigned packbf(float a, float b) {
    __nv_bfloat162 t = __floats2bfloat162_rn(a, b);
    return reinterpret_cast<unsigned&>(t);
}

// ======================== scratch ============================================
__device__ float g_X  [MTOK*CDIM];
__device__ float g_YH [NBATCH*TLEN*HD];
__device__ float g_TMP[MTOK*RANK];
__device__ int   g_idx32;

__device__ __nv_bfloat16 g_wqkv_h[NLAYER*3*CDIM*CDIM], g_wqkv_l[NLAYER*3*CDIM*CDIM];
__device__ __nv_bfloat16 g_wproj_h[NLAYER*CDIM*CDIM],  g_wproj_l[NLAYER*CDIM*CDIM];
__device__ __nv_bfloat16 g_wfc_h [NLAYER*4*CDIM*CDIM], g_wfc_l [NLAYER*4*CDIM*CDIM];
__device__ __nv_bfloat16 g_wmp_h [NLAYER*CDIM*4*CDIM], g_wmp_l [NLAYER*CDIM*4*CDIM];
__device__ __half        g_whead16[VOCAB*CDIM];
__device__ __nv_bfloat16 g_Hh[MTOK*CDIM],  g_Hl[MTOK*CDIM];
__device__ __half        g_H16[MTOK*CDIM];
__device__ __nv_bfloat16 g_Yhb[MTOK*CDIM], g_Ylb[MTOK*CDIM];
__device__ __nv_bfloat16 g_FCGh[MTOK*4*CDIM], g_FCGl[MTOK*4*CDIM];
__device__ __nv_bfloat16 g_Qh[NBATCH*TLEN*HD], g_Ql[NBATCH*TLEN*HD];
__device__ __nv_bfloat16 g_Kh[NBATCH*TLEN*HD], g_Kl[NBATCH*TLEN*HD];
__device__ __nv_bfloat16 g_Vth[NBATCH*HD*TLEN], g_Vtl[NBATCH*HD*TLEN];

// ======================== common tile helpers ================================
#define TILE_B    16384                 // 128x64 16-bit tile (128B rows, swizzled)
#define STAGE_B   (4*TILE_B)
#define GEMM_SMEM (2*STAGE_B)           // 131072
#define STAGE2_B  (2*TILE_B)            // fp16 head: A, B
#define GEMM_SMEM_F16 (2*STAGE2_B)      // 65536

__device__ __forceinline__ unsigned swz(int row, int colB) {
    unsigned o = (unsigned)(row * 128 + colB);
    return o ^ ((unsigned)(row & 7) << 4);
}

__device__ __forceinline__ void stage_load(
    unsigned sbase,
    const __nv_bfloat16* __restrict__ ah, const __nv_bfloat16* __restrict__ al,
    const __nv_bfloat16* __restrict__ bh, const __nv_bfloat16* __restrict__ bl,
    int m0, int n0, int M, int N, int K, int k0, int lr, int lcB)
{
    {
        int gr = m0 + lr; bool ok = (gr < M); int r = ok ? gr : 0;
        const char* pa = (const char*)(ah + (size_t)r * K + k0) + lcB;
        const char* pl = (const char*)(al + (size_t)r * K + k0) + lcB;
        #pragma unroll
        for (int j = 0; j < 4; j++) {
            unsigned o = swz(lr, lcB + 16*j);
            cp16(sbase + o,          pa + 16*j, ok);
            cp16(sbase + TILE_B + o, pl + 16*j, ok);
        }
    }
    {
        int gr = n0 + lr; bool ok = (gr < N); int r = ok ? gr : 0;
        const char* pb = (const char*)(bh + (size_t)r * K + k0) + lcB;
        const char* pl = (const char*)(bl + (size_t)r * K + k0) + lcB;
        #pragma unroll
        for (int j = 0; j < 4; j++) {
            unsigned o = swz(lr, lcB + 16*j);
            cp16(sbase + 2*TILE_B + o, pb + 16*j, ok);
            cp16(sbase + 3*TILE_B + o, pl + 16*j, ok);
        }
    }
}

// ======================== bf16 3-term dense GEMM =============================
// MODE: 1 gelu->bf16 split; 2 residual +=; 3 qkv scatter split
template<int MODE>
__global__ __launch_bounds__(256, 1)
void mma_gemm(const __nv_bfloat16* __restrict__ Ah, const __nv_bfloat16* __restrict__ Al,
              const __nv_bfloat16* __restrict__ Bh, const __nv_bfloat16* __restrict__ Bl,
              const float* __restrict__ bias,
              const float* __restrict__ loraT, const float* __restrict__ loraB,
              float* __restrict__ Cm,
              int M, int N, int K)
{
    extern __shared__ char smem_raw[];
    const int m0 = blockIdx.x * 128;
    const int n0 = blockIdx.y * 128;

    const unsigned sbase = smem_u32(smem_raw);
    const int tid  = threadIdx.x;
    const int lane = tid & 31;
    const int wid  = tid >> 5;
    const int wm   = wid & 1;
    const int wn   = wid >> 1;
    const int lr   = tid >> 1;
    const int lcB  = (tid & 1) << 6;

    float acc[4][4][4];
    #pragma unroll
    for (int i = 0; i < 4; i++)
        #pragma unroll
        for (int j = 0; j < 4; j++)
            #pragma unroll
            for (int t = 0; t < 4; t++) acc[i][j][t] = 0.f;

    const int nc = K >> 6;

    stage_load(sbase, Ah, Al, Bh, Bl, m0, n0, M, N, K, 0, lr, lcB);
    CP_COMMIT();

    const int a_rin  = lane & 15;
    const int a_cB   = (lane >> 4) * 16;
    const int b_sel  = lane >> 3;
    const int b_rin  = (b_sel >> 1) * 8 + (lane & 7);
    const int b_cB   = (b_sel & 1) * 16;

    for (int cI = 0; cI < nc; ++cI) {
        const int s = cI & 1;
        if (cI + 1 < nc) {
            stage_load(sbase + (unsigned)(1 - s) * STAGE_B, Ah, Al, Bh, Bl,
                       m0, n0, M, N, K, (cI + 1) << 6, lr, lcB);
            CP_COMMIT();
            CP_WAIT_1();
        } else {
            CP_WAIT_0();
        }
        __syncthreads();

        const unsigned st = sbase + (unsigned)s * STAGE_B;
        #pragma unroll
        for (int ks = 0; ks < 4; ++ks) {
            unsigned ra_h[4][4], ra_l[4][4], rb_h[4][2], rb_l[4][2];
            #pragma unroll
            for (int i = 0; i < 4; ++i) {
                int row = wm*64 + i*16 + a_rin;
                unsigned o = swz(row, ks*32 + a_cB);
                ldmx4(ra_h[i], st + o);
                ldmx4(ra_l[i], st + TILE_B + o);
            }
            #pragma unroll
            for (int jp = 0; jp < 2; ++jp) {
                int row = wn*32 + jp*16 + b_rin;
                unsigned o = swz(row, ks*32 + b_cB);
                unsigned r[4];
                ldmx4(r, st + 2*TILE_B + o);
                rb_h[2*jp][0] = r[0]; rb_h[2*jp][1] = r[1];
                rb_h[2*jp+1][0] = r[2]; rb_h[2*jp+1][1] = r[3];
                ldmx4(r, st + 3*TILE_B + o);
                rb_l[2*jp][0] = r[0]; rb_l[2*jp][1] = r[1];
                rb_l[2*jp+1][0] = r[2]; rb_l[2*jp+1][1] = r[3];
            }
            #pragma unroll
            for (int i = 0; i < 4; ++i)
                #pragma unroll
                for (int j = 0; j < 4; ++j) {
                    mma16816(acc[i][j], ra_h[i], rb_h[j]);
                    mma16816(acc[i][j], ra_l[i], rb_h[j]);
                    mma16816(acc[i][j], ra_h[i], rb_l[j]);
                }
        }
        __syncthreads();
    }

    const int group = lane >> 2, tig = lane & 3;
    #pragma unroll
    for (int i = 0; i < 4; ++i) {
        int m_lo = m0 + wm*64 + i*16 + group;
        #pragma unroll
        for (int j = 0; j < 4; ++j) {
            int nA = n0 + wn*32 + j*8 + tig*2;
            #pragma unroll
            for (int h = 0; h < 2; ++h) {
                int m = m_lo + h*8;
                if (m >= M) continue;
                #pragma unroll
                for (int e = 0; e < 2; ++e) {
                    int n = nA + e;
                    if (n >= N) continue;
                    float v = acc[i][j][h*2 + e];
                    if (bias)  v += bias[n];
                    if ((MODE == 2 || MODE == 3) && loraT) {
                        const float* t  = loraT + (size_t)m * RANK;
                        const float* bb = loraB + (size_t)n * RANK;
                        float s = 0.f;
                        #pragma unroll
                        for (int r = 0; r < RANK; r++) s += t[r] * bb[r];
                        v += LSCALE * s;
                    }
                    if (MODE == 2) {
                        Cm[(long long)m * N + n] += v;
                    } else if (MODE == 1) {
                        float gv = 0.5f * v * (1.f + tanhf(0.7978845608028654f * (v + 0.044715f * v*v*v)));
                        __nv_bfloat16 hi, lo; bsplit(gv, hi, lo);
                        g_FCGh[(long long)m * N + n] = hi;
                        g_FCGl[(long long)m * N + n] = lo;
                    } else { // MODE 3: qkv scatter split
                        int b  = m >> 10;
                        int t  = m & (TLEN - 1);
                        int sec = n >> 9;
                        int cc  = n & 511;
                        int hh  = cc >> 6, d = cc & 63;
                        __nv_bfloat16 hi, lo; bsplit(v, hi, lo);
                        if (sec == 2) {
                            long long vi = (((long long)(b*NHEAD + hh)) * HD + d) * TLEN + t;
                            g_Vth[vi] = hi; g_Vtl[vi] = lo;
                        } else {
                            long long qi = (((long long)(b*NHEAD + hh)) * TLEN + t) * HD + d;
                            if (sec == 0) { g_Qh[qi] = hi; g_Ql[qi] = lo; }
                            else          { g_Kh[qi] = hi; g_Kl[qi] = lo; }
                        }
                    }
                }
            }
        }
    }
}

// ======================== fp16 1-MMA head GEMM (R9 shape, occ=2) =============
__global__ __launch_bounds__(256, 2)
void mma_gemm_f16(const __half* __restrict__ Am, const __half* __restrict__ Bm,
                  float* __restrict__ Cm, int M, int N, int K)
{
    extern __shared__ char smem_raw[];
    const int m0 = blockIdx.x * 128;
    const int n0 = blockIdx.y * 128;

    const unsigned sbase = smem_u32(smem_raw);
    const int tid  = threadIdx.x;
    const int lane = tid & 31;
    const int wid  = tid >> 5;
    const int wm   = wid & 1;
    const int wn   = wid >> 1;
    const int lr   = tid >> 1;
    const int lcB  = (tid & 1) << 6;

    float acc[4][4][4];
    #pragma unroll
    for (int i = 0; i < 4; i++)
        #pragma unroll
        for (int j = 0; j < 4; j++)
            #pragma unroll
            for (int t = 0; t < 4; t++) acc[i][j][t] = 0.f;

    const int nc = K >> 6;

    auto stage2 = [&](unsigned sb, int k0) {
        {
            int gr = m0 + lr; bool ok = (gr < M); int r = ok ? gr : 0;
            const char* pa = (const char*)(Am + (size_t)r * K + k0) + lcB;
            #pragma unroll
            for (int j = 0; j < 4; j++) {
                unsigned o = swz(lr, lcB + 16*j);
                cp16(sb + o, pa + 16*j, ok);
            }
        }
        {
            int gr = n0 + lr; bool ok = (gr < N); int r = ok ? gr : 0;
            const char* pb = (const char*)(Bm + (size_t)r * K + k0) + lcB;
            #pragma unroll
            for (int j = 0; j < 4; j++) {
                unsigned o = swz(lr, lcB + 16*j);
                cp16(sb + TILE_B + o, pb + 16*j, ok);
            }
        }
    };

    stage2(sbase, 0);
    CP_COMMIT();

    const int a_rin  = lane & 15;
    const int a_cB   = (lane >> 4) * 16;
    const int b_sel  = lane >> 3;
    const int b_rin  = (b_sel >> 1) * 8 + (lane & 7);
    const int b_cB   = (b_sel & 1) * 16;

    for (int cI = 0; cI < nc; ++cI) {
        const int s = cI & 1;
        if (cI + 1 < nc) {
            stage2(sbase + (unsigned)(1 - s) * STAGE2_B, (cI + 1) << 6);
            CP_COMMIT();
            CP_WAIT_1();
        } else {
            CP_WAIT_0();
        }
        __syncthreads();

        const unsigned st = sbase + (unsigned)s * STAGE2_B;
        #pragma unroll
        for (int ks = 0; ks < 4; ++ks) {
            unsigned ra[4][4], rb[4][2];
            #pragma unroll
            for (int i = 0; i < 4; ++i) {
                int row = wm*64 + i*16 + a_rin;
                unsigned o = swz(row, ks*32 + a_cB);
                ldmx4(ra[i], st + o);
            }
            #pragma unroll
            for (int jp = 0; jp < 2; ++jp) {
                int row = wn*32 + jp*16 + b_rin;
                unsigned o = swz(row, ks*32 + b_cB);
                unsigned r[4];
                ldmx4(r, st + TILE_B + o);
                rb[2*jp][0] = r[0]; rb[2*jp][1] = r[1];
                rb[2*jp+1][0] = r[2]; rb[2*jp+1][1] = r[3];
            }
            #pragma unroll
            for (int i = 0; i < 4; ++i)
                #pragma unroll
                for (int j = 0; j < 4; ++j)
                    mma16816h(acc[i][j], ra[i], rb[j]);
        }
        __syncthreads();
    }

    const int group = lane >> 2, tig = lane & 3;
    #pragma unroll
    for (int i = 0; i < 4; ++i) {
        int m_lo = m0 + wm*64 + i*16 + group;
        #pragma unroll
        for (int j = 0; j < 4; ++j) {
            int nA = n0 + wn*32 + j*8 + tig*2;
            #pragma unroll
            for (int h = 0; h < 2; ++h) {
                int m = m_lo + h*8;
                if (m >= M) continue;
                float* crow = Cm + (long long)m * N;
                #pragma unroll
                for (int e = 0; e < 2; ++e) {
                    int n = nA + e;
                    if (n < N) crow[n] = acc[i][j][h*2 + e];
                }
            }
        }
    }
}

// ======================== fused flash attention ==============================
#define FA_QTILE 16384
#define FA_STAGE 65536
#define FA_SMEM  (2*FA_QTILE + 2*FA_STAGE)   // 163840

__global__ __launch_bounds__(256, 1)
void flash_attn(const __nv_bfloat16* __restrict__ Qh, const __nv_bfloat16* __restrict__ Ql,
                const __nv_bfloat16* __restrict__ Kh, const __nv_bfloat16* __restrict__ Kl,
                const __nv_bfloat16* __restrict__ Vth, const __nv_bfloat16* __restrict__ Vtl,
                float* __restrict__ YH)
{
    extern __shared__ char smem_raw[];
    const unsigned sbase = smem_u32(smem_raw);
    const int m0 = blockIdx.x * 128;
    const int bh = blockIdx.y;
    const int tid = threadIdx.x;
    const int lane = tid & 31;
    const int wid = tid >> 5;

    const __nv_bfloat16* qh  = Qh  + (size_t)bh * TLEN * HD;
    const __nv_bfloat16* ql  = Ql  + (size_t)bh * TLEN * HD;
    const __nv_bfloat16* kh  = Kh  + (size_t)bh * TLEN * HD;
    const __nv_bfloat16* kl  = Kl  + (size_t)bh * TLEN * HD;
    const __nv_bfloat16* vth = Vth + (size_t)bh * HD * TLEN;
    const __nv_bfloat16* vtl = Vtl + (size_t)bh * HD * TLEN;

    const unsigned sQ = sbase;
    const unsigned sStage = sbase + 2*FA_QTILE;

    {
        int lr = tid >> 1, lcB = (tid & 1) << 6;
        const char* pqh = (const char*)(qh + (size_t)(m0 + lr) * HD) + lcB;
        const char* pql = (const char*)(ql + (size_t)(m0 + lr) * HD) + lcB;
        #pragma unroll
        for (int j = 0; j < 4; j++) {
            unsigned o = swz(lr, lcB + 16*j);
            cp16(sQ + o,            pqh + 16*j, true);
            cp16(sQ + FA_QTILE + o, pql + 16*j, true);
        }
    }
    CP_COMMIT();

    const int nkb = blockIdx.x + 1;

    auto load_stage = [&](int kb, int s) {
        unsigned st = sStage + (unsigned)s * FA_STAGE;
        int lr = tid >> 1, lcB = (tid & 1) << 6;
        const char* pkh = (const char*)(kh + (size_t)(kb*128 + lr) * HD) + lcB;
        const char* pkl = (const char*)(kl + (size_t)(kb*128 + lr) * HD) + lcB;
        #pragma unroll
        for (int j = 0; j < 4; j++) {
            unsigned o = swz(lr, lcB + 16*j);
            cp16(st + o,         pkh + 16*j, true);
            cp16(st + 16384 + o, pkl + 16*j, true);
        }
        int vr = tid >> 2, vc = (tid & 3) << 5;
        #pragma unroll
        for (int c = 0; c < 2; c++) {
            const char* pvh = (const char*)(vth + (size_t)vr * TLEN + kb*128 + c*64) + vc;
            const char* pvl = (const char*)(vtl + (size_t)vr * TLEN + kb*128 + c*64) + vc;
            unsigned vb = st + 32768 + (unsigned)c * 8192;
            #pragma unroll
            for (int j = 0; j < 2; j++) {
                unsigned o = swz(vr, vc + 16*j);
                cp16(vb + o,         pvh + 16*j, true);
                cp16(vb + 16384 + o, pvl + 16*j, true);
            }
        }
    };

    load_stage(0, 0);
    CP_COMMIT();
    CP_WAIT_1();
    __syncthreads();

    unsigned qfh[4][4], qfl[4][4];
    const int a_rin = lane & 15, a_cB = (lane >> 4) * 16;
    #pragma unroll
    for (int ks = 0; ks < 4; ks++) {
        unsigned o = swz(wid*16 + a_rin, ks*32 + a_cB);
        ldmx4(qfh[ks], sQ + o);
        ldmx4(qfl[ks], sQ + FA_QTILE + o);
    }

    float O[8][4];
    #pragma unroll
    for (int i = 0; i < 8; i++)
        #pragma unroll
        for (int t = 0; t < 4; t++) O[i][t] = 0.f;
    float mrun0 = -1e30f, mrun1 = -1e30f, lrun0 = 0.f, lrun1 = 0.f;

    const int b_sel = lane >> 3;
    const int b_rin = (b_sel >> 1)*8 + (lane & 7);
    const int b_cB  = (b_sel & 1)*16;
    const int g = lane >> 2, tig = lane & 3;

    for (int kb = 0; kb < nkb; kb++) {
        if (kb + 1 < nkb) { load_stage(kb + 1, (kb + 1) & 1); CP_COMMIT(); CP_WAIT_1(); }
        else CP_WAIT_0();
        __syncthreads();
        const unsigned st = sStage + (unsigned)(kb & 1) * FA_STAGE;

        float S[16][4];
        #pragma unroll
        for (int j = 0; j < 16; j++)
            #pragma unroll
            for (int t = 0; t < 4; t++) S[j][t] = 0.f;

        #pragma unroll
        for (int ks = 0; ks < 4; ks++) {
            #pragma unroll
            for (int jp = 0; jp < 8; jp++) {
                unsigned o = swz(jp*16 + b_rin, ks*32 + b_cB);
                unsigned rh[4], rl[4];
                ldmx4(rh, st + o);
                ldmx4(rl, st + 16384 + o);
                unsigned bh0[2] = {rh[0], rh[1]}, bh1[2] = {rh[2], rh[3]};
                unsigned bl0[2] = {rl[0], rl[1]}, bl1[2] = {rl[2], rl[3]};
                mma16816(S[2*jp],   qfh[ks], bh0);
                mma16816(S[2*jp],   qfl[ks], bh0);
                mma16816(S[2*jp],   qfh[ks], bl0);
                mma16816(S[2*jp+1], qfh[ks], bh1);
                mma16816(S[2*jp+1], qfl[ks], bh1);
                mma16816(S[2*jp+1], qfh[ks], bl1);
            }
        }
        #pragma unroll
        for (int j = 0; j < 16; j++)
            #pragma unroll
            for (int t = 0; t < 4; t++) S[j][t] *= 0.125f;

        if (kb == nkb - 1) {
            int row0 = m0 + wid*16 + g;
            int row1 = row0 + 8;
            #pragma unroll
            for (int j = 0; j < 16; j++) {
                int col = kb*128 + j*8 + tig*2;
                if (col     > row0) S[j][0] = -1e30f;
                if (col + 1 > row0) S[j][1] = -1e30f;
                if (col     > row1) S[j][2] = -1e30f;
                if (col + 1 > row1) S[j][3] = -1e30f;
            }
        }

        float mx0 = -1e30f, mx1 = -1e30f;
        #pragma unroll
        for (int j = 0; j < 16; j++) {
            mx0 = fmaxf(mx0, fmaxf(S[j][0], S[j][1]));
            mx1 = fmaxf(mx1, fmaxf(S[j][2], S[j][3]));
        }
        mx0 = fmaxf(mx0, __shfl_xor_sync(0xffffffffu, mx0, 1));
        mx0 = fmaxf(mx0, __shfl_xor_sync(0xffffffffu, mx0, 2));
        mx1 = fmaxf(mx1, __shfl_xor_sync(0xffffffffu, mx1, 1));
        mx1 = fmaxf(mx1, __shfl_xor_sync(0xffffffffu, mx1, 2));
        float nm0 = fmaxf(mrun0, mx0), nm1 = fmaxf(mrun1, mx1);
        float f0 = expf(mrun0 - nm0), f1 = expf(mrun1 - nm1);
        mrun0 = nm0; mrun1 = nm1;
        float rs0 = 0.f, rs1 = 0.f;
        #pragma unroll
        for (int j = 0; j < 16; j++) {
            S[j][0] = expf(S[j][0] - nm0);
            S[j][1] = expf(S[j][1] - nm0);
            S[j][2] = expf(S[j][2] - nm1);
            S[j][3] = expf(S[j][3] - nm1);
            rs0 += S[j][0] + S[j][1];
            rs1 += S[j][2] + S[j][3];
        }
        rs0 += __shfl_xor_sync(0xffffffffu, rs0, 1);
        rs0 += __shfl_xor_sync(0xffffffffu, rs0, 2);
        rs1 += __shfl_xor_sync(0xffffffffu, rs1, 1);
        rs1 += __shfl_xor_sync(0xffffffffu, rs1, 2);
        lrun0 = lrun0 * f0 + rs0;
        lrun1 = lrun1 * f1 + rs1;
        #pragma unroll
        for (int i = 0; i < 8; i++) {
            O[i][0] *= f0; O[i][1] *= f0;
            O[i][2] *= f1; O[i][3] *= f1;
        }

        #pragma unroll
        for (int c2 = 0; c2 < 2; c2++) {
            const unsigned vst = st + 32768 + (unsigned)c2 * 8192;
            #pragma unroll
            for (int ks = 0; ks < 4; ks++) {
                const int sI = c2*4 + ks;
                const float* e0 = S[2*sI];
                const float* e1 = S[2*sI + 1];
                unsigned ah[4], al[4];
                ah[0] = packbf(e0[0], e0[1]);
                ah[1] = packbf(e0[2], e0[3]);
                ah[2] = packbf(e1[0], e1[1]);
                ah[3] = packbf(e1[2], e1[3]);
                al[0] = packbf(e0[0] - __bfloat162float(__float2bfloat16(e0[0])),
                               e0[1] - __bfloat162float(__float2bfloat16(e0[1])));
                al[1] = packbf(e0[2] - __bfloat162float(__float2bfloat16(e0[2])),
                               e0[3] - __bfloat162float(__float2bfloat16(e0[3])));
                al[2] = packbf(e1[0] - __bfloat162float(__float2bfloat16(e1[0])),
                               e1[1] - __bfloat162float(__float2bfloat16(e1[1])));
                al[3] = packbf(e1[2] - __bfloat162float(__float2bfloat16(e1[2])),
                               e1[3] - __bfloat162float(__float2bfloat16(e1[3])));
                #pragma unroll
                for (int jp = 0; jp < 4; jp++) {
                    unsigned o = swz(jp*16 + b_rin, ks*32 + b_cB);
                    unsigned rh[4], rl[4];
                    ldmx4(rh, vst + o);
                    ldmx4(rl, vst + 16384 + o);
                    unsigned bh0[2] = {rh[0], rh[1]}, bh1[2] = {rh[2], rh[3]};
                    unsigned bl0[2] = {rl[0], rl[1]}, bl1[2] = {rl[2], rl[3]};
                    mma16816(O[2*jp],   ah, bh0);
                    mma16816(O[2*jp],   al, bh0);
                    mma16816(O[2*jp],   ah, bl0);
                    mma16816(O[2*jp+1], ah, bh1);
                    mma16816(O[2*jp+1], al, bh1);
                    mma16816(O[2*jp+1], ah, bl1);
                }
            }
        }
        __syncthreads();
    }

    float inv0 = 1.f / lrun0, inv1 = 1.f / lrun1;
    float* y0 = YH + ((size_t)bh * TLEN + m0 + wid*16 + g) * HD;
    float* y1 = y0 + 8 * HD;
    #pragma unroll
    for (int i = 0; i < 8; i++) {
        int d = i*8 + tig*2;
        y0[d]     = O[i][0] * inv0;
        y0[d + 1] = O[i][1] * inv0;
        y1[d]     = O[i][2] * inv1;
        y1[d + 1] = O[i][3] * inv1;
    }
}

// ======================== small kernels ======================================
__global__ void detect_idx_kernel(const unsigned int* w) {
    __shared__ unsigned int s;
    if (threadIdx.x == 0) s = 0u;
    __syncthreads();
    unsigned int v = 0u;
    for (int i = threadIdx.x; i < 1024; i += blockDim.x) v |= w[2*i + 1];
    atomicOr(&s, v);
    __syncthreads();
    if (threadIdx.x == 0) g_idx32 = (s != 0u) ? 1 : 0;
}

__global__ void embed_kernel(const void* idx, const float* __restrict__ wte,
                             const float* __restrict__ wpe, float* __restrict__ x) {
    int i = blockIdx.x * blockDim.x + threadIdx.x;
    if (i >= MTOK*CDIM) return;
    int c  = i % CDIM;
    int bt = i / CDIM;
    int t  = bt % TLEN;
    long long tok;
    if (g_idx32) tok = (long long)((const int*)idx)[bt];
    else         tok = ((const long long*)idx)[bt];
    x[i] = wte[tok*CDIM + c] + wpe[(long long)t*CDIM + c];
}

__global__ void ln_lora_kernel(const float* __restrict__ x, const float* __restrict__ g,
                               const float* __restrict__ b,
                               const float* __restrict__ lA,
                               __nv_bfloat16* __restrict__ oh, __nv_bfloat16* __restrict__ ol,
                               float* __restrict__ tmp) {
    const int row = blockIdx.x;
    const float* xr = x + (long long)row * CDIM;
    __shared__ float sx[CDIM];
    __shared__ float red[128];
    __shared__ float s_mean, s_rstd;
    int tid = threadIdx.x;
    float s = 0.f;
    for (int c = tid; c < CDIM; c += 128) { float v = xr[c]; sx[c] = v; s += v; }
    red[tid] = s; __syncthreads();
    for (int st = 64; st > 0; st >>= 1) { if (tid < st) red[tid] += red[tid+st]; __syncthreads(); }
    if (tid == 0) s_mean = red[0] / (float)CDIM;
    __syncthreads();
    float mean = s_mean;
    float sq = 0.f;
    for (int c = tid; c < CDIM; c += 128) { float d = sx[c] - mean; sq += d*d; }
    red[tid] = sq; __syncthreads();
    for (int st = 64; st > 0; st >>= 1) { if (tid < st) red[tid] += red[tid+st]; __syncthreads(); }
    if (tid == 0) s_rstd = rsqrtf(red[0] / (float)CDIM + 1e-5f);
    __syncthreads();
    float mean2 = s_mean, rstd = s_rstd;
    for (int c = tid; c < CDIM; c += 128) {
        float v = (sx[c] - mean2) * rstd * g[c] + b[c];
        long long o = (long long)row*CDIM + c;
        __nv_bfloat16 hi, lo; bsplit(v, hi, lo);
        oh[o] = hi; ol[o] = lo;
        sx[c] = v;
    }
    __syncthreads();
    if (lA) {
        int w = tid >> 5, lane = tid & 31;
        #pragma unroll
        for (int rr = 0; rr < 2; ++rr) {
            int r = w*2 + rr;
            const float* Ar = lA + (long long)r * CDIM;
            float acc = 0.f;
            for (int c = lane; c < CDIM; c += 32) acc += sx[c] * Ar[c];
            #pragma unroll
            for (int off = 16; off > 0; off >>= 1) acc += __shfl_down_sync(0xffffffffu, acc, off);
            if (lane == 0) tmp[row*RANK + r] = acc;
        }
    }
}

__global__ void ln_f16_kernel(const float* __restrict__ x, const float* __restrict__ g,
                              const float* __restrict__ b, __half* __restrict__ oh) {
    const int row = blockIdx.x;
    const float* xr = x + (long long)row * CDIM;
    __shared__ float sx[CDIM];
    __shared__ float red[128];
    __shared__ float s_mean, s_rstd;
    int tid = threadIdx.x;
    float s = 0.f;
    for (int c = tid; c < CDIM; c += 128) { float v = xr[c]; sx[c] = v; s += v; }
    red[tid] = s; __syncthreads();
    for (int st = 64; st > 0; st >>= 1) { if (tid < st) red[tid] += red[tid+st]; __syncthreads(); }
    if (tid == 0) s_mean = red[0] / (float)CDIM;
    __syncthreads();
    float mean = s_mean;
    float sq = 0.f;
    for (int c = tid; c < CDIM; c += 128) { float d = sx[c] - mean; sq += d*d; }
    red[tid] = sq; __syncthreads();
    for (int st = 64; st > 0; st >>= 1) { if (tid < st) red[tid] += red[tid+st]; __syncthreads(); }
    if (tid == 0) s_rstd = rsqrtf(red[0] / (float)CDIM + 1e-5f);
    __syncthreads();
    float mean2 = s_mean, rstd = s_rstd;
    for (int c = tid; c < CDIM; c += 128) {
        float v = (sx[c] - mean2) * rstd * g[c] + b[c];
        oh[(long long)row*CDIM + c] = __float2half(v);
    }
}

__global__ void wsplitA_kernel(const float* __restrict__ wq, const float* __restrict__ wp,
                               const float* __restrict__ wf, const float* __restrict__ wm,
                               __nv_bfloat16* __restrict__ qh, __nv_bfloat16* __restrict__ ql,
                               __nv_bfloat16* __restrict__ ph, __nv_bfloat16* __restrict__ pl,
                               __nv_bfloat16* __restrict__ fh, __nv_bfloat16* __restrict__ fl,
                               __nv_bfloat16* __restrict__ mh, __nv_bfloat16* __restrict__ ml) {
    const int NQ = NLAYER*3*CDIM*CDIM, NP = NLAYER*CDIM*CDIM,
              NF = NLAYER*4*CDIM*CDIM, NM = NLAYER*CDIM*4*CDIM;
    int i4 = (blockIdx.x * 256 + threadIdx.x) * 4;
    const float* src; __nv_bfloat16 *dh, *dl; int k;
    if (i4 < NQ)                { src = wq; dh = qh; dl = ql; k = i4; }
    else if (i4 < NQ+NP)        { src = wp; dh = ph; dl = pl; k = i4 - NQ; }
    else if (i4 < NQ+NP+NF)     { src = wf; dh = fh; dl = fl; k = i4 - NQ - NP; }
    else if (i4 < NQ+NP+NF+NM)  { src = wm; dh = mh; dl = ml; k = i4 - NQ - NP - NF; }
    else return;
    float4 v = *reinterpret_cast<const float4*>(src + k);
    __nv_bfloat16 h0, l0, h1, l1, h2, l2, h3, l3;
    bsplit(v.x, h0, l0); bsplit(v.y, h1, l1);
    bsplit(v.z, h2, l2); bsplit(v.w, h3, l3);
    uint2 hv, lv;
    hv.x = ((unsigned)__bfloat16_as_ushort(h1) << 16) | __bfloat16_as_ushort(h0);
    hv.y = ((unsigned)__bfloat16_as_ushort(h3) << 16) | __bfloat16_as_ushort(h2);
    lv.x = ((unsigned)__bfloat16_as_ushort(l1) << 16) | __bfloat16_as_ushort(l0);
    lv.y = ((unsigned)__bfloat16_as_ushort(l3) << 16) | __bfloat16_as_ushort(l2);
    *reinterpret_cast<uint2*>(dh + k) = hv;
    *reinterpret_cast<uint2*>(dl + k) = lv;
}

__global__ void wsplit_f16_kernel(const float* __restrict__ w, __half* __restrict__ h, int n) {
    int i4 = (blockIdx.x * 256 + threadIdx.x) * 4;
    if (i4 >= n) return;
    float4 v = *reinterpret_cast<const float4*>(w + i4);
    __half2 a = __floats2half2_rn(v.x, v.y);
    __half2 b = __floats2half2_rn(v.z, v.w);
    uint2 o;
    o.x = reinterpret_cast<unsigned&>(a);
    o.y = reinterpret_cast<unsigned&>(b);
    *reinterpret_cast<uint2*>(h + i4) = o;
}

__global__ void merge_lora_kernel(const float* __restrict__ yh,
                                  const float* __restrict__ lA,
                                  __nv_bfloat16* __restrict__ oh, __nv_bfloat16* __restrict__ ol,
                                  float* __restrict__ tmp) {
    const int row = blockIdx.x;
    const int t = row & (TLEN - 1);
    const int b = row >> 10;
    __shared__ float sy[CDIM];
    int tid = threadIdx.x;
    for (int c = tid; c < CDIM; c += 128) {
        int h = c >> 6, d = c & 63;
        sy[c] = yh[(((long long)(b*NHEAD + h) * TLEN) + t) * HD + d];
    }
    __syncthreads();
    for (int c = tid; c < CDIM; c += 128) {
        long long o = (long long)row*CDIM + c;
        __nv_bfloat16 hi, lo; bsplit(sy[c], hi, lo);
        oh[o] = hi; ol[o] = lo;
    }
    int w = tid >> 5, lane = tid & 31;
    #pragma unroll
    for (int rr = 0; rr < 2; ++rr) {
        int r = w*2 + rr;
        const float* Ar = lA + (long long)r * CDIM;
        float acc = 0.f;
        for (int c = lane; c < CDIM; c += 32) acc += sy[c] * Ar[c];
        #pragma unroll
        for (int off = 16; off > 0; off >>= 1) acc += __shfl_down_sync(0xffffffffu, acc, off);
        if (lane == 0) tmp[row*RANK + r] = acc;
    }
}

// ======================== host driver ========================================
template<int MODE>
static void launch_gemm(dim3 grid,
                        const __nv_bfloat16* Ah, const __nv_bfloat16* Al,
                        const __nv_bfloat16* Bh, const __nv_bfloat16* Bl,
                        const float* bias, const float* loraT, const float* loraB,
                        float* Cm, int M, int N, int K) {
    cudaFuncSetAttribute(mma_gemm<MODE>,
                         cudaFuncAttributeMaxDynamicSharedMemorySize, GEMM_SMEM);
    mma_gemm<MODE><<<grid, 256, GEMM_SMEM>>>(
        Ah, Al, Bh, Bl, bias, loraT, loraB, Cm, M, N, K);
}

extern "C" void kernel_launch(void* const* d_in, const int* in_sizes, int n_in,
                              void* d_out, int out_size) {
    (void)in_sizes; (void)n_in; (void)out_size;
    const void*  idx     = d_in[0];
    const float* wte     = (const float*)d_in[1];
    const float* wpe     = (const float*)d_in[2];
    const float* ln1_g   = (const float*)d_in[3];
    const float* ln1_b   = (const float*)d_in[4];
    const float* attn_w  = (const float*)d_in[5];
    const float* attn_lA = (const float*)d_in[6];
    const float* attn_lB = (const float*)d_in[7];
    const float* proj_w  = (const float*)d_in[8];
    const float* proj_lA = (const float*)d_in[9];
    const float* proj_lB = (const float*)d_in[10];
    const float* ln2_g   = (const float*)d_in[11];
    const float* ln2_b   = (const float*)d_in[12];
    const float* fc_w    = (const float*)d_in[13];
    const float* fc_b    = (const float*)d_in[14];
    const float* mproj_w = (const float*)d_in[15];
    const float* mproj_b = (const float*)d_in[16];
    const float* lnf_g   = (const float*)d_in[17];
    const float* lnf_b   = (const float*)d_in[18];
    const float* head_w  = (const float*)d_in[19];
    float* out = (float*)d_out;

    float *X, *YH, *TMP;
    cudaGetSymbolAddress((void**)&X,   g_X);
    cudaGetSymbolAddress((void**)&YH,  g_YH);
    cudaGetSymbolAddress((void**)&TMP, g_TMP);

    __nv_bfloat16 *wqkv_h, *wqkv_l, *wproj_h, *wproj_l, *wfc_h, *wfc_l, *wmp_h, *wmp_l,
                  *Hh, *Hl, *Yh, *Yl, *FCGh, *FCGl,
                  *Qh, *Ql, *Kh, *Kl, *Vth, *Vtl;
    __half *whead16, *H16;
    cudaGetSymbolAddress((void**)&wqkv_h,  g_wqkv_h);  cudaGetSymbolAddress((void**)&wqkv_l,  g_wqkv_l);
    cudaGetSymbolAddress((void**)&wproj_h, g_wproj_h); cudaGetSymbolAddress((void**)&wproj_l, g_wproj_l);
    cudaGetSymbolAddress((void**)&wfc_h,   g_wfc_h);   cudaGetSymbolAddress((void**)&wfc_l,   g_wfc_l);
    cudaGetSymbolAddress((void**)&wmp_h,   g_wmp_h);   cudaGetSymbolAddress((void**)&wmp_l,   g_wmp_l);
    cudaGetSymbolAddress((void**)&whead16, g_whead16);
    cudaGetSymbolAddress((void**)&H16,  g_H16);
    cudaGetSymbolAddress((void**)&Hh,   g_Hh);   cudaGetSymbolAddress((void**)&Hl,   g_Hl);
    cudaGetSymbolAddress((void**)&Yh,   g_Yhb);  cudaGetSymbolAddress((void**)&Yl,   g_Ylb);
    cudaGetSymbolAddress((void**)&FCGh, g_FCGh); cudaGetSymbolAddress((void**)&FCGl, g_FCGl);
    cudaGetSymbolAddress((void**)&Qh,   g_Qh);   cudaGetSymbolAddress((void**)&Ql,   g_Ql);
    cudaGetSymbolAddress((void**)&Kh,   g_Kh);   cudaGetSymbolAddress((void**)&Kl,   g_Kl);
    cudaGetSymbolAddress((void**)&Vth,  g_Vth);  cudaGetSymbolAddress((void**)&Vtl,  g_Vtl);

    cudaFuncSetAttribute(flash_attn, cudaFuncAttributeMaxDynamicSharedMemorySize, FA_SMEM);

    detect_idx_kernel<<<1, 256>>>((const unsigned int*)idx);
    embed_kernel<<<(MTOK*CDIM + 255)/256, 256>>>(idx, wte, wpe, X);
    {
        int nA = NLAYER*(3*CDIM*CDIM + CDIM*CDIM + 4*CDIM*CDIM + 4*CDIM*CDIM);
        wsplitA_kernel<<<(nA/4 + 255)/256, 256>>>(attn_w, proj_w, fc_w, mproj_w,
            wqkv_h, wqkv_l, wproj_h, wproj_l, wfc_h, wfc_l, wmp_h, wmp_l);
        int nB = VOCAB*CDIM;
        wsplit_f16_kernel<<<(nB/4 + 255)/256, 256>>>(head_w, whead16, nB);
    }

    for (int l = 0; l < NLAYER; l++) {
        long long oq = (long long)l * 3*CDIM*CDIM;
        long long op = (long long)l * CDIM*CDIM;
        long long of = (long long)l * 4*CDIM*CDIM;
        long long om = (long long)l * CDIM*4*CDIM;
        const float* lA_q = attn_lA + (long long)l * RANK*CDIM;
        const float* lB_q = attn_lB + (long long)l * 3*CDIM*RANK;
        const float* lA_p = proj_lA + (long long)l * RANK*CDIM;
        const float* lB_p = proj_lB + (long long)l * CDIM*RANK;

        // ---- attention ----
        ln_lora_kernel<<<MTOK, 128>>>(X, ln1_g + l*CDIM, ln1_b + l*CDIM, lA_q, Hh, Hl, TMP);
        launch_gemm<3>(dim3(MTOK/128, 3*CDIM/128),
            Hh, Hl, wqkv_h + oq, wqkv_l + oq, nullptr, TMP, lB_q, nullptr,
            MTOK, 3*CDIM, CDIM);

        flash_attn<<<dim3(TLEN/128, NBATCH), 256, FA_SMEM>>>(Qh, Ql, Kh, Kl, Vth, Vtl, YH);
        merge_lora_kernel<<<MTOK, 128>>>(YH, lA_p, Yh, Yl, TMP);

        launch_gemm<2>(dim3(MTOK/128, CDIM/128),
            Yh, Yl, wproj_h + op, wproj_l + op, nullptr, TMP, lB_p, X,
            MTOK, CDIM, CDIM);

        // ---- MLP ----
        ln_lora_kernel<<<MTOK, 128>>>(X, ln2_g + l*CDIM, ln2_b + l*CDIM, nullptr, Hh, Hl, TMP);
        launch_gemm<1>(dim3(MTOK/128, 4*CDIM/128),
            Hh, Hl, wfc_h + of, wfc_l + of, fc_b + (long long)l*4*CDIM, nullptr, nullptr, nullptr,
            MTOK, 4*CDIM, CDIM);
        launch_gemm<2>(dim3(MTOK/128, CDIM/128),
            FCGh, FCGl, wmp_h + om, wmp_l + om, mproj_b + (long long)l*CDIM, nullptr, nullptr, X,
            MTOK, CDIM, 4*CDIM);
    }

    // ---- final layernorm + fp16 1-MMA vocab head (128x128, occ=2) ----
    ln_f16_kernel<<<MTOK, 128>>>(X, lnf_g, lnf_b, H16);
    cudaFuncSetAttribute(mma_gemm_f16, cudaFuncAttributeMaxDynamicSharedMemorySize, GEMM_SMEM_F16);
    mma_gemm_f16<<<dim3(MTOK/128, (VOCAB + 127)/128), 256, GEMM_SMEM_F16>>>(
        H16, whead16, out, MTOK, VOCAB, CDIM);
}

// round 12
// speedup vs baseline: 1.2842x; 1.1686x over previous
#include <cuda_runtime.h>
#include <cuda_bf16.h>
#include <cuda_fp16.h>
#include <math.h>

// ---------------------------------------------------------------------------
// GPT_3959959847300 round 12: R11 + split-K=2 for proj/mproj GEMMs (they were
// launching only 64 CTAs on 148 SMs). Epilogue: atomicAdd into fp32 residual.
// ---------------------------------------------------------------------------

#define BSZ    2
#define TLEN   1024
#define CDIM   512
#define NHEAD  8
#define HD     64
#define NLAYER 4
#define VOCAB  50257
#define RANK   8
#define LSCALE 4.0f
#define MTOK   (BSZ*TLEN)
#define NBATCH (BSZ*NHEAD)

// ======================== PTX helpers ========================================
__device__ __forceinline__ unsigned smem_u32(const void* p) {
    unsigned a;
    asm("{ .reg .u64 t; cvta.to.shared.u64 t, %1; cvt.u32.u64 %0, t; }" : "=r"(a) : "l"(p));
    return a;
}
__device__ __forceinline__ void ldmx4(unsigned* r, unsigned addr) {
    asm volatile("ldmatrix.sync.aligned.m8n8.x4.shared.b16 {%0,%1,%2,%3}, [%4];"
                 : "=r"(r[0]), "=r"(r[1]), "=r"(r[2]), "=r"(r[3]) : "r"(addr));
}
__device__ __forceinline__ void mma16816(float* d, const unsigned* a, const unsigned* b) {
    asm volatile(
        "mma.sync.aligned.m16n8k16.row.col.f32.bf16.bf16.f32 "
        "{%0,%1,%2,%3},{%4,%5,%6,%7},{%8,%9},{%0,%1,%2,%3};"
        : "+f"(d[0]), "+f"(d[1]), "+f"(d[2]), "+f"(d[3])
        : "r"(a[0]), "r"(a[1]), "r"(a[2]), "r"(a[3]), "r"(b[0]), "r"(b[1]));
}
__device__ __forceinline__ void mma16816h(float* d, const unsigned* a, const unsigned* b) {
    asm volatile(
        "mma.sync.aligned.m16n8k16.row.col.f32.f16.f16.f32 "
        "{%0,%1,%2,%3},{%4,%5,%6,%7},{%8,%9},{%0,%1,%2,%3};"
        : "+f"(d[0]), "+f"(d[1]), "+f"(d[2]), "+f"(d[3])
        : "r"(a[0]), "r"(a[1]), "r"(a[2]), "r"(a[3]), "r"(b[0]), "r"(b[1]));
}
__device__ __forceinline__ void cp16(unsigned dst, const void* src, bool pred) {
    int sz = pred ? 16 : 0;
    asm volatile("cp.async.cg.shared.global [%0], [%1], 16, %2;"
                 :: "r"(dst), "l"(src), "r"(sz) : "memory");
}
#define CP_COMMIT()  asm volatile("cp.async.commit_group;" ::: "memory")
#define CP_WAIT_1()  asm volatile("cp.async.wait_group 1;" ::: "memory")
#define CP_WAIT_0()  asm volatile("cp.async.wait_group 0;" ::: "memory")

__device__ __forceinline__ void bsplit(float x, __nv_bfloat16& hi, __nv_bfloat16& lo) {
    hi = __float2bfloat16(x);
    lo = __float2bfloat16(x - __bfloat162float(hi));
}
__device__ __forceinline__ unsigned packbf(float a, float b) {
    __nv_bfloat162 t = __floats2bfloat162_rn(a, b);
    return reinterpret_cast<unsigned&>(t);
}

// ======================== scratch ============================================
__device__ float g_X  [MTOK*CDIM];
__device__ float g_YH [NBATCH*TLEN*HD];
__device__ float g_TMP[MTOK*RANK];
__device__ int   g_idx32;

__device__ __nv_bfloat16 g_wqkv_h[NLAYER*3*CDIM*CDIM], g_wqkv_l[NLAYER*3*CDIM*CDIM];
__device__ __nv_bfloat16 g_wproj_h[NLAYER*CDIM*CDIM],  g_wproj_l[NLAYER*CDIM*CDIM];
__device__ __nv_bfloat16 g_wfc_h [NLAYER*4*CDIM*CDIM], g_wfc_l [NLAYER*4*CDIM*CDIM];
__device__ __nv_bfloat16 g_wmp_h [NLAYER*CDIM*4*CDIM], g_wmp_l [NLAYER*CDIM*4*CDIM];
__device__ __half        g_whead16[VOCAB*CDIM];
__device__ __nv_bfloat16 g_Hh[MTOK*CDIM],  g_Hl[MTOK*CDIM];
__device__ __half        g_H16[MTOK*CDIM];
__device__ __nv_bfloat16 g_Yhb[MTOK*CDIM], g_Ylb[MTOK*CDIM];
__device__ __nv_bfloat16 g_FCGh[MTOK*4*CDIM], g_FCGl[MTOK*4*CDIM];
__device__ __nv_bfloat16 g_Qh[NBATCH*TLEN*HD], g_Ql[NBATCH*TLEN*HD];
__device__ __nv_bfloat16 g_Kh[NBATCH*TLEN*HD], g_Kl[NBATCH*TLEN*HD];
__device__ __nv_bfloat16 g_Vth[NBATCH*HD*TLEN], g_Vtl[NBATCH*HD*TLEN];

// ======================== common tile helpers ================================
#define TILE_B    16384                 // 128x64 16-bit tile (128B rows, swizzled)
#define STAGE_B   (4*TILE_B)
#define GEMM_SMEM (2*STAGE_B)           // 131072
#define STAGE2_B  (2*TILE_B)            // fp16 head: A, B
#define GEMM_SMEM_F16 (2*STAGE2_B)      // 65536

__device__ __forceinline__ unsigned swz(int row, int colB) {
    unsigned o = (unsigned)(row * 128 + colB);
    return o ^ ((unsigned)(row & 7) << 4);
}

__device__ __forceinline__ void stage_load(
    unsigned sbase,
    const __nv_bfloat16* __restrict__ ah, const __nv_bfloat16* __restrict__ al,
    const __nv_bfloat16* __restrict__ bh, const __nv_bfloat16* __restrict__ bl,
    int m0, int n0, int M, int N, int K, int k0, int lr, int lcB)
{
    {
        int gr = m0 + lr; bool ok = (gr < M); int r = ok ? gr : 0;
        const char* pa = (const char*)(ah + (size_t)r * K + k0) + lcB;
        const char* pl = (const char*)(al + (size_t)r * K + k0) + lcB;
        #pragma unroll
        for (int j = 0; j < 4; j++) {
            unsigned o = swz(lr, lcB + 16*j);
            cp16(sbase + o,          pa + 16*j, ok);
            cp16(sbase + TILE_B + o, pl + 16*j, ok);
        }
    }
    {
        int gr = n0 + lr; bool ok = (gr < N); int r = ok ? gr : 0;
        const char* pb = (const char*)(bh + (size_t)r * K + k0) + lcB;
        const char* pl = (const char*)(bl + (size_t)r * K + k0) + lcB;
        #pragma unroll
        for (int j = 0; j < 4; j++) {
            unsigned o = swz(lr, lcB + 16*j);
            cp16(sbase + 2*TILE_B + o, pb + 16*j, ok);
            cp16(sbase + 3*TILE_B + o, pl + 16*j, ok);
        }
    }
}

// ======================== bf16 3-term dense GEMM =============================
// MODE: 1 gelu->bf16 split; 2 residual += (atomicAdd if SPLITK); 3 qkv scatter
// SPLITK: 0 normal; 1 K halved across blockIdx.z (MODE 2 only)
template<int MODE, int SPLITK>
__global__ __launch_bounds__(256, 1)
void mma_gemm(const __nv_bfloat16* __restrict__ Ah, const __nv_bfloat16* __restrict__ Al,
              const __nv_bfloat16* __restrict__ Bh, const __nv_bfloat16* __restrict__ Bl,
              const float* __restrict__ bias,
              const float* __restrict__ loraT, const float* __restrict__ loraB,
              float* __restrict__ Cm,
              int M, int N, int K)
{
    extern __shared__ char smem_raw[];
    const int m0 = blockIdx.x * 128;
    const int n0 = blockIdx.y * 128;
    const int kz = SPLITK ? (int)blockIdx.z : 0;
    const int kslice = SPLITK ? (K >> 1) : K;
    const int koff = kz * kslice;

    const unsigned sbase = smem_u32(smem_raw);
    const int tid  = threadIdx.x;
    const int lane = tid & 31;
    const int wid  = tid >> 5;
    const int wm   = wid & 1;
    const int wn   = wid >> 1;
    const int lr   = tid >> 1;
    const int lcB  = (tid & 1) << 6;

    float acc[4][4][4];
    #pragma unroll
    for (int i = 0; i < 4; i++)
        #pragma unroll
        for (int j = 0; j < 4; j++)
            #pragma unroll
            for (int t = 0; t < 4; t++) acc[i][j][t] = 0.f;

    const int nc = kslice >> 6;

    stage_load(sbase, Ah, Al, Bh, Bl, m0, n0, M, N, K, koff, lr, lcB);
    CP_COMMIT();

    const int a_rin  = lane & 15;
    const int a_cB   = (lane >> 4) * 16;
    const int b_sel  = lane >> 3;
    const int b_rin  = (b_sel >> 1) * 8 + (lane & 7);
    const int b_cB   = (b_sel & 1) * 16;

    for (int cI = 0; cI < nc; ++cI) {
        const int s = cI & 1;
        if (cI + 1 < nc) {
            stage_load(sbase + (unsigned)(1 - s) * STAGE_B, Ah, Al, Bh, Bl,
                       m0, n0, M, N, K, koff + ((cI + 1) << 6), lr, lcB);
            CP_COMMIT();
            CP_WAIT_1();
        } else {
            CP_WAIT_0();
        }
        __syncthreads();

        const unsigned st = sbase + (unsigned)s * STAGE_B;
        #pragma unroll
        for (int ks = 0; ks < 4; ++ks) {
            unsigned ra_h[4][4], ra_l[4][4], rb_h[4][2], rb_l[4][2];
            #pragma unroll
            for (int i = 0; i < 4; ++i) {
                int row = wm*64 + i*16 + a_rin;
                unsigned o = swz(row, ks*32 + a_cB);
                ldmx4(ra_h[i], st + o);
                ldmx4(ra_l[i], st + TILE_B + o);
            }
            #pragma unroll
            for (int jp = 0; jp < 2; ++jp) {
                int row = wn*32 + jp*16 + b_rin;
                unsigned o = swz(row, ks*32 + b_cB);
                unsigned r[4];
                ldmx4(r, st + 2*TILE_B + o);
                rb_h[2*jp][0] = r[0]; rb_h[2*jp][1] = r[1];
                rb_h[2*jp+1][0] = r[2]; rb_h[2*jp+1][1] = r[3];
                ldmx4(r, st + 3*TILE_B + o);
                rb_l[2*jp][0] = r[0]; rb_l[2*jp][1] = r[1];
                rb_l[2*jp+1][0] = r[2]; rb_l[2*jp+1][1] = r[3];
            }
            #pragma unroll
            for (int i = 0; i < 4; ++i)
                #pragma unroll
                for (int j = 0; j < 4; ++j) {
                    mma16816(acc[i][j], ra_h[i], rb_h[j]);
                    mma16816(acc[i][j], ra_l[i], rb_h[j]);
                    mma16816(acc[i][j], ra_h[i], rb_l[j]);
                }
        }
        __syncthreads();
    }

    const int group = lane >> 2, tig = lane & 3;
    #pragma unroll
    for (int i = 0; i < 4; ++i) {
        int m_lo = m0 + wm*64 + i*16 + group;
        #pragma unroll
        for (int j = 0; j < 4; ++j) {
            int nA = n0 + wn*32 + j*8 + tig*2;
            #pragma unroll
            for (int h = 0; h < 2; ++h) {
                int m = m_lo + h*8;
                if (m >= M) continue;
                #pragma unroll
                for (int e = 0; e < 2; ++e) {
                    int n = nA + e;
                    if (n >= N) continue;
                    float v = acc[i][j][h*2 + e];
                    if (bias && kz == 0)  v += bias[n];
                    if ((MODE == 2 || MODE == 3) && loraT && kz == 0) {
                        const float* t  = loraT + (size_t)m * RANK;
                        const float* bb = loraB + (size_t)n * RANK;
                        float s = 0.f;
                        #pragma unroll
                        for (int r = 0; r < RANK; r++) s += t[r] * bb[r];
                        v += LSCALE * s;
                    }
                    if (MODE == 2) {
                        if (SPLITK) atomicAdd(&Cm[(long long)m * N + n], v);
                        else        Cm[(long long)m * N + n] += v;
                    } else if (MODE == 1) {
                        float gv = 0.5f * v * (1.f + tanhf(0.7978845608028654f * (v + 0.044715f * v*v*v)));
                        __nv_bfloat16 hi, lo; bsplit(gv, hi, lo);
                        g_FCGh[(long long)m * N + n] = hi;
                        g_FCGl[(long long)m * N + n] = lo;
                    } else { // MODE 3: qkv scatter split
                        int b  = m >> 10;
                        int t  = m & (TLEN - 1);
                        int sec = n >> 9;
                        int cc  = n & 511;
                        int hh  = cc >> 6, d = cc & 63;
                        __nv_bfloat16 hi, lo; bsplit(v, hi, lo);
                        if (sec == 2) {
                            long long vi = (((long long)(b*NHEAD + hh)) * HD + d) * TLEN + t;
                            g_Vth[vi] = hi; g_Vtl[vi] = lo;
                        } else {
                            long long qi = (((long long)(b*NHEAD + hh)) * TLEN + t) * HD + d;
                            if (sec == 0) { g_Qh[qi] = hi; g_Ql[qi] = lo; }
                            else          { g_Kh[qi] = hi; g_Kl[qi] = lo; }
                        }
                    }
                }
            }
        }
    }
}

// ======================== fp16 1-MMA head GEMM (128x128, occ=2) ==============
__global__ __launch_bounds__(256, 2)
void mma_gemm_f16(const __half* __restrict__ Am, const __half* __restrict__ Bm,
                  float* __restrict__ Cm, int M, int N, int K)
{
    extern __shared__ char smem_raw[];
    const int m0 = blockIdx.x * 128;
    const int n0 = blockIdx.y * 128;

    const unsigned sbase = smem_u32(smem_raw);
    const int tid  = threadIdx.x;
    const int lane = tid & 31;
    const int wid  = tid >> 5;
    const int wm   = wid & 1;
    const int wn   = wid >> 1;
    const int lr   = tid >> 1;
    const int lcB  = (tid & 1) << 6;

    float acc[4][4][4];
    #pragma unroll
    for (int i = 0; i < 4; i++)
        #pragma unroll
        for (int j = 0; j < 4; j++)
            #pragma unroll
            for (int t = 0; t < 4; t++) acc[i][j][t] = 0.f;

    const int nc = K >> 6;

    auto stage2 = [&](unsigned sb, int k0) {
        {
            int gr = m0 + lr; bool ok = (gr < M); int r = ok ? gr : 0;
            const char* pa = (const char*)(Am + (size_t)r * K + k0) + lcB;
            #pragma unroll
            for (int j = 0; j < 4; j++) {
                unsigned o = swz(lr, lcB + 16*j);
                cp16(sb + o, pa + 16*j, ok);
            }
        }
        {
            int gr = n0 + lr; bool ok = (gr < N); int r = ok ? gr : 0;
            const char* pb = (const char*)(Bm + (size_t)r * K + k0) + lcB;
            #pragma unroll
            for (int j = 0; j < 4; j++) {
                unsigned o = swz(lr, lcB + 16*j);
                cp16(sb + TILE_B + o, pb + 16*j, ok);
            }
        }
    };

    stage2(sbase, 0);
    CP_COMMIT();

    const int a_rin  = lane & 15;
    const int a_cB   = (lane >> 4) * 16;
    const int b_sel  = lane >> 3;
    const int b_rin  = (b_sel >> 1) * 8 + (lane & 7);
    const int b_cB   = (b_sel & 1) * 16;

    for (int cI = 0; cI < nc; ++cI) {
        const int s = cI & 1;
        if (cI + 1 < nc) {
            stage2(sbase + (unsigned)(1 - s) * STAGE2_B, (cI + 1) << 6);
            CP_COMMIT();
            CP_WAIT_1();
        } else {
            CP_WAIT_0();
        }
        __syncthreads();

        const unsigned st = sbase + (unsigned)s * STAGE2_B;
        #pragma unroll
        for (int ks = 0; ks < 4; ++ks) {
            unsigned ra[4][4], rb[4][2];
            #pragma unroll
            for (int i = 0; i < 4; ++i) {
                int row = wm*64 + i*16 + a_rin;
                unsigned o = swz(row, ks*32 + a_cB);
                ldmx4(ra[i], st + o);
            }
            #pragma unroll
            for (int jp = 0; jp < 2; ++jp) {
                int row = wn*32 + jp*16 + b_rin;
                unsigned o = swz(row, ks*32 + b_cB);
                unsigned r[4];
                ldmx4(r, st + TILE_B + o);
                rb[2*jp][0] = r[0]; rb[2*jp][1] = r[1];
                rb[2*jp+1][0] = r[2]; rb[2*jp+1][1] = r[3];
            }
            #pragma unroll
            for (int i = 0; i < 4; ++i)
                #pragma unroll
                for (int j = 0; j < 4; ++j)
                    mma16816h(acc[i][j], ra[i], rb[j]);
        }
        __syncthreads();
    }

    const int group = lane >> 2, tig = lane & 3;
    #pragma unroll
    for (int i = 0; i < 4; ++i) {
        int m_lo = m0 + wm*64 + i*16 + group;
        #pragma unroll
        for (int j = 0; j < 4; ++j) {
            int nA = n0 + wn*32 + j*8 + tig*2;
            #pragma unroll
            for (int h = 0; h < 2; ++h) {
                int m = m_lo + h*8;
                if (m >= M) continue;
                float* crow = Cm + (long long)m * N;
                #pragma unroll
                for (int e = 0; e < 2; ++e) {
                    int n = nA + e;
                    if (n < N) crow[n] = acc[i][j][h*2 + e];
                }
            }
        }
    }
}

// ======================== fused flash attention ==============================
#define FA_QTILE 16384
#define FA_STAGE 65536
#define FA_SMEM  (2*FA_QTILE + 2*FA_STAGE)   // 163840

__global__ __launch_bounds__(256, 1)
void flash_attn(const __nv_bfloat16* __restrict__ Qh, const __nv_bfloat16* __restrict__ Ql,
                const __nv_bfloat16* __restrict__ Kh, const __nv_bfloat16* __restrict__ Kl,
                const __nv_bfloat16* __restrict__ Vth, const __nv_bfloat16* __restrict__ Vtl,
                float* __restrict__ YH)
{
    extern __shared__ char smem_raw[];
    const unsigned sbase = smem_u32(smem_raw);
    const int m0 = blockIdx.x * 128;
    const int bh = blockIdx.y;
    const int tid = threadIdx.x;
    const int lane = tid & 31;
    const int wid = tid >> 5;

    const __nv_bfloat16* qh  = Qh  + (size_t)bh * TLEN * HD;
    const __nv_bfloat16* ql  = Ql  + (size_t)bh * TLEN * HD;
    const __nv_bfloat16* kh  = Kh  + (size_t)bh * TLEN * HD;
    const __nv_bfloat16* kl  = Kl  + (size_t)bh * TLEN * HD;
    const __nv_bfloat16* vth = Vth + (size_t)bh * HD * TLEN;
    const __nv_bfloat16* vtl = Vtl + (size_t)bh * HD * TLEN;

    const unsigned sQ = sbase;
    const unsigned sStage = sbase + 2*FA_QTILE;

    {
        int lr = tid >> 1, lcB = (tid & 1) << 6;
        const char* pqh = (const char*)(qh + (size_t)(m0 + lr) * HD) + lcB;
        const char* pql = (const char*)(ql + (size_t)(m0 + lr) * HD) + lcB;
        #pragma unroll
        for (int j = 0; j < 4; j++) {
            unsigned o = swz(lr, lcB + 16*j);
            cp16(sQ + o,            pqh + 16*j, true);
            cp16(sQ + FA_QTILE + o, pql + 16*j, true);
        }
    }
    CP_COMMIT();

    const int nkb = blockIdx.x + 1;

    auto load_stage = [&](int kb, int s) {
        unsigned st = sStage + (unsigned)s * FA_STAGE;
        int lr = tid >> 1, lcB = (tid & 1) << 6;
        const char* pkh = (const char*)(kh + (size_t)(kb*128 + lr) * HD) + lcB;
        const char* pkl = (const char*)(kl + (size_t)(kb*128 + lr) * HD) + lcB;
        #pragma unroll
        for (int j = 0; j < 4; j++) {
            unsigned o = swz(lr, lcB + 16*j);
            cp16(st + o,         pkh + 16*j, true);
            cp16(st + 16384 + o, pkl + 16*j, true);
        }
        int vr = tid >> 2, vc = (tid & 3) << 5;
        #pragma unroll
        for (int c = 0; c < 2; c++) {
            const char* pvh = (const char*)(vth + (size_t)vr * TLEN + kb*128 + c*64) + vc;
            const char* pvl = (const char*)(vtl + (size_t)vr * TLEN + kb*128 + c*64) + vc;
            unsigned vb = st + 32768 + (unsigned)c * 8192;
            #pragma unroll
            for (int j = 0; j < 2; j++) {
                unsigned o = swz(vr, vc + 16*j);
                cp16(vb + o,         pvh + 16*j, true);
                cp16(vb + 16384 + o, pvl + 16*j, true);
            }
        }
    };

    load_stage(0, 0);
    CP_COMMIT();
    CP_WAIT_1();
    __syncthreads();

    unsigned qfh[4][4], qfl[4][4];
    const int a_rin = lane & 15, a_cB = (lane >> 4) * 16;
    #pragma unroll
    for (int ks = 0; ks < 4; ks++) {
        unsigned o = swz(wid*16 + a_rin, ks*32 + a_cB);
        ldmx4(qfh[ks], sQ + o);
        ldmx4(qfl[ks], sQ + FA_QTILE + o);
    }

    float O[8][4];
    #pragma unroll
    for (int i = 0; i < 8; i++)
        #pragma unroll
        for (int t = 0; t < 4; t++) O[i][t] = 0.f;
    float mrun0 = -1e30f, mrun1 = -1e30f, lrun0 = 0.f, lrun1 = 0.f;

    const int b_sel = lane >> 3;
    const int b_rin = (b_sel >> 1)*8 + (lane & 7);
    const int b_cB  = (b_sel & 1)*16;
    const int g = lane >> 2, tig = lane & 3;

    for (int kb = 0; kb < nkb; kb++) {
        if (kb + 1 < nkb) { load_stage(kb + 1, (kb + 1) & 1); CP_COMMIT(); CP_WAIT_1(); }
        else CP_WAIT_0();
        __syncthreads();
        const unsigned st = sStage + (unsigned)(kb & 1) * FA_STAGE;

        float S[16][4];
        #pragma unroll
        for (int j = 0; j < 16; j++)
            #pragma unroll
            for (int t = 0; t < 4; t++) S[j][t] = 0.f;

        #pragma unroll
        for (int ks = 0; ks < 4; ks++) {
            #pragma unroll
            for (int jp = 0; jp < 8; jp++) {
                unsigned o = swz(jp*16 + b_rin, ks*32 + b_cB);
                unsigned rh[4], rl[4];
                ldmx4(rh, st + o);
                ldmx4(rl, st + 16384 + o);
                unsigned bh0[2] = {rh[0], rh[1]}, bh1[2] = {rh[2], rh[3]};
                unsigned bl0[2] = {rl[0], rl[1]}, bl1[2] = {rl[2], rl[3]};
                mma16816(S[2*jp],   qfh[ks], bh0);
                mma16816(S[2*jp],   qfl[ks], bh0);
                mma16816(S[2*jp],   qfh[ks], bl0);
                mma16816(S[2*jp+1], qfh[ks], bh1);
                mma16816(S[2*jp+1], qfl[ks], bh1);
                mma16816(S[2*jp+1], qfh[ks], bl1);
            }
        }
        #pragma unroll
        for (int j = 0; j < 16; j++)
            #pragma unroll
            for (int t = 0; t < 4; t++) S[j][t] *= 0.125f;

        if (kb == nkb - 1) {
            int row0 = m0 + wid*16 + g;
            int row1 = row0 + 8;
            #pragma unroll
            for (int j = 0; j < 16; j++) {
                int col = kb*128 + j*8 + tig*2;
                if (col     > row0) S[j][0] = -1e30f;
                if (col + 1 > row0) S[j][1] = -1e30f;
                if (col     > row1) S[j][2] = -1e30f;
                if (col + 1 > row1) S[j][3] = -1e30f;
            }
        }

        float mx0 = -1e30f, mx1 = -1e30f;
        #pragma unroll
        for (int j = 0; j < 16; j++) {
            mx0 = fmaxf(mx0, fmaxf(S[j][0], S[j][1]));
            mx1 = fmaxf(mx1, fmaxf(S[j][2], S[j][3]));
        }
        mx0 = fmaxf(mx0, __shfl_xor_sync(0xffffffffu, mx0, 1));
        mx0 = fmaxf(mx0, __shfl_xor_sync(0xffffffffu, mx0, 2));
        mx1 = fmaxf(mx1, __shfl_xor_sync(0xffffffffu, mx1, 1));
        mx1 = fmaxf(mx1, __shfl_xor_sync(0xffffffffu, mx1, 2));
        float nm0 = fmaxf(mrun0, mx0), nm1 = fmaxf(mrun1, mx1);
        float f0 = expf(mrun0 - nm0), f1 = expf(mrun1 - nm1);
        mrun0 = nm0; mrun1 = nm1;
        float rs0 = 0.f, rs1 = 0.f;
        #pragma unroll
        for (int j = 0; j < 16; j++) {
            S[j][0] = expf(S[j][0] - nm0);
            S[j][1] = expf(S[j][1] - nm0);
            S[j][2] = expf(S[j][2] - nm1);
            S[j][3] = expf(S[j][3] - nm1);
            rs0 += S[j][0] + S[j][1];
            rs1 += S[j][2] + S[j][3];
        }
        rs0 += __shfl_xor_sync(0xffffffffu, rs0, 1);
        rs0 += __shfl_xor_sync(0xffffffffu, rs0, 2);
        rs1 += __shfl_xor_sync(0xffffffffu, rs1, 1);
        rs1 += __shfl_xor_sync(0xffffffffu, rs1, 2);
        lrun0 = lrun0 * f0 + rs0;
        lrun1 = lrun1 * f1 + rs1;
        #pragma unroll
        for (int i = 0; i < 8; i++) {
            O[i][0] *= f0; O[i][1] *= f0;
            O[i][2] *= f1; O[i][3] *= f1;
        }

        #pragma unroll
        for (int c2 = 0; c2 < 2; c2++) {
            const unsigned vst = st + 32768 + (unsigned)c2 * 8192;
            #pragma unroll
            for (int ks = 0; ks < 4; ks++) {
                const int sI = c2*4 + ks;
                const float* e0 = S[2*sI];
                const float* e1 = S[2*sI + 1];
                unsigned ah[4], al[4];
                ah[0] = packbf(e0[0], e0[1]);
                ah[1] = packbf(e0[2], e0[3]);
                ah[2] = packbf(e1[0], e1[1]);
                ah[3] = packbf(e1[2], e1[3]);
                al[0] = packbf(e0[0] - __bfloat162float(__float2bfloat16(e0[0])),
                               e0[1] - __bfloat162float(__float2bfloat16(e0[1])));
                al[1] = packbf(e0[2] - __bfloat162float(__float2bfloat16(e0[2])),
                               e0[3] - __bfloat162float(__float2bfloat16(e0[3])));
                al[2] = packbf(e1[0] - __bfloat162float(__float2bfloat16(e1[0])),
                               e1[1] - __bfloat162float(__float2bfloat16(e1[1])));
                al[3] = packbf(e1[2] - __bfloat162float(__float2bfloat16(e1[2])),
                               e1[3] - __bfloat162float(__float2bfloat16(e1[3])));
                #pragma unroll
                for (int jp = 0; jp < 4; jp++) {
                    unsigned o = swz(jp*16 + b_rin, ks*32 + b_cB);
                    unsigned rh[4], rl[4];
                    ldmx4(rh, vst + o);
                    ldmx4(rl, vst + 16384 + o);
                    unsigned bh0[2] = {rh[0], rh[1]}, bh1[2] = {rh[2], rh[3]};
                    unsigned bl0[2] = {rl[0], rl[1]}, bl1[2] = {rl[2], rl[3]};
                    mma16816(O[2*jp],   ah, bh0);
                    mma16816(O[2*jp],   al, bh0);
                    mma16816(O[2*jp],   ah, bl0);
                    mma16816(O[2*jp+1], ah, bh1);
                    mma16816(O[2*jp+1], al, bh1);
                    mma16816(O[2*jp+1], ah, bl1);
                }
            }
        }
        __syncthreads();
    }

    float inv0 = 1.f / lrun0, inv1 = 1.f / lrun1;
    float* y0 = YH + ((size_t)bh * TLEN + m0 + wid*16 + g) * HD;
    float* y1 = y0 + 8 * HD;
    #pragma unroll
    for (int i = 0; i < 8; i++) {
        int d = i*8 + tig*2;
        y0[d]     = O[i][0] * inv0;
        y0[d + 1] = O[i][1] * inv0;
        y1[d]     = O[i][2] * inv1;
        y1[d + 1] = O[i][3] * inv1;
    }
}

// ======================== small kernels ======================================
__global__ void detect_idx_kernel(const unsigned int* w) {
    __shared__ unsigned int s;
    if (threadIdx.x == 0) s = 0u;
    __syncthreads();
    unsigned int v = 0u;
    for (int i = threadIdx.x; i < 1024; i += blockDim.x) v |= w[2*i + 1];
    atomicOr(&s, v);
    __syncthreads();
    if (threadIdx.x == 0) g_idx32 = (s != 0u) ? 1 : 0;
}

__global__ void embed_kernel(const void* idx, const float* __restrict__ wte,
                             const float* __restrict__ wpe, float* __restrict__ x) {
    int i = blockIdx.x * blockDim.x + threadIdx.x;
    if (i >= MTOK*CDIM) return;
    int c  = i % CDIM;
    int bt = i / CDIM;
    int t  = bt % TLEN;
    long long tok;
    if (g_idx32) tok = (long long)((const int*)idx)[bt];
    else         tok = ((const long long*)idx)[bt];
    x[i] = wte[tok*CDIM + c] + wpe[(long long)t*CDIM + c];
}

__global__ void ln_lora_kernel(const float* __restrict__ x, const float* __restrict__ g,
                               const float* __restrict__ b,
                               const float* __restrict__ lA,
                               __nv_bfloat16* __restrict__ oh, __nv_bfloat16* __restrict__ ol,
                               float* __restrict__ tmp) {
    const int row = blockIdx.x;
    const float* xr = x + (long long)row * CDIM;
    __shared__ float sx[CDIM];
    __shared__ float red[128];
    __shared__ float s_mean, s_rstd;
    int tid = threadIdx.x;
    float s = 0.f;
    for (int c = tid; c < CDIM; c += 128) { float v = xr[c]; sx[c] = v; s += v; }
    red[tid] = s; __syncthreads();
    for (int st = 64; st > 0; st >>= 1) { if (tid < st) red[tid] += red[tid+st]; __syncthreads(); }
    if (tid == 0) s_mean = red[0] / (float)CDIM;
    __syncthreads();
    float mean = s_mean;
    float sq = 0.f;
    for (int c = tid; c < CDIM; c += 128) { float d = sx[c] - mean; sq += d*d; }
    red[tid] = sq; __syncthreads();
    for (int st = 64; st > 0; st >>= 1) { if (tid < st) red[tid] += red[tid+st]; __syncthreads(); }
    if (tid == 0) s_rstd = rsqrtf(red[0] / (float)CDIM + 1e-5f);
    __syncthreads();
    float mean2 = s_mean, rstd = s_rstd;
    for (int c = tid; c < CDIM; c += 128) {
        float v = (sx[c] - mean2) * rstd * g[c] + b[c];
        long long o = (long long)row*CDIM + c;
        __nv_bfloat16 hi, lo; bsplit(v, hi, lo);
        oh[o] = hi; ol[o] = lo;
        sx[c] = v;
    }
    __syncthreads();
    if (lA) {
        int w = tid >> 5, lane = tid & 31;
        #pragma unroll
        for (int rr = 0; rr < 2; ++rr) {
            int r = w*2 + rr;
            const float* Ar = lA + (long long)r * CDIM;
            float acc = 0.f;
            for (int c = lane; c < CDIM; c += 32) acc += sx[c] * Ar[c];
            #pragma unroll
            for (int off = 16; off > 0; off >>= 1) acc += __shfl_down_sync(0xffffffffu, acc, off);
            if (lane == 0) tmp[row*RANK + r] = acc;
        }
    }
}

__global__ void ln_f16_kernel(const float* __restrict__ x, const float* __restrict__ g,
                              const float* __restrict__ b, __half* __restrict__ oh) {
    const int row = blockIdx.x;
    const float* xr = x + (long long)row * CDIM;
    __shared__ float sx[CDIM];
    __shared__ float red[128];
    __shared__ float s_mean, s_rstd;
    int tid = threadIdx.x;
    float s = 0.f;
    for (int c = tid; c < CDIM; c += 128) { float v = xr[c]; sx[c] = v; s += v; }
    red[tid] = s; __syncthreads();
    for (int st = 64; st > 0; st >>= 1) { if (tid < st) red[tid] += red[tid+st]; __syncthreads(); }
    if (tid == 0) s_mean = red[0] / (float)CDIM;
    __syncthreads();
    float mean = s_mean;
    float sq = 0.f;
    for (int c = tid; c < CDIM; c += 128) { float d = sx[c] - mean; sq += d*d; }
    red[tid] = sq; __syncthreads();
    for (int st = 64; st > 0; st >>= 1) { if (tid < st) red[tid] += red[tid+st]; __syncthreads(); }
    if (tid == 0) s_rstd = rsqrtf(red[0] / (float)CDIM + 1e-5f);
    __syncthreads();
    float mean2 = s_mean, rstd = s_rstd;
    for (int c = tid; c < CDIM; c += 128) {
        float v = (sx[c] - mean2) * rstd * g[c] + b[c];
        oh[(long long)row*CDIM + c] = __float2half(v);
    }
}

__global__ void wsplitA_kernel(const float* __restrict__ wq, const float* __restrict__ wp,
                               const float* __restrict__ wf, const float* __restrict__ wm,
                               __nv_bfloat16* __restrict__ qh, __nv_bfloat16* __restrict__ ql,
                               __nv_bfloat16* __restrict__ ph, __nv_bfloat16* __restrict__ pl,
                               __nv_bfloat16* __restrict__ fh, __nv_bfloat16* __restrict__ fl,
                               __nv_bfloat16* __restrict__ mh, __nv_bfloat16* __restrict__ ml) {
    const int NQ = NLAYER*3*CDIM*CDIM, NP = NLAYER*CDIM*CDIM,
              NF = NLAYER*4*CDIM*CDIM, NM = NLAYER*CDIM*4*CDIM;
    int i4 = (blockIdx.x * 256 + threadIdx.x) * 4;
    const float* src; __nv_bfloat16 *dh, *dl; int k;
    if (i4 < NQ)                { src = wq; dh = qh; dl = ql; k = i4; }
    else if (i4 < NQ+NP)        { src = wp; dh = ph; dl = pl; k = i4 - NQ; }
    else if (i4 < NQ+NP+NF)     { src = wf; dh = fh; dl = fl; k = i4 - NQ - NP; }
    else if (i4 < NQ+NP+NF+NM)  { src = wm; dh = mh; dl = ml; k = i4 - NQ - NP - NF; }
    else return;
    float4 v = *reinterpret_cast<const float4*>(src + k);
    __nv_bfloat16 h0, l0, h1, l1, h2, l2, h3, l3;
    bsplit(v.x, h0, l0); bsplit(v.y, h1, l1);
    bsplit(v.z, h2, l2); bsplit(v.w, h3, l3);
    uint2 hv, lv;
    hv.x = ((unsigned)__bfloat16_as_ushort(h1) << 16) | __bfloat16_as_ushort(h0);
    hv.y = ((unsigned)__bfloat16_as_ushort(h3) << 16) | __bfloat16_as_ushort(h2);
    lv.x = ((unsigned)__bfloat16_as_ushort(l1) << 16) | __bfloat16_as_ushort(l0);
    lv.y = ((unsigned)__bfloat16_as_ushort(l3) << 16) | __bfloat16_as_ushort(l2);
    *reinterpret_cast<uint2*>(dh + k) = hv;
    *reinterpret_cast<uint2*>(dl + k) = lv;
}

__global__ void wsplit_f16_kernel(const float* __restrict__ w, __half* __restrict__ h, int n) {
    int i4 = (blockIdx.x * 256 + threadIdx.x) * 4;
    if (i4 >= n) return;
    float4 v = *reinterpret_cast<const float4*>(w + i4);
    __half2 a = __floats2half2_rn(v.x, v.y);
    __half2 b = __floats2half2_rn(v.z, v.w);
    uint2 o;
    o.x = reinterpret_cast<unsigned&>(a);
    o.y = reinterpret_cast<unsigned&>(b);
    *reinterpret_cast<uint2*>(h + i4) = o;
}

__global__ void merge_lora_kernel(const float* __restrict__ yh,
                                  const float* __restrict__ lA,
                                  __nv_bfloat16* __restrict__ oh, __nv_bfloat16* __restrict__ ol,
                                  float* __restrict__ tmp) {
    const int row = blockIdx.x;
    const int t = row & (TLEN - 1);
    const int b = row >> 10;
    __shared__ float sy[CDIM];
    int tid = threadIdx.x;
    for (int c = tid; c < CDIM; c += 128) {
        int h = c >> 6, d = c & 63;
        sy[c] = yh[(((long long)(b*NHEAD + h) * TLEN) + t) * HD + d];
    }
    __syncthreads();
    for (int c = tid; c < CDIM; c += 128) {
        long long o = (long long)row*CDIM + c;
        __nv_bfloat16 hi, lo; bsplit(sy[c], hi, lo);
        oh[o] = hi; ol[o] = lo;
    }
    int w = tid >> 5, lane = tid & 31;
    #pragma unroll
    for (int rr = 0; rr < 2; ++rr) {
        int r = w*2 + rr;
        const float* Ar = lA + (long long)r * CDIM;
        float acc = 0.f;
        for (int c = lane; c < CDIM; c += 32) acc += sy[c] * Ar[c];
        #pragma unroll
        for (int off = 16; off > 0; off >>= 1) acc += __shfl_down_sync(0xffffffffu, acc, off);
        if (lane == 0) tmp[row*RANK + r] = acc;
    }
}

// ======================== host driver ========================================
template<int MODE, int SPLITK>
static void launch_gemm(dim3 grid,
                        const __nv_bfloat16* Ah, const __nv_bfloat16* Al,
                        const __nv_bfloat16* Bh, const __nv_bfloat16* Bl,
                        const float* bias, const float* loraT, const float* loraB,
                        float* Cm, int M, int N, int K) {
    cudaFuncSetAttribute(mma_gemm<MODE, SPLITK>,
                         cudaFuncAttributeMaxDynamicSharedMemorySize, GEMM_SMEM);
    mma_gemm<MODE, SPLITK><<<grid, 256, GEMM_SMEM>>>(
        Ah, Al, Bh, Bl, bias, loraT, loraB, Cm, M, N, K);
}

extern "C" void kernel_launch(void* const* d_in, const int* in_sizes, int n_in,
                              void* d_out, int out_size) {
    (void)in_sizes; (void)n_in; (void)out_size;
    const void*  idx     = d_in[0];
    const float* wte     = (const float*)d_in[1];
    const float* wpe     = (const float*)d_in[2];
    const float* ln1_g   = (const float*)d_in[3];
    const float* ln1_b   = (const float*)d_in[4];
    const float* attn_w  = (const float*)d_in[5];
    const float* attn_lA = (const float*)d_in[6];
    const float* attn_lB = (const float*)d_in[7];
    const float* proj_w  = (const float*)d_in[8];
    const float* proj_lA = (const float*)d_in[9];
    const float* proj_lB = (const float*)d_in[10];
    const float* ln2_g   = (const float*)d_in[11];
    const float* ln2_b   = (const float*)d_in[12];
    const float* fc_w    = (const float*)d_in[13];
    const float* fc_b    = (const float*)d_in[14];
    const float* mproj_w = (const float*)d_in[15];
    const float* mproj_b = (const float*)d_in[16];
    const float* lnf_g   = (const float*)d_in[17];
    const float* lnf_b   = (const float*)d_in[18];
    const float* head_w  = (const float*)d_in[19];
    float* out = (float*)d_out;

    float *X, *YH, *TMP;
    cudaGetSymbolAddress((void**)&X,   g_X);
    cudaGetSymbolAddress((void**)&YH,  g_YH);
    cudaGetSymbolAddress((void**)&TMP, g_TMP);

    __nv_bfloat16 *wqkv_h, *wqkv_l, *wproj_h, *wproj_l, *wfc_h, *wfc_l, *wmp_h, *wmp_l,
                  *Hh, *Hl, *Yh, *Yl, *FCGh, *FCGl,
                  *Qh, *Ql, *Kh, *Kl, *Vth, *Vtl;
    __half *whead16, *H16;
    cudaGetSymbolAddress((void**)&wqkv_h,  g_wqkv_h);  cudaGetSymbolAddress((void**)&wqkv_l,  g_wqkv_l);
    cudaGetSymbolAddress((void**)&wproj_h, g_wproj_h); cudaGetSymbolAddress((void**)&wproj_l, g_wproj_l);
    cudaGetSymbolAddress((void**)&wfc_h,   g_wfc_h);   cudaGetSymbolAddress((void**)&wfc_l,   g_wfc_l);
    cudaGetSymbolAddress((void**)&wmp_h,   g_wmp_h);   cudaGetSymbolAddress((void**)&wmp_l,   g_wmp_l);
    cudaGetSymbolAddress((void**)&whead16, g_whead16);
    cudaGetSymbolAddress((void**)&H16,  g_H16);
    cudaGetSymbolAddress((void**)&Hh,   g_Hh);   cudaGetSymbolAddress((void**)&Hl,   g_Hl);
    cudaGetSymbolAddress((void**)&Yh,   g_Yhb);  cudaGetSymbolAddress((void**)&Yl,   g_Ylb);
    cudaGetSymbolAddress((void**)&FCGh, g_FCGh); cudaGetSymbolAddress((void**)&FCGl, g_FCGl);
    cudaGetSymbolAddress((void**)&Qh,   g_Qh);   cudaGetSymbolAddress((void**)&Ql,   g_Ql);
    cudaGetSymbolAddress((void**)&Kh,   g_Kh);   cudaGetSymbolAddress((void**)&Kl,   g_Kl);
    cudaGetSymbolAddress((void**)&Vth,  g_Vth);  cudaGetSymbolAddress((void**)&Vtl,  g_Vtl);

    cudaFuncSetAttribute(flash_attn, cudaFuncAttributeMaxDynamicSharedMemorySize, FA_SMEM);

    detect_idx_kernel<<<1, 256>>>((const unsigned int*)idx);
    embed_kernel<<<(MTOK*CDIM + 255)/256, 256>>>(idx, wte, wpe, X);
    {
        int nA = NLAYER*(3*CDIM*CDIM + CDIM*CDIM + 4*CDIM*CDIM + 4*CDIM*CDIM);
        wsplitA_kernel<<<(nA/4 + 255)/256, 256>>>(attn_w, proj_w, fc_w, mproj_w,
            wqkv_h, wqkv_l, wproj_h, wproj_l, wfc_h, wfc_l, wmp_h, wmp_l);
        int nB = VOCAB*CDIM;
        wsplit_f16_kernel<<<(nB/4 + 255)/256, 256>>>(head_w, whead16, nB);
    }

    for (int l = 0; l < NLAYER; l++) {
        long long oq = (long long)l * 3*CDIM*CDIM;
        long long op = (long long)l * CDIM*CDIM;
        long long of = (long long)l * 4*CDIM*CDIM;
        long long om = (long long)l * CDIM*4*CDIM;
        const float* lA_q = attn_lA + (long long)l * RANK*CDIM;
        const float* lB_q = attn_lB + (long long)l * 3*CDIM*RANK;
        const float* lA_p = proj_lA + (long long)l * RANK*CDIM;
        const float* lB_p = proj_lB + (long long)l * CDIM*RANK;

        // ---- attention ----
        ln_lora_kernel<<<MTOK, 128>>>(X, ln1_g + l*CDIM, ln1_b + l*CDIM, lA_q, Hh, Hl, TMP);
        launch_gemm<3, 0>(dim3(MTOK/128, 3*CDIM/128, 1),
            Hh, Hl, wqkv_h + oq, wqkv_l + oq, nullptr, TMP, lB_q, nullptr,
            MTOK, 3*CDIM, CDIM);

        flash_attn<<<dim3(TLEN/128, NBATCH), 256, FA_SMEM>>>(Qh, Ql, Kh, Kl, Vth, Vtl, YH);
        merge_lora_kernel<<<MTOK, 128>>>(YH, lA_p, Yh, Yl, TMP);

        // proj: split-K=2 (grid 16x4x2 = 128 CTAs), atomicAdd residual into X
        launch_gemm<2, 1>(dim3(MTOK/128, CDIM/128, 2),
            Yh, Yl, wproj_h + op, wproj_l + op, nullptr, TMP, lB_p, X,
            MTOK, CDIM, CDIM);

        // ---- MLP ----
        ln_lora_kernel<<<MTOK, 128>>>(X, ln2_g + l*CDIM, ln2_b + l*CDIM, nullptr, Hh, Hl, TMP);
        launch_gemm<1, 0>(dim3(MTOK/128, 4*CDIM/128, 1),
            Hh, Hl, wfc_h + of, wfc_l + of, fc_b + (long long)l*4*CDIM, nullptr, nullptr, nullptr,
            MTOK, 4*CDIM, CDIM);
        // mproj: split-K=2 (grid 16x4x2 = 128 CTAs)
        launch_gemm<2, 1>(dim3(MTOK/128, CDIM/128, 2),
            FCGh, FCGl, wmp_h + om, wmp_l + om, mproj_b + (long long)l*CDIM, nullptr, nullptr, X,
            MTOK, CDIM, 4*CDIM);
    }

    // ---- final layernorm + fp16 1-MMA vocab head (128x128, occ=2) ----
    ln_f16_kernel<<<MTOK, 128>>>(X, lnf_g, lnf_b, H16);
    cudaFuncSetAttribute(mma_gemm_f16, cudaFuncAttributeMaxDynamicSharedMemorySize, GEMM_SMEM_F16);
    mma_gemm_f16<<<dim3(MTOK/128, (VOCAB + 127)/128), 256, GEMM_SMEM_F16>>>(
        H16, whead16, out, MTOK, VOCAB, CDIM);
}

// round 13
// speedup vs baseline: 1.2980x; 1.0107x over previous
#include <cuda_runtime.h>
#include <cuda_bf16.h>
#include <cuda_fp16.h>
#include <math.h>

// ---------------------------------------------------------------------------
// GPT_3959959847300 round 13: R12 + split-K=2 for qkv GEMM (dual fp32 partial
// buffers + combine/scatter kernel). proj/mproj keep atomic split-K=2.
// ---------------------------------------------------------------------------

#define BSZ    2
#define TLEN   1024
#define CDIM   512
#define NHEAD  8
#define HD     64
#define NLAYER 4
#define VOCAB  50257
#define RANK   8
#define LSCALE 4.0f
#define MTOK   (BSZ*TLEN)
#define NBATCH (BSZ*NHEAD)

// ======================== PTX helpers ========================================
__device__ __forceinline__ unsigned smem_u32(const void* p) {
    unsigned a;
    asm("{ .reg .u64 t; cvta.to.shared.u64 t, %1; cvt.u32.u64 %0, t; }" : "=r"(a) : "l"(p));
    return a;
}
__device__ __forceinline__ void ldmx4(unsigned* r, unsigned addr) {
    asm volatile("ldmatrix.sync.aligned.m8n8.x4.shared.b16 {%0,%1,%2,%3}, [%4];"
                 : "=r"(r[0]), "=r"(r[1]), "=r"(r[2]), "=r"(r[3]) : "r"(addr));
}
__device__ __forceinline__ void mma16816(float* d, const unsigned* a, const unsigned* b) {
    asm volatile(
        "mma.sync.aligned.m16n8k16.row.col.f32.bf16.bf16.f32 "
        "{%0,%1,%2,%3},{%4,%5,%6,%7},{%8,%9},{%0,%1,%2,%3};"
        : "+f"(d[0]), "+f"(d[1]), "+f"(d[2]), "+f"(d[3])
        : "r"(a[0]), "r"(a[1]), "r"(a[2]), "r"(a[3]), "r"(b[0]), "r"(b[1]));
}
__device__ __forceinline__ void mma16816h(float* d, const unsigned* a, const unsigned* b) {
    asm volatile(
        "mma.sync.aligned.m16n8k16.row.col.f32.f16.f16.f32 "
        "{%0,%1,%2,%3},{%4,%5,%6,%7},{%8,%9},{%0,%1,%2,%3};"
        : "+f"(d[0]), "+f"(d[1]), "+f"(d[2]), "+f"(d[3])
        : "r"(a[0]), "r"(a[1]), "r"(a[2]), "r"(a[3]), "r"(b[0]), "r"(b[1]));
}
__device__ __forceinline__ void cp16(unsigned dst, const void* src, bool pred) {
    int sz = pred ? 16 : 0;
    asm volatile("cp.async.cg.shared.global [%0], [%1], 16, %2;"
                 :: "r"(dst), "l"(src), "r"(sz) : "memory");
}
#define CP_COMMIT()  asm volatile("cp.async.commit_group;" ::: "memory")
#define CP_WAIT_1()  asm volatile("cp.async.wait_group 1;" ::: "memory")
#define CP_WAIT_0()  asm volatile("cp.async.wait_group 0;" ::: "memory")

__device__ __forceinline__ void bsplit(float x, __nv_bfloat16& hi, __nv_bfloat16& lo) {
    hi = __float2bfloat16(x);
    lo = __float2bfloat16(x - __bfloat162float(hi));
}
__device__ __forceinline__ unsigned packbf(float a, float b) {
    __nv_bfloat162 t = __floats2bfloat162_rn(a, b);
    return reinterpret_cast<unsigned&>(t);
}

// ======================== scratch ============================================
__device__ float g_X  [MTOK*CDIM];
__device__ float g_YH [NBATCH*TLEN*HD];
__device__ float g_TMP[MTOK*RANK];
__device__ float g_QKVp[2ll*MTOK*3*CDIM];    // split-K partials for qkv
__device__ int   g_idx32;

__device__ __nv_bfloat16 g_wqkv_h[NLAYER*3*CDIM*CDIM], g_wqkv_l[NLAYER*3*CDIM*CDIM];
__device__ __nv_bfloat16 g_wproj_h[NLAYER*CDIM*CDIM],  g_wproj_l[NLAYER*CDIM*CDIM];
__device__ __nv_bfloat16 g_wfc_h [NLAYER*4*CDIM*CDIM], g_wfc_l [NLAYER*4*CDIM*CDIM];
__device__ __nv_bfloat16 g_wmp_h [NLAYER*CDIM*4*CDIM], g_wmp_l [NLAYER*CDIM*4*CDIM];
__device__ __half        g_whead16[VOCAB*CDIM];
__device__ __nv_bfloat16 g_Hh[MTOK*CDIM],  g_Hl[MTOK*CDIM];
__device__ __half        g_H16[MTOK*CDIM];
__device__ __nv_bfloat16 g_Yhb[MTOK*CDIM], g_Ylb[MTOK*CDIM];
__device__ __nv_bfloat16 g_FCGh[MTOK*4*CDIM], g_FCGl[MTOK*4*CDIM];
__device__ __nv_bfloat16 g_Qh[NBATCH*TLEN*HD], g_Ql[NBATCH*TLEN*HD];
__device__ __nv_bfloat16 g_Kh[NBATCH*TLEN*HD], g_Kl[NBATCH*TLEN*HD];
__device__ __nv_bfloat16 g_Vth[NBATCH*HD*TLEN], g_Vtl[NBATCH*HD*TLEN];

// ======================== common tile helpers ================================
#define TILE_B    16384                 // 128x64 16-bit tile (128B rows, swizzled)
#define STAGE_B   (4*TILE_B)
#define GEMM_SMEM (2*STAGE_B)           // 131072
#define STAGE2_B  (2*TILE_B)            // fp16 head: A, B
#define GEMM_SMEM_F16 (2*STAGE2_B)      // 65536

__device__ __forceinline__ unsigned swz(int row, int colB) {
    unsigned o = (unsigned)(row * 128 + colB);
    return o ^ ((unsigned)(row & 7) << 4);
}

__device__ __forceinline__ void stage_load(
    unsigned sbase,
    const __nv_bfloat16* __restrict__ ah, const __nv_bfloat16* __restrict__ al,
    const __nv_bfloat16* __restrict__ bh, const __nv_bfloat16* __restrict__ bl,
    int m0, int n0, int M, int N, int K, int k0, int lr, int lcB)
{
    {
        int gr = m0 + lr; bool ok = (gr < M); int r = ok ? gr : 0;
        const char* pa = (const char*)(ah + (size_t)r * K + k0) + lcB;
        const char* pl = (const char*)(al + (size_t)r * K + k0) + lcB;
        #pragma unroll
        for (int j = 0; j < 4; j++) {
            unsigned o = swz(lr, lcB + 16*j);
            cp16(sbase + o,          pa + 16*j, ok);
            cp16(sbase + TILE_B + o, pl + 16*j, ok);
        }
    }
    {
        int gr = n0 + lr; bool ok = (gr < N); int r = ok ? gr : 0;
        const char* pb = (const char*)(bh + (size_t)r * K + k0) + lcB;
        const char* pl = (const char*)(bl + (size_t)r * K + k0) + lcB;
        #pragma unroll
        for (int j = 0; j < 4; j++) {
            unsigned o = swz(lr, lcB + 16*j);
            cp16(sbase + 2*TILE_B + o, pb + 16*j, ok);
            cp16(sbase + 3*TILE_B + o, pl + 16*j, ok);
        }
    }
}

// ======================== bf16 3-term dense GEMM =============================
// MODE: 0 plain fp32 store (SPLITK: per-z partial buffers, +bias/lora on z==0)
//       1 gelu->bf16 split; 2 residual += (atomicAdd if SPLITK)
// SPLITK: 0 normal; 1 K halved across blockIdx.z
template<int MODE, int SPLITK>
__global__ __launch_bounds__(256, 1)
void mma_gemm(const __nv_bfloat16* __restrict__ Ah, const __nv_bfloat16* __restrict__ Al,
              const __nv_bfloat16* __restrict__ Bh, const __nv_bfloat16* __restrict__ Bl,
              const float* __restrict__ bias,
              const float* __restrict__ loraT, const float* __restrict__ loraB,
              float* __restrict__ Cm,
              int M, int N, int K)
{
    extern __shared__ char smem_raw[];
    const int m0 = blockIdx.x * 128;
    const int n0 = blockIdx.y * 128;
    const int kz = SPLITK ? (int)blockIdx.z : 0;
    const int kslice = SPLITK ? (K >> 1) : K;
    const int koff = kz * kslice;

    const unsigned sbase = smem_u32(smem_raw);
    const int tid  = threadIdx.x;
    const int lane = tid & 31;
    const int wid  = tid >> 5;
    const int wm   = wid & 1;
    const int wn   = wid >> 1;
    const int lr   = tid >> 1;
    const int lcB  = (tid & 1) << 6;

    float acc[4][4][4];
    #pragma unroll
    for (int i = 0; i < 4; i++)
        #pragma unroll
        for (int j = 0; j < 4; j++)
            #pragma unroll
            for (int t = 0; t < 4; t++) acc[i][j][t] = 0.f;

    const int nc = kslice >> 6;

    stage_load(sbase, Ah, Al, Bh, Bl, m0, n0, M, N, K, koff, lr, lcB);
    CP_COMMIT();

    const int a_rin  = lane & 15;
    const int a_cB   = (lane >> 4) * 16;
    const int b_sel  = lane >> 3;
    const int b_rin  = (b_sel >> 1) * 8 + (lane & 7);
    const int b_cB   = (b_sel & 1) * 16;

    for (int cI = 0; cI < nc; ++cI) {
        const int s = cI & 1;
        if (cI + 1 < nc) {
            stage_load(sbase + (unsigned)(1 - s) * STAGE_B, Ah, Al, Bh, Bl,
                       m0, n0, M, N, K, koff + ((cI + 1) << 6), lr, lcB);
            CP_COMMIT();
            CP_WAIT_1();
        } else {
            CP_WAIT_0();
        }
        __syncthreads();

        const unsigned st = sbase + (unsigned)s * STAGE_B;
        #pragma unroll
        for (int ks = 0; ks < 4; ++ks) {
            unsigned ra_h[4][4], ra_l[4][4], rb_h[4][2], rb_l[4][2];
            #pragma unroll
            for (int i = 0; i < 4; ++i) {
                int row = wm*64 + i*16 + a_rin;
                unsigned o = swz(row, ks*32 + a_cB);
                ldmx4(ra_h[i], st + o);
                ldmx4(ra_l[i], st + TILE_B + o);
            }
            #pragma unroll
            for (int jp = 0; jp < 2; ++jp) {
                int row = wn*32 + jp*16 + b_rin;
                unsigned o = swz(row, ks*32 + b_cB);
                unsigned r[4];
                ldmx4(r, st + 2*TILE_B + o);
                rb_h[2*jp][0] = r[0]; rb_h[2*jp][1] = r[1];
                rb_h[2*jp+1][0] = r[2]; rb_h[2*jp+1][1] = r[3];
                ldmx4(r, st + 3*TILE_B + o);
                rb_l[2*jp][0] = r[0]; rb_l[2*jp][1] = r[1];
                rb_l[2*jp+1][0] = r[2]; rb_l[2*jp+1][1] = r[3];
            }
            #pragma unroll
            for (int i = 0; i < 4; ++i)
                #pragma unroll
                for (int j = 0; j < 4; ++j) {
                    mma16816(acc[i][j], ra_h[i], rb_h[j]);
                    mma16816(acc[i][j], ra_l[i], rb_h[j]);
                    mma16816(acc[i][j], ra_h[i], rb_l[j]);
                }
        }
        __syncthreads();
    }

    const int group = lane >> 2, tig = lane & 3;
    float* cbuf = (MODE == 0) ? (Cm + (size_t)kz * M * N) : Cm;
    #pragma unroll
    for (int i = 0; i < 4; ++i) {
        int m_lo = m0 + wm*64 + i*16 + group;
        #pragma unroll
        for (int j = 0; j < 4; ++j) {
            int nA = n0 + wn*32 + j*8 + tig*2;
            #pragma unroll
            for (int h = 0; h < 2; ++h) {
                int m = m_lo + h*8;
                if (m >= M) continue;
                #pragma unroll
                for (int e = 0; e < 2; ++e) {
                    int n = nA + e;
                    if (n >= N) continue;
                    float v = acc[i][j][h*2 + e];
                    if (bias && kz == 0)  v += bias[n];
                    if (loraT && kz == 0) {
                        const float* t  = loraT + (size_t)m * RANK;
                        const float* bb = loraB + (size_t)n * RANK;
                        float s = 0.f;
                        #pragma unroll
                        for (int r = 0; r < RANK; r++) s += t[r] * bb[r];
                        v += LSCALE * s;
                    }
                    if (MODE == 0) {
                        cbuf[(long long)m * N + n] = v;
                    } else if (MODE == 2) {
                        if (SPLITK) atomicAdd(&Cm[(long long)m * N + n], v);
                        else        Cm[(long long)m * N + n] += v;
                    } else { // MODE 1: gelu -> bf16 split
                        float gv = 0.5f * v * (1.f + tanhf(0.7978845608028654f * (v + 0.044715f * v*v*v)));
                        __nv_bfloat16 hi, lo; bsplit(gv, hi, lo);
                        g_FCGh[(long long)m * N + n] = hi;
                        g_FCGl[(long long)m * N + n] = lo;
                    }
                }
            }
        }
    }
}

// combine qkv split-K partials -> Q/K (bhtd) and V^T (bhdt) bf16 hi/lo
__global__ void split_qkv2_kernel(const float* __restrict__ qkvp) {
    int i = blockIdx.x * 256 + threadIdx.x;
    if (i >= NBATCH*TLEN*HD) return;
    int d = i % HD;
    int t = (i / HD) % TLEN;
    int h = (i / (HD*TLEN)) % NHEAD;
    int b = i / (HD*TLEN*NHEAD);
    long long src = (long long)(b*TLEN + t) * (3*CDIM) + h*HD + d;
    const long long off = (long long)MTOK * 3*CDIM;
    __nv_bfloat16 hi, lo;
    float q = qkvp[src] + qkvp[src + off];
    float k = qkvp[src + CDIM] + qkvp[src + CDIM + off];
    float v = qkvp[src + 2*CDIM] + qkvp[src + 2*CDIM + off];
    bsplit(q, hi, lo); g_Qh[i] = hi; g_Ql[i] = lo;
    bsplit(k, hi, lo); g_Kh[i] = hi; g_Kl[i] = lo;
    long long vi = ((long long)(b*NHEAD + h) * HD + d) * TLEN + t;
    bsplit(v, hi, lo); g_Vth[vi] = hi; g_Vtl[vi] = lo;
}

// ======================== fp16 1-MMA head GEMM (128x128, occ=2) ==============
__global__ __launch_bounds__(256, 2)
void mma_gemm_f16(const __half* __restrict__ Am, const __half* __restrict__ Bm,
                  float* __restrict__ Cm, int M, int N, int K)
{
    extern __shared__ char smem_raw[];
    const int m0 = blockIdx.x * 128;
    const int n0 = blockIdx.y * 128;

    const unsigned sbase = smem_u32(smem_raw);
    const int tid  = threadIdx.x;
    const int lane = tid & 31;
    const int wid  = tid >> 5;
    const int wm   = wid & 1;
    const int wn   = wid >> 1;
    const int lr   = tid >> 1;
    const int lcB  = (tid & 1) << 6;

    float acc[4][4][4];
    #pragma unroll
    for (int i = 0; i < 4; i++)
        #pragma unroll
        for (int j = 0; j < 4; j++)
            #pragma unroll
            for (int t = 0; t < 4; t++) acc[i][j][t] = 0.f;

    const int nc = K >> 6;

    auto stage2 = [&](unsigned sb, int k0) {
        {
            int gr = m0 + lr; bool ok = (gr < M); int r = ok ? gr : 0;
            const char* pa = (const char*)(Am + (size_t)r * K + k0) + lcB;
            #pragma unroll
            for (int j = 0; j < 4; j++) {
                unsigned o = swz(lr, lcB + 16*j);
                cp16(sb + o, pa + 16*j, ok);
            }
        }
        {
            int gr = n0 + lr; bool ok = (gr < N); int r = ok ? gr : 0;
            const char* pb = (const char*)(Bm + (size_t)r * K + k0) + lcB;
            #pragma unroll
            for (int j = 0; j < 4; j++) {
                unsigned o = swz(lr, lcB + 16*j);
                cp16(sb + TILE_B + o, pb + 16*j, ok);
            }
        }
    };

    stage2(sbase, 0);
    CP_COMMIT();

    const int a_rin  = lane & 15;
    const int a_cB   = (lane >> 4) * 16;
    const int b_sel  = lane >> 3;
    const int b_rin  = (b_sel >> 1) * 8 + (lane & 7);
    const int b_cB   = (b_sel & 1) * 16;

    for (int cI = 0; cI < nc; ++cI) {
        const int s = cI & 1;
        if (cI + 1 < nc) {
            stage2(sbase + (unsigned)(1 - s) * STAGE2_B, (cI + 1) << 6);
            CP_COMMIT();
            CP_WAIT_1();
        } else {
            CP_WAIT_0();
        }
        __syncthreads();

        const unsigned st = sbase + (unsigned)s * STAGE2_B;
        #pragma unroll
        for (int ks = 0; ks < 4; ++ks) {
            unsigned ra[4][4], rb[4][2];
            #pragma unroll
            for (int i = 0; i < 4; ++i) {
                int row = wm*64 + i*16 + a_rin;
                unsigned o = swz(row, ks*32 + a_cB);
                ldmx4(ra[i], st + o);
            }
            #pragma unroll
            for (int jp = 0; jp < 2; ++jp) {
                int row = wn*32 + jp*16 + b_rin;
                unsigned o = swz(row, ks*32 + b_cB);
                unsigned r[4];
                ldmx4(r, st + TILE_B + o);
                rb[2*jp][0] = r[0]; rb[2*jp][1] = r[1];
                rb[2*jp+1][0] = r[2]; rb[2*jp+1][1] = r[3];
            }
            #pragma unroll
            for (int i = 0; i < 4; ++i)
                #pragma unroll
                for (int j = 0; j < 4; ++j)
                    mma16816h(acc[i][j], ra[i], rb[j]);
        }
        __syncthreads();
    }

    const int group = lane >> 2, tig = lane & 3;
    #pragma unroll
    for (int i = 0; i < 4; ++i) {
        int m_lo = m0 + wm*64 + i*16 + group;
        #pragma unroll
        for (int j = 0; j < 4; ++j) {
            int nA = n0 + wn*32 + j*8 + tig*2;
            #pragma unroll
            for (int h = 0; h < 2; ++h) {
                int m = m_lo + h*8;
                if (m >= M) continue;
                float* crow = Cm + (long long)m * N;
                #pragma unroll
                for (int e = 0; e < 2; ++e) {
                    int n = nA + e;
                    if (n < N) crow[n] = acc[i][j][h*2 + e];
                }
            }
        }
    }
}

// ======================== fused flash attention ==============================
#define FA_QTILE 16384
#define FA_STAGE 65536
#define FA_SMEM  (2*FA_QTILE + 2*FA_STAGE)   // 163840

__global__ __launch_bounds__(256, 1)
void flash_attn(const __nv_bfloat16* __restrict__ Qh, const __nv_bfloat16* __restrict__ Ql,
                const __nv_bfloat16* __restrict__ Kh, const __nv_bfloat16* __restrict__ Kl,
                const __nv_bfloat16* __restrict__ Vth, const __nv_bfloat16* __restrict__ Vtl,
                float* __restrict__ YH)
{
    extern __shared__ char smem_raw[];
    const unsigned sbase = smem_u32(smem_raw);
    const int m0 = blockIdx.x * 128;
    const int bh = blockIdx.y;
    const int tid = threadIdx.x;
    const int lane = tid & 31;
    const int wid = tid >> 5;

    const __nv_bfloat16* qh  = Qh  + (size_t)bh * TLEN * HD;
    const __nv_bfloat16* ql  = Ql  + (size_t)bh * TLEN * HD;
    const __nv_bfloat16* kh  = Kh  + (size_t)bh * TLEN * HD;
    const __nv_bfloat16* kl  = Kl  + (size_t)bh * TLEN * HD;
    const __nv_bfloat16* vth = Vth + (size_t)bh * HD * TLEN;
    const __nv_bfloat16* vtl = Vtl + (size_t)bh * HD * TLEN;

    const unsigned sQ = sbase;
    const unsigned sStage = sbase + 2*FA_QTILE;

    {
        int lr = tid >> 1, lcB = (tid & 1) << 6;
        const char* pqh = (const char*)(qh + (size_t)(m0 + lr) * HD) + lcB;
        const char* pql = (const char*)(ql + (size_t)(m0 + lr) * HD) + lcB;
        #pragma unroll
        for (int j = 0; j < 4; j++) {
            unsigned o = swz(lr, lcB + 16*j);
            cp16(sQ + o,            pqh + 16*j, true);
            cp16(sQ + FA_QTILE + o, pql + 16*j, true);
        }
    }
    CP_COMMIT();

    const int nkb = blockIdx.x + 1;

    auto load_stage = [&](int kb, int s) {
        unsigned st = sStage + (unsigned)s * FA_STAGE;
        int lr = tid >> 1, lcB = (tid & 1) << 6;
        const char* pkh = (const char*)(kh + (size_t)(kb*128 + lr) * HD) + lcB;
        const char* pkl = (const char*)(kl + (size_t)(kb*128 + lr) * HD) + lcB;
        #pragma unroll
        for (int j = 0; j < 4; j++) {
            unsigned o = swz(lr, lcB + 16*j);
            cp16(st + o,         pkh + 16*j, true);
            cp16(st + 16384 + o, pkl + 16*j, true);
        }
        int vr = tid >> 2, vc = (tid & 3) << 5;
        #pragma unroll
        for (int c = 0; c < 2; c++) {
            const char* pvh = (const char*)(vth + (size_t)vr * TLEN + kb*128 + c*64) + vc;
            const char* pvl = (const char*)(vtl + (size_t)vr * TLEN + kb*128 + c*64) + vc;
            unsigned vb = st + 32768 + (unsigned)c * 8192;
            #pragma unroll
            for (int j = 0; j < 2; j++) {
                unsigned o = swz(vr, vc + 16*j);
                cp16(vb + o,         pvh + 16*j, true);
                cp16(vb + 16384 + o, pvl + 16*j, true);
            }
        }
    };

    load_stage(0, 0);
    CP_COMMIT();
    CP_WAIT_1();
    __syncthreads();

    unsigned qfh[4][4], qfl[4][4];
    const int a_rin = lane & 15, a_cB = (lane >> 4) * 16;
    #pragma unroll
    for (int ks = 0; ks < 4; ks++) {
        unsigned o = swz(wid*16 + a_rin, ks*32 + a_cB);
        ldmx4(qfh[ks], sQ + o);
        ldmx4(qfl[ks], sQ + FA_QTILE + o);
    }

    float O[8][4];
    #pragma unroll
    for (int i = 0; i < 8; i++)
        #pragma unroll
        for (int t = 0; t < 4; t++) O[i][t] = 0.f;
    float mrun0 = -1e30f, mrun1 = -1e30f, lrun0 = 0.f, lrun1 = 0.f;

    const int b_sel = lane >> 3;
    const int b_rin = (b_sel >> 1)*8 + (lane & 7);
    const int b_cB  = (b_sel & 1)*16;
    const int g = lane >> 2, tig = lane & 3;

    for (int kb = 0; kb < nkb; kb++) {
        if (kb + 1 < nkb) { load_stage(kb + 1, (kb + 1) & 1); CP_COMMIT(); CP_WAIT_1(); }
        else CP_WAIT_0();
        __syncthreads();
        const unsigned st = sStage + (unsigned)(kb & 1) * FA_STAGE;

        float S[16][4];
        #pragma unroll
        for (int j = 0; j < 16; j++)
            #pragma unroll
            for (int t = 0; t < 4; t++) S[j][t] = 0.f;

        #pragma unroll
        for (int ks = 0; ks < 4; ks++) {
            #pragma unroll
            for (int jp = 0; jp < 8; jp++) {
                unsigned o = swz(jp*16 + b_rin, ks*32 + b_cB);
                unsigned rh[4], rl[4];
                ldmx4(rh, st + o);
                ldmx4(rl, st + 16384 + o);
                unsigned bh0[2] = {rh[0], rh[1]}, bh1[2] = {rh[2], rh[3]};
                unsigned bl0[2] = {rl[0], rl[1]}, bl1[2] = {rl[2], rl[3]};
                mma16816(S[2*jp],   qfh[ks], bh0);
                mma16816(S[2*jp],   qfl[ks], bh0);
                mma16816(S[2*jp],   qfh[ks], bl0);
                mma16816(S[2*jp+1], qfh[ks], bh1);
                mma16816(S[2*jp+1], qfl[ks], bh1);
                mma16816(S[2*jp+1], qfh[ks], bl1);
            }
        }
        #pragma unroll
        for (int j = 0; j < 16; j++)
            #pragma unroll
            for (int t = 0; t < 4; t++) S[j][t] *= 0.125f;

        if (kb == nkb - 1) {
            int row0 = m0 + wid*16 + g;
            int row1 = row0 + 8;
            #pragma unroll
            for (int j = 0; j < 16; j++) {
                int col = kb*128 + j*8 + tig*2;
                if (col     > row0) S[j][0] = -1e30f;
                if (col + 1 > row0) S[j][1] = -1e30f;
                if (col     > row1) S[j][2] = -1e30f;
                if (col + 1 > row1) S[j][3] = -1e30f;
            }
        }

        float mx0 = -1e30f, mx1 = -1e30f;
        #pragma unroll
        for (int j = 0; j < 16; j++) {
            mx0 = fmaxf(mx0, fmaxf(S[j][0], S[j][1]));
            mx1 = fmaxf(mx1, fmaxf(S[j][2], S[j][3]));
        }
        mx0 = fmaxf(mx0, __shfl_xor_sync(0xffffffffu, mx0, 1));
        mx0 = fmaxf(mx0, __shfl_xor_sync(0xffffffffu, mx0, 2));
        mx1 = fmaxf(mx1, __shfl_xor_sync(0xffffffffu, mx1, 1));
        mx1 = fmaxf(mx1, __shfl_xor_sync(0xffffffffu, mx1, 2));
        float nm0 = fmaxf(mrun0, mx0), nm1 = fmaxf(mrun1, mx1);
        float f0 = expf(mrun0 - nm0), f1 = expf(mrun1 - nm1);
        mrun0 = nm0; mrun1 = nm1;
        float rs0 = 0.f, rs1 = 0.f;
        #pragma unroll
        for (int j = 0; j < 16; j++) {
            S[j][0] = expf(S[j][0] - nm0);
            S[j][1] = expf(S[j][1] - nm0);
            S[j][2] = expf(S[j][2] - nm1);
            S[j][3] = expf(S[j][3] - nm1);
            rs0 += S[j][0] + S[j][1];
            rs1 += S[j][2] + S[j][3];
        }
        rs0 += __shfl_xor_sync(0xffffffffu, rs0, 1);
        rs0 += __shfl_xor_sync(0xffffffffu, rs0, 2);
        rs1 += __shfl_xor_sync(0xffffffffu, rs1, 1);
        rs1 += __shfl_xor_sync(0xffffffffu, rs1, 2);
        lrun0 = lrun0 * f0 + rs0;
        lrun1 = lrun1 * f1 + rs1;
        #pragma unroll
        for (int i = 0; i < 8; i++) {
            O[i][0] *= f0; O[i][1] *= f0;
            O[i][2] *= f1; O[i][3] *= f1;
        }

        #pragma unroll
        for (int c2 = 0; c2 < 2; c2++) {
            const unsigned vst = st + 32768 + (unsigned)c2 * 8192;
            #pragma unroll
            for (int ks = 0; ks < 4; ks++) {
                const int sI = c2*4 + ks;
                const float* e0 = S[2*sI];
                const float* e1 = S[2*sI + 1];
                unsigned ah[4], al[4];
                ah[0] = packbf(e0[0], e0[1]);
                ah[1] = packbf(e0[2], e0[3]);
                ah[2] = packbf(e1[0], e1[1]);
                ah[3] = packbf(e1[2], e1[3]);
                al[0] = packbf(e0[0] - __bfloat162float(__float2bfloat16(e0[0])),
                               e0[1] - __bfloat162float(__float2bfloat16(e0[1])));
                al[1] = packbf(e0[2] - __bfloat162float(__float2bfloat16(e0[2])),
                               e0[3] - __bfloat162float(__float2bfloat16(e0[3])));
                al[2] = packbf(e1[0] - __bfloat162float(__float2bfloat16(e1[0])),
                               e1[1] - __bfloat162float(__float2bfloat16(e1[1])));
                al[3] = packbf(e1[2] - __bfloat162float(__float2bfloat16(e1[2])),
                               e1[3] - __bfloat162float(__float2bfloat16(e1[3])));
                #pragma unroll
                for (int jp = 0; jp < 4; jp++) {
                    unsigned o = swz(jp*16 + b_rin, ks*32 + b_cB);
                    unsigned rh[4], rl[4];
                    ldmx4(rh, vst + o);
                    ldmx4(rl, vst + 16384 + o);
                    unsigned bh0[2] = {rh[0], rh[1]}, bh1[2] = {rh[2], rh[3]};
                    unsigned bl0[2] = {rl[0], rl[1]}, bl1[2] = {rl[2], rl[3]};
                    mma16816(O[2*jp],   ah, bh0);
                    mma16816(O[2*jp],   al, bh0);
                    mma16816(O[2*jp],   ah, bl0);
                    mma16816(O[2*jp+1], ah, bh1);
                    mma16816(O[2*jp+1], al, bh1);
                    mma16816(O[2*jp+1], ah, bl1);
                }
            }
        }
        __syncthreads();
    }

    float inv0 = 1.f / lrun0, inv1 = 1.f / lrun1;
    float* y0 = YH + ((size_t)bh * TLEN + m0 + wid*16 + g) * HD;
    float* y1 = y0 + 8 * HD;
    #pragma unroll
    for (int i = 0; i < 8; i++) {
        int d = i*8 + tig*2;
        y0[d]     = O[i][0] * inv0;
        y0[d + 1] = O[i][1] * inv0;
        y1[d]     = O[i][2] * inv1;
        y1[d + 1] = O[i][3] * inv1;
    }
}

// ======================== small kernels ======================================
__global__ void detect_idx_kernel(const unsigned int* w) {
    __shared__ unsigned int s;
    if (threadIdx.x == 0) s = 0u;
    __syncthreads();
    unsigned int v = 0u;
    for (int i = threadIdx.x; i < 1024; i += blockDim.x) v |= w[2*i + 1];
    atomicOr(&s, v);
    __syncthreads();
    if (threadIdx.x == 0) g_idx32 = (s != 0u) ? 1 : 0;
}

__global__ void embed_kernel(const void* idx, const float* __restrict__ wte,
                             const float* __restrict__ wpe, float* __restrict__ x) {
    int i = blockIdx.x * blockDim.x + threadIdx.x;
    if (i >= MTOK*CDIM) return;
    int c  = i % CDIM;
    int bt = i / CDIM;
    int t  = bt % TLEN;
    long long tok;
    if (g_idx32) tok = (long long)((const int*)idx)[bt];
    else         tok = ((const long long*)idx)[bt];
    x[i] = wte[tok*CDIM + c] + wpe[(long long)t*CDIM + c];
}

__global__ void ln_lora_kernel(const float* __restrict__ x, const float* __restrict__ g,
                               const float* __restrict__ b,
                               const float* __restrict__ lA,
                               __nv_bfloat16* __restrict__ oh, __nv_bfloat16* __restrict__ ol,
                               float* __restrict__ tmp) {
    const int row = blockIdx.x;
    const float* xr = x + (long long)row * CDIM;
    __shared__ float sx[CDIM];
    __shared__ float red[128];
    __shared__ float s_mean, s_rstd;
    int tid = threadIdx.x;
    float s = 0.f;
    for (int c = tid; c < CDIM; c += 128) { float v = xr[c]; sx[c] = v; s += v; }
    red[tid] = s; __syncthreads();
    for (int st = 64; st > 0; st >>= 1) { if (tid < st) red[tid] += red[tid+st]; __syncthreads(); }
    if (tid == 0) s_mean = red[0] / (float)CDIM;
    __syncthreads();
    float mean = s_mean;
    float sq = 0.f;
    for (int c = tid; c < CDIM; c += 128) { float d = sx[c] - mean; sq += d*d; }
    red[tid] = sq; __syncthreads();
    for (int st = 64; st > 0; st >>= 1) { if (tid < st) red[tid] += red[tid+st]; __syncthreads(); }
    if (tid == 0) s_rstd = rsqrtf(red[0] / (float)CDIM + 1e-5f);
    __syncthreads();
    float mean2 = s_mean, rstd = s_rstd;
    for (int c = tid; c < CDIM; c += 128) {
        float v = (sx[c] - mean2) * rstd * g[c] + b[c];
        long long o = (long long)row*CDIM + c;
        __nv_bfloat16 hi, lo; bsplit(v, hi, lo);
        oh[o] = hi; ol[o] = lo;
        sx[c] = v;
    }
    __syncthreads();
    if (lA) {
        int w = tid >> 5, lane = tid & 31;
        #pragma unroll
        for (int rr = 0; rr < 2; ++rr) {
            int r = w*2 + rr;
            const float* Ar = lA + (long long)r * CDIM;
            float acc = 0.f;
            for (int c = lane; c < CDIM; c += 32) acc += sx[c] * Ar[c];
            #pragma unroll
            for (int off = 16; off > 0; off >>= 1) acc += __shfl_down_sync(0xffffffffu, acc, off);
            if (lane == 0) tmp[row*RANK + r] = acc;
        }
    }
}

__global__ void ln_f16_kernel(const float* __restrict__ x, const float* __restrict__ g,
                              const float* __restrict__ b, __half* __restrict__ oh) {
    const int row = blockIdx.x;
    const float* xr = x + (long long)row * CDIM;
    __shared__ float sx[CDIM];
    __shared__ float red[128];
    __shared__ float s_mean, s_rstd;
    int tid = threadIdx.x;
    float s = 0.f;
    for (int c = tid; c < CDIM; c += 128) { float v = xr[c]; sx[c] = v; s += v; }
    red[tid] = s; __syncthreads();
    for (int st = 64; st > 0; st >>= 1) { if (tid < st) red[tid] += red[tid+st]; __syncthreads(); }
    if (tid == 0) s_mean = red[0] / (float)CDIM;
    __syncthreads();
    float mean = s_mean;
    float sq = 0.f;
    for (int c = tid; c < CDIM; c += 128) { float d = sx[c] - mean; sq += d*d; }
    red[tid] = sq; __syncthreads();
    for (int st = 64; st > 0; st >>= 1) { if (tid < st) red[tid] += red[tid+st]; __syncthreads(); }
    if (tid == 0) s_rstd = rsqrtf(red[0] / (float)CDIM + 1e-5f);
    __syncthreads();
    float mean2 = s_mean, rstd = s_rstd;
    for (int c = tid; c < CDIM; c += 128) {
        float v = (sx[c] - mean2) * rstd * g[c] + b[c];
        oh[(long long)row*CDIM + c] = __float2half(v);
    }
}

__global__ void wsplitA_kernel(const float* __restrict__ wq, const float* __restrict__ wp,
                               const float* __restrict__ wf, const float* __restrict__ wm,
                               __nv_bfloat16* __restrict__ qh, __nv_bfloat16* __restrict__ ql,
                               __nv_bfloat16* __restrict__ ph, __nv_bfloat16* __restrict__ pl,
                               __nv_bfloat16* __restrict__ fh, __nv_bfloat16* __restrict__ fl,
                               __nv_bfloat16* __restrict__ mh, __nv_bfloat16* __restrict__ ml) {
    const int NQ = NLAYER*3*CDIM*CDIM, NP = NLAYER*CDIM*CDIM,
              NF = NLAYER*4*CDIM*CDIM, NM = NLAYER*CDIM*4*CDIM;
    int i4 = (blockIdx.x * 256 + threadIdx.x) * 4;
    const float* src; __nv_bfloat16 *dh, *dl; int k;
    if (i4 < NQ)                { src = wq; dh = qh; dl = ql; k = i4; }
    else if (i4 < NQ+NP)        { src = wp; dh = ph; dl = pl; k = i4 - NQ; }
    else if (i4 < NQ+NP+NF)     { src = wf; dh = fh; dl = fl; k = i4 - NQ - NP; }
    else if (i4 < NQ+NP+NF+NM)  { src = wm; dh = mh; dl = ml; k = i4 - NQ - NP - NF; }
    else return;
    float4 v = *reinterpret_cast<const float4*>(src + k);
    __nv_bfloat16 h0, l0, h1, l1, h2, l2, h3, l3;
    bsplit(v.x, h0, l0); bsplit(v.y, h1, l1);
    bsplit(v.z, h2, l2); bsplit(v.w, h3, l3);
    uint2 hv, lv;
    hv.x = ((unsigned)__bfloat16_as_ushort(h1) << 16) | __bfloat16_as_ushort(h0);
    hv.y = ((unsigned)__bfloat16_as_ushort(h3) << 16) | __bfloat16_as_ushort(h2);
    lv.x = ((unsigned)__bfloat16_as_ushort(l1) << 16) | __bfloat16_as_ushort(l0);
    lv.y = ((unsigned)__bfloat16_as_ushort(l3) << 16) | __bfloat16_as_ushort(l2);
    *reinterpret_cast<uint2*>(dh + k) = hv;
    *reinterpret_cast<uint2*>(dl + k) = lv;
}

__global__ void wsplit_f16_kernel(const float* __restrict__ w, __half* __restrict__ h, int n) {
    int i4 = (blockIdx.x * 256 + threadIdx.x) * 4;
    if (i4 >= n) return;
    float4 v = *reinterpret_cast<const float4*>(w + i4);
    __half2 a = __floats2half2_rn(v.x, v.y);
    __half2 b = __floats2half2_rn(v.z, v.w);
    uint2 o;
    o.x = reinterpret_cast<unsigned&>(a);
    o.y = reinterpret_cast<unsigned&>(b);
    *reinterpret_cast<uint2*>(h + i4) = o;
}

__global__ void merge_lora_kernel(const float* __restrict__ yh,
                                  const float* __restrict__ lA,
                                  __nv_bfloat16* __restrict__ oh, __nv_bfloat16* __restrict__ ol,
                                  float* __restrict__ tmp) {
    const int row = blockIdx.x;
    const int t = row & (TLEN - 1);
    const int b = row >> 10;
    __shared__ float sy[CDIM];
    int tid = threadIdx.x;
    for (int c = tid; c < CDIM; c += 128) {
        int h = c >> 6, d = c & 63;
        sy[c] = yh[(((long long)(b*NHEAD + h) * TLEN) + t) * HD + d];
    }
    __syncthreads();
    for (int c = tid; c < CDIM; c += 128) {
        long long o = (long long)row*CDIM + c;
        __nv_bfloat16 hi, lo; bsplit(sy[c], hi, lo);
        oh[o] = hi; ol[o] = lo;
    }
    int w = tid >> 5, lane = tid & 31;
    #pragma unroll
    for (int rr = 0; rr < 2; ++rr) {
        int r = w*2 + rr;
        const float* Ar = lA + (long long)r * CDIM;
        float acc = 0.f;
        for (int c = lane; c < CDIM; c += 32) acc += sy[c] * Ar[c];
        #pragma unroll
        for (int off = 16; off > 0; off >>= 1) acc += __shfl_down_sync(0xffffffffu, acc, off);
        if (lane == 0) tmp[row*RANK + r] = acc;
    }
}

// ======================== host driver ========================================
template<int MODE, int SPLITK>
static void launch_gemm(dim3 grid,
                        const __nv_bfloat16* Ah, const __nv_bfloat16* Al,
                        const __nv_bfloat16* Bh, const __nv_bfloat16* Bl,
                        const float* bias, const float* loraT, const float* loraB,
                        float* Cm, int M, int N, int K) {
    cudaFuncSetAttribute(mma_gemm<MODE, SPLITK>,
                         cudaFuncAttributeMaxDynamicSharedMemorySize, GEMM_SMEM);
    mma_gemm<MODE, SPLITK><<<grid, 256, GEMM_SMEM>>>(
        Ah, Al, Bh, Bl, bias, loraT, loraB, Cm, M, N, K);
}

extern "C" void kernel_launch(void* const* d_in, const int* in_sizes, int n_in,
                              void* d_out, int out_size) {
    (void)in_sizes; (void)n_in; (void)out_size;
    const void*  idx     = d_in[0];
    const float* wte     = (const float*)d_in[1];
    const float* wpe     = (const float*)d_in[2];
    const float* ln1_g   = (const float*)d_in[3];
    const float* ln1_b   = (const float*)d_in[4];
    const float* attn_w  = (const float*)d_in[5];
    const float* attn_lA = (const float*)d_in[6];
    const float* attn_lB = (const float*)d_in[7];
    const float* proj_w  = (const float*)d_in[8];
    const float* proj_lA = (const float*)d_in[9];
    const float* proj_lB = (const float*)d_in[10];
    const float* ln2_g   = (const float*)d_in[11];
    const float* ln2_b   = (const float*)d_in[12];
    const float* fc_w    = (const float*)d_in[13];
    const float* fc_b    = (const float*)d_in[14];
    const float* mproj_w = (const float*)d_in[15];
    const float* mproj_b = (const float*)d_in[16];
    const float* lnf_g   = (const float*)d_in[17];
    const float* lnf_b   = (const float*)d_in[18];
    const float* head_w  = (const float*)d_in[19];
    float* out = (float*)d_out;

    float *X, *YH, *TMP, *QKVp;
    cudaGetSymbolAddress((void**)&X,    g_X);
    cudaGetSymbolAddress((void**)&YH,   g_YH);
    cudaGetSymbolAddress((void**)&TMP,  g_TMP);
    cudaGetSymbolAddress((void**)&QKVp, g_QKVp);

    __nv_bfloat16 *wqkv_h, *wqkv_l, *wproj_h, *wproj_l, *wfc_h, *wfc_l, *wmp_h, *wmp_l,
                  *Hh, *Hl, *Yh, *Yl, *FCGh, *FCGl,
                  *Qh, *Ql, *Kh, *Kl, *Vth, *Vtl;
    __half *whead16, *H16;
    cudaGetSymbolAddress((void**)&wqkv_h,  g_wqkv_h);  cudaGetSymbolAddress((void**)&wqkv_l,  g_wqkv_l);
    cudaGetSymbolAddress((void**)&wproj_h, g_wproj_h); cudaGetSymbolAddress((void**)&wproj_l, g_wproj_l);
    cudaGetSymbolAddress((void**)&wfc_h,   g_wfc_h);   cudaGetSymbolAddress((void**)&wfc_l,   g_wfc_l);
    cudaGetSymbolAddress((void**)&wmp_h,   g_wmp_h);   cudaGetSymbolAddress((void**)&wmp_l,   g_wmp_l);
    cudaGetSymbolAddress((void**)&whead16, g_whead16);
    cudaGetSymbolAddress((void**)&H16,  g_H16);
    cudaGetSymbolAddress((void**)&Hh,   g_Hh);   cudaGetSymbolAddress((void**)&Hl,   g_Hl);
    cudaGetSymbolAddress((void**)&Yh,   g_Yhb);  cudaGetSymbolAddress((void**)&Yl,   g_Ylb);
    cudaGetSymbolAddress((void**)&FCGh, g_FCGh); cudaGetSymbolAddress((void**)&FCGl, g_FCGl);
    cudaGetSymbolAddress((void**)&Qh,   g_Qh);   cudaGetSymbolAddress((void**)&Ql,   g_Ql);
    cudaGetSymbolAddress((void**)&Kh,   g_Kh);   cudaGetSymbolAddress((void**)&Kl,   g_Kl);
    cudaGetSymbolAddress((void**)&Vth,  g_Vth);  cudaGetSymbolAddress((void**)&Vtl,  g_Vtl);

    cudaFuncSetAttribute(flash_attn, cudaFuncAttributeMaxDynamicSharedMemorySize, FA_SMEM);

    detect_idx_kernel<<<1, 256>>>((const unsigned int*)idx);
    embed_kernel<<<(MTOK*CDIM + 255)/256, 256>>>(idx, wte, wpe, X);
    {
        int nA = NLAYER*(3*CDIM*CDIM + CDIM*CDIM + 4*CDIM*CDIM + 4*CDIM*CDIM);
        wsplitA_kernel<<<(nA/4 + 255)/256, 256>>>(attn_w, proj_w, fc_w, mproj_w,
            wqkv_h, wqkv_l, wproj_h, wproj_l, wfc_h, wfc_l, wmp_h, wmp_l);
        int nB = VOCAB*CDIM;
        wsplit_f16_kernel<<<(nB/4 + 255)/256, 256>>>(head_w, whead16, nB);
    }

    for (int l = 0; l < NLAYER; l++) {
        long long oq = (long long)l * 3*CDIM*CDIM;
        long long op = (long long)l * CDIM*CDIM;
        long long of = (long long)l * 4*CDIM*CDIM;
        long long om = (long long)l * CDIM*4*CDIM;
        const float* lA_q = attn_lA + (long long)l * RANK*CDIM;
        const float* lB_q = attn_lB + (long long)l * 3*CDIM*RANK;
        const float* lA_p = proj_lA + (long long)l * RANK*CDIM;
        const float* lB_p = proj_lB + (long long)l * CDIM*RANK;

        // ---- attention ----
        ln_lora_kernel<<<MTOK, 128>>>(X, ln1_g + l*CDIM, ln1_b + l*CDIM, lA_q, Hh, Hl, TMP);
        // qkv: split-K=2 into dual fp32 partial buffers (384 CTAs)
        launch_gemm<0, 1>(dim3(MTOK/128, 3*CDIM/128, 2),
            Hh, Hl, wqkv_h + oq, wqkv_l + oq, nullptr, TMP, lB_q, QKVp,
            MTOK, 3*CDIM, CDIM);
        split_qkv2_kernel<<<(NBATCH*TLEN*HD + 255)/256, 256>>>(QKVp);

        flash_attn<<<dim3(TLEN/128, NBATCH), 256, FA_SMEM>>>(Qh, Ql, Kh, Kl, Vth, Vtl, YH);
        merge_lora_kernel<<<MTOK, 128>>>(YH, lA_p, Yh, Yl, TMP);

        // proj: split-K=2 atomic residual into X
        launch_gemm<2, 1>(dim3(MTOK/128, CDIM/128, 2),
            Yh, Yl, wproj_h + op, wproj_l + op, nullptr, TMP, lB_p, X,
            MTOK, CDIM, CDIM);

        // ---- MLP ----
        ln_lora_kernel<<<MTOK, 128>>>(X, ln2_g + l*CDIM, ln2_b + l*CDIM, nullptr, Hh, Hl, TMP);
        launch_gemm<1, 0>(dim3(MTOK/128, 4*CDIM/128, 1),
            Hh, Hl, wfc_h + of, wfc_l + of, fc_b + (long long)l*4*CDIM, nullptr, nullptr, nullptr,
            MTOK, 4*CDIM, CDIM);
        // mproj: split-K=2 atomic residual into X
        launch_gemm<2, 1>(dim3(MTOK/128, CDIM/128, 2),
            FCGh, FCGl, wmp_h + om, wmp_l + om, mproj_b + (long long)l*CDIM, nullptr, nullptr, X,
            MTOK, CDIM, 4*CDIM);
    }

    // ---- final layernorm + fp16 1-MMA vocab head (128x128, occ=2) ----
    ln_f16_kernel<<<MTOK, 128>>>(X, lnf_g, lnf_b, H16);
    cudaFuncSetAttribute(mma_gemm_f16, cudaFuncAttributeMaxDynamicSharedMemorySize, GEMM_SMEM_F16);
    mma_gemm_f16<<<dim3(MTOK/128, (VOCAB + 127)/128), 256, GEMM_SMEM_F16>>>(
        H16, whead16, out, MTOK, VOCAB, CDIM);
}

// round 14
// speedup vs baseline: 1.4881x; 1.1465x over previous
#include <cuda_runtime.h>
#include <cuda_bf16.h>
#include <cuda_fp16.h>
#include <math.h>

// ---------------------------------------------------------------------------
// GPT_3959959847300 round 14: fp16 2-term layer GEMMs (A hi/lo fp16, W fp16;
// 2 MMAs + 3 smem tiles/stage). Attention bf16 3-term and fp16 head unchanged.
// ---------------------------------------------------------------------------

#define BSZ    2
#define TLEN   1024
#define CDIM   512
#define NHEAD  8
#define HD     64
#define NLAYER 4
#define VOCAB  50257
#define RANK   8
#define LSCALE 4.0f
#define MTOK   (BSZ*TLEN)
#define NBATCH (BSZ*NHEAD)

// ======================== PTX helpers ========================================
__device__ __forceinline__ unsigned smem_u32(const void* p) {
    unsigned a;
    asm("{ .reg .u64 t; cvta.to.shared.u64 t, %1; cvt.u32.u64 %0, t; }" : "=r"(a) : "l"(p));
    return a;
}
__device__ __forceinline__ void ldmx4(unsigned* r, unsigned addr) {
    asm volatile("ldmatrix.sync.aligned.m8n8.x4.shared.b16 {%0,%1,%2,%3}, [%4];"
                 : "=r"(r[0]), "=r"(r[1]), "=r"(r[2]), "=r"(r[3]) : "r"(addr));
}
__device__ __forceinline__ void mma16816(float* d, const unsigned* a, const unsigned* b) {
    asm volatile(
        "mma.sync.aligned.m16n8k16.row.col.f32.bf16.bf16.f32 "
        "{%0,%1,%2,%3},{%4,%5,%6,%7},{%8,%9},{%0,%1,%2,%3};"
        : "+f"(d[0]), "+f"(d[1]), "+f"(d[2]), "+f"(d[3])
        : "r"(a[0]), "r"(a[1]), "r"(a[2]), "r"(a[3]), "r"(b[0]), "r"(b[1]));
}
__device__ __forceinline__ void mma16816h(float* d, const unsigned* a, const unsigned* b) {
    asm volatile(
        "mma.sync.aligned.m16n8k16.row.col.f32.f16.f16.f32 "
        "{%0,%1,%2,%3},{%4,%5,%6,%7},{%8,%9},{%0,%1,%2,%3};"
        : "+f"(d[0]), "+f"(d[1]), "+f"(d[2]), "+f"(d[3])
        : "r"(a[0]), "r"(a[1]), "r"(a[2]), "r"(a[3]), "r"(b[0]), "r"(b[1]));
}
__device__ __forceinline__ void cp16(unsigned dst, const void* src, bool pred) {
    int sz = pred ? 16 : 0;
    asm volatile("cp.async.cg.shared.global [%0], [%1], 16, %2;"
                 :: "r"(dst), "l"(src), "r"(sz) : "memory");
}
#define CP_COMMIT()  asm volatile("cp.async.commit_group;" ::: "memory")
#define CP_WAIT_1()  asm volatile("cp.async.wait_group 1;" ::: "memory")
#define CP_WAIT_0()  asm volatile("cp.async.wait_group 0;" ::: "memory")

__device__ __forceinline__ void bsplit(float x, __nv_bfloat16& hi, __nv_bfloat16& lo) {
    hi = __float2bfloat16(x);
    lo = __float2bfloat16(x - __bfloat162float(hi));
}
__device__ __forceinline__ void hsplit(float x, __half& hi, __half& lo) {
    hi = __float2half(x);
    lo = __float2half(x - __half2float(hi));
}
__device__ __forceinline__ unsigned packbf(float a, float b) {
    __nv_bfloat162 t = __floats2bfloat162_rn(a, b);
    return reinterpret_cast<unsigned&>(t);
}

// ======================== scratch ============================================
__device__ float g_X  [MTOK*CDIM];
__device__ float g_YH [NBATCH*TLEN*HD];
__device__ float g_TMP[MTOK*RANK];
__device__ float g_QKVp[2ll*MTOK*3*CDIM];
__device__ int   g_idx32;

__device__ __half g_wqkv16[NLAYER*3*CDIM*CDIM];
__device__ __half g_wproj16[NLAYER*CDIM*CDIM];
__device__ __half g_wfc16 [NLAYER*4*CDIM*CDIM];
__device__ __half g_wmp16 [NLAYER*CDIM*4*CDIM];
__device__ __half g_whead16[VOCAB*CDIM];
__device__ __half g_H16h[MTOK*CDIM],  g_H16l[MTOK*CDIM];
__device__ __half g_Y16h[MTOK*CDIM],  g_Y16l[MTOK*CDIM];
__device__ __half g_FCG16h[MTOK*4*CDIM], g_FCG16l[MTOK*4*CDIM];
__device__ __nv_bfloat16 g_Qh[NBATCH*TLEN*HD], g_Ql[NBATCH*TLEN*HD];
__device__ __nv_bfloat16 g_Kh[NBATCH*TLEN*HD], g_Kl[NBATCH*TLEN*HD];
__device__ __nv_bfloat16 g_Vth[NBATCH*HD*TLEN], g_Vtl[NBATCH*HD*TLEN];

// ======================== common tile helpers ================================
#define TILE_B    16384                 // 128x64 16-bit tile (128B rows, swizzled)
#define LSTAGE_B  (3*TILE_B)            // layer GEMM: Ah, Al, B
#define LGEMM_SMEM (2*LSTAGE_B)         // 98304
#define STAGE2_B  (2*TILE_B)            // fp16 head: A, B
#define GEMM_SMEM_F16 (2*STAGE2_B)      // 65536

__device__ __forceinline__ unsigned swz(int row, int colB) {
    unsigned o = (unsigned)(row * 128 + colB);
    return o ^ ((unsigned)(row & 7) << 4);
}

// ======================== fp16 2-term layer GEMM =============================
// MODE: 0 fp32 partial store (per-z buffers, +bias/lora on z==0)
//       1 gelu->fp16 hi/lo split; 2 residual += (atomicAdd if SPLITK)
// SPLITK: 0 normal; 1 K halved across blockIdx.z
template<int MODE, int SPLITK>
__global__ __launch_bounds__(256, 1)
void mma_gemm_h(const __half* __restrict__ Ah, const __half* __restrict__ Al,
                const __half* __restrict__ Bm,
                const float* __restrict__ bias,
                const float* __restrict__ loraT, const float* __restrict__ loraB,
                float* __restrict__ Cm,
                int M, int N, int K)
{
    extern __shared__ char smem_raw[];
    const int m0 = blockIdx.x * 128;
    const int n0 = blockIdx.y * 128;
    const int kz = SPLITK ? (int)blockIdx.z : 0;
    const int kslice = SPLITK ? (K >> 1) : K;
    const int koff = kz * kslice;

    const unsigned sbase = smem_u32(smem_raw);
    const int tid  = threadIdx.x;
    const int lane = tid & 31;
    const int wid  = tid >> 5;
    const int wm   = wid & 1;
    const int wn   = wid >> 1;
    const int lr   = tid >> 1;
    const int lcB  = (tid & 1) << 6;

    float acc[4][4][4];
    #pragma unroll
    for (int i = 0; i < 4; i++)
        #pragma unroll
        for (int j = 0; j < 4; j++)
            #pragma unroll
            for (int t = 0; t < 4; t++) acc[i][j][t] = 0.f;

    const int nc = kslice >> 6;

    auto stage3 = [&](unsigned sb, int k0) {
        {
            const char* pa = (const char*)(Ah + (size_t)(m0 + lr) * K + k0) + lcB;
            const char* pl = (const char*)(Al + (size_t)(m0 + lr) * K + k0) + lcB;
            #pragma unroll
            for (int j = 0; j < 4; j++) {
                unsigned o = swz(lr, lcB + 16*j);
                cp16(sb + o,          pa + 16*j, true);
                cp16(sb + TILE_B + o, pl + 16*j, true);
            }
        }
        {
            const char* pb = (const char*)(Bm + (size_t)(n0 + lr) * K + k0) + lcB;
            #pragma unroll
            for (int j = 0; j < 4; j++) {
                unsigned o = swz(lr, lcB + 16*j);
                cp16(sb + 2*TILE_B + o, pb + 16*j, true);
            }
        }
    };

    stage3(sbase, koff);
    CP_COMMIT();

    const int a_rin  = lane & 15;
    const int a_cB   = (lane >> 4) * 16;
    const int b_sel  = lane >> 3;
    const int b_rin  = (b_sel >> 1) * 8 + (lane & 7);
    const int b_cB   = (b_sel & 1) * 16;

    for (int cI = 0; cI < nc; ++cI) {
        const int s = cI & 1;
        if (cI + 1 < nc) {
            stage3(sbase + (unsigned)(1 - s) * LSTAGE_B, koff + ((cI + 1) << 6));
            CP_COMMIT();
            CP_WAIT_1();
        } else {
            CP_WAIT_0();
        }
        __syncthreads();

        const unsigned st = sbase + (unsigned)s * LSTAGE_B;
        #pragma unroll
        for (int ks = 0; ks < 4; ++ks) {
            unsigned ra_h[4][4], ra_l[4][4], rb[4][2];
            #pragma unroll
            for (int i = 0; i < 4; ++i) {
                int row = wm*64 + i*16 + a_rin;
                unsigned o = swz(row, ks*32 + a_cB);
                ldmx4(ra_h[i], st + o);
                ldmx4(ra_l[i], st + TILE_B + o);
            }
            #pragma unroll
            for (int jp = 0; jp < 2; ++jp) {
                int row = wn*32 + jp*16 + b_rin;
                unsigned o = swz(row, ks*32 + b_cB);
                unsigned r[4];
                ldmx4(r, st + 2*TILE_B + o);
                rb[2*jp][0] = r[0]; rb[2*jp][1] = r[1];
                rb[2*jp+1][0] = r[2]; rb[2*jp+1][1] = r[3];
            }
            #pragma unroll
            for (int i = 0; i < 4; ++i)
                #pragma unroll
                for (int j = 0; j < 4; ++j) {
                    mma16816h(acc[i][j], ra_h[i], rb[j]);
                    mma16816h(acc[i][j], ra_l[i], rb[j]);
                }
        }
        __syncthreads();
    }

    const int group = lane >> 2, tig = lane & 3;
    float* cbuf = (MODE == 0) ? (Cm + (size_t)kz * M * N) : Cm;
    #pragma unroll
    for (int i = 0; i < 4; ++i) {
        int m_lo = m0 + wm*64 + i*16 + group;
        #pragma unroll
        for (int j = 0; j < 4; ++j) {
            int nA = n0 + wn*32 + j*8 + tig*2;
            #pragma unroll
            for (int h = 0; h < 2; ++h) {
                int m = m_lo + h*8;
                #pragma unroll
                for (int e = 0; e < 2; ++e) {
                    int n = nA + e;
                    float v = acc[i][j][h*2 + e];
                    if (bias && kz == 0)  v += bias[n];
                    if (loraT && kz == 0) {
                        const float* t  = loraT + (size_t)m * RANK;
                        const float* bb = loraB + (size_t)n * RANK;
                        float s = 0.f;
                        #pragma unroll
                        for (int r = 0; r < RANK; r++) s += t[r] * bb[r];
                        v += LSCALE * s;
                    }
                    if (MODE == 0) {
                        cbuf[(long long)m * N + n] = v;
                    } else if (MODE == 2) {
                        if (SPLITK) atomicAdd(&Cm[(long long)m * N + n], v);
                        else        Cm[(long long)m * N + n] += v;
                    } else { // MODE 1: gelu -> fp16 hi/lo
                        float gv = 0.5f * v * (1.f + tanhf(0.7978845608028654f * (v + 0.044715f * v*v*v)));
                        __half hi, lo; hsplit(gv, hi, lo);
                        g_FCG16h[(long long)m * N + n] = hi;
                        g_FCG16l[(long long)m * N + n] = lo;
                    }
                }
            }
        }
    }
}

// combine qkv split-K partials -> Q/K (bhtd) and V^T (bhdt) bf16 hi/lo
__global__ void split_qkv2_kernel(const float* __restrict__ qkvp) {
    int i = blockIdx.x * 256 + threadIdx.x;
    if (i >= NBATCH*TLEN*HD) return;
    int d = i % HD;
    int t = (i / HD) % TLEN;
    int h = (i / (HD*TLEN)) % NHEAD;
    int b = i / (HD*TLEN*NHEAD);
    long long src = (long long)(b*TLEN + t) * (3*CDIM) + h*HD + d;
    const long long off = (long long)MTOK * 3*CDIM;
    __nv_bfloat16 hi, lo;
    float q = qkvp[src] + qkvp[src + off];
    float k = qkvp[src + CDIM] + qkvp[src + CDIM + off];
    float v = qkvp[src + 2*CDIM] + qkvp[src + 2*CDIM + off];
    bsplit(q, hi, lo); g_Qh[i] = hi; g_Ql[i] = lo;
    bsplit(k, hi, lo); g_Kh[i] = hi; g_Kl[i] = lo;
    long long vi = ((long long)(b*NHEAD + h) * HD + d) * TLEN + t;
    bsplit(v, hi, lo); g_Vth[vi] = hi; g_Vtl[vi] = lo;
}

// ======================== fp16 1-MMA head GEMM (128x128, occ=2) ==============
__global__ __launch_bounds__(256, 2)
void mma_gemm_f16(const __half* __restrict__ Am, const __half* __restrict__ Bm,
                  float* __restrict__ Cm, int M, int N, int K)
{
    extern __shared__ char smem_raw[];
    const int m0 = blockIdx.x * 128;
    const int n0 = blockIdx.y * 128;

    const unsigned sbase = smem_u32(smem_raw);
    const int tid  = threadIdx.x;
    const int lane = tid & 31;
    const int wid  = tid >> 5;
    const int wm   = wid & 1;
    const int wn   = wid >> 1;
    const int lr   = tid >> 1;
    const int lcB  = (tid & 1) << 6;

    float acc[4][4][4];
    #pragma unroll
    for (int i = 0; i < 4; i++)
        #pragma unroll
        for (int j = 0; j < 4; j++)
            #pragma unroll
            for (int t = 0; t < 4; t++) acc[i][j][t] = 0.f;

    const int nc = K >> 6;

    auto stage2 = [&](unsigned sb, int k0) {
        {
            int gr = m0 + lr; bool ok = (gr < M); int r = ok ? gr : 0;
            const char* pa = (const char*)(Am + (size_t)r * K + k0) + lcB;
            #pragma unroll
            for (int j = 0; j < 4; j++) {
                unsigned o = swz(lr, lcB + 16*j);
                cp16(sb + o, pa + 16*j, ok);
            }
        }
        {
            int gr = n0 + lr; bool ok = (gr < N); int r = ok ? gr : 0;
            const char* pb = (const char*)(Bm + (size_t)r * K + k0) + lcB;
            #pragma unroll
            for (int j = 0; j < 4; j++) {
                unsigned o = swz(lr, lcB + 16*j);
                cp16(sb + TILE_B + o, pb + 16*j, ok);
            }
        }
    };

    stage2(sbase, 0);
    CP_COMMIT();

    const int a_rin  = lane & 15;
    const int a_cB   = (lane >> 4) * 16;
    const int b_sel  = lane >> 3;
    const int b_rin  = (b_sel >> 1) * 8 + (lane & 7);
    const int b_cB   = (b_sel & 1) * 16;

    for (int cI = 0; cI < nc; ++cI) {
        const int s = cI & 1;
        if (cI + 1 < nc) {
            stage2(sbase + (unsigned)(1 - s) * STAGE2_B, (cI + 1) << 6);
            CP_COMMIT();
            CP_WAIT_1();
        } else {
            CP_WAIT_0();
        }
        __syncthreads();

        const unsigned st = sbase + (unsigned)s * STAGE2_B;
        #pragma unroll
        for (int ks = 0; ks < 4; ++ks) {
            unsigned ra[4][4], rb[4][2];
            #pragma unroll
            for (int i = 0; i < 4; ++i) {
                int row = wm*64 + i*16 + a_rin;
                unsigned o = swz(row, ks*32 + a_cB);
                ldmx4(ra[i], st + o);
            }
            #pragma unroll
            for (int jp = 0; jp < 2; ++jp) {
                int row = wn*32 + jp*16 + b_rin;
                unsigned o = swz(row, ks*32 + b_cB);
                unsigned r[4];
                ldmx4(r, st + TILE_B + o);
                rb[2*jp][0] = r[0]; rb[2*jp][1] = r[1];
                rb[2*jp+1][0] = r[2]; rb[2*jp+1][1] = r[3];
            }
            #pragma unroll
            for (int i = 0; i < 4; ++i)
                #pragma unroll
                for (int j = 0; j < 4; ++j)
                    mma16816h(acc[i][j], ra[i], rb[j]);
        }
        __syncthreads();
    }

    const int group = lane >> 2, tig = lane & 3;
    #pragma unroll
    for (int i = 0; i < 4; ++i) {
        int m_lo = m0 + wm*64 + i*16 + group;
        #pragma unroll
        for (int j = 0; j < 4; ++j) {
            int nA = n0 + wn*32 + j*8 + tig*2;
            #pragma unroll
            for (int h = 0; h < 2; ++h) {
                int m = m_lo + h*8;
                if (m >= M) continue;
                float* crow = Cm + (long long)m * N;
                #pragma unroll
                for (int e = 0; e < 2; ++e) {
                    int n = nA + e;
                    if (n < N) crow[n] = acc[i][j][h*2 + e];
                }
            }
        }
    }
}

// ======================== fused flash attention (bf16 3-term) ================
#define FA_QTILE 16384
#define FA_STAGE 65536
#define FA_SMEM  (2*FA_QTILE + 2*FA_STAGE)   // 163840

__global__ __launch_bounds__(256, 1)
void flash_attn(const __nv_bfloat16* __restrict__ Qh, const __nv_bfloat16* __restrict__ Ql,
                const __nv_bfloat16* __restrict__ Kh, const __nv_bfloat16* __restrict__ Kl,
                const __nv_bfloat16* __restrict__ Vth, const __nv_bfloat16* __restrict__ Vtl,
                float* __restrict__ YH)
{
    extern __shared__ char smem_raw[];
    const unsigned sbase = smem_u32(smem_raw);
    const int m0 = blockIdx.x * 128;
    const int bh = blockIdx.y;
    const int tid = threadIdx.x;
    const int lane = tid & 31;
    const int wid = tid >> 5;

    const __nv_bfloat16* qh  = Qh  + (size_t)bh * TLEN * HD;
    const __nv_bfloat16* ql  = Ql  + (size_t)bh * TLEN * HD;
    const __nv_bfloat16* kh  = Kh  + (size_t)bh * TLEN * HD;
    const __nv_bfloat16* kl  = Kl  + (size_t)bh * TLEN * HD;
    const __nv_bfloat16* vth = Vth + (size_t)bh * HD * TLEN;
    const __nv_bfloat16* vtl = Vtl + (size_t)bh * HD * TLEN;

    const unsigned sQ = sbase;
    const unsigned sStage = sbase + 2*FA_QTILE;

    {
        int lr = tid >> 1, lcB = (tid & 1) << 6;
        const char* pqh = (const char*)(qh + (size_t)(m0 + lr) * HD) + lcB;
        const char* pql = (const char*)(ql + (size_t)(m0 + lr) * HD) + lcB;
        #pragma unroll
        for (int j = 0; j < 4; j++) {
            unsigned o = swz(lr, lcB + 16*j);
            cp16(sQ + o,            pqh + 16*j, true);
            cp16(sQ + FA_QTILE + o, pql + 16*j, true);
        }
    }
    CP_COMMIT();

    const int nkb = blockIdx.x + 1;

    auto load_stage = [&](int kb, int s) {
        unsigned st = sStage + (unsigned)s * FA_STAGE;
        int lr = tid >> 1, lcB = (tid & 1) << 6;
        const char* pkh = (const char*)(kh + (size_t)(kb*128 + lr) * HD) + lcB;
        const char* pkl = (const char*)(kl + (size_t)(kb*128 + lr) * HD) + lcB;
        #pragma unroll
        for (int j = 0; j < 4; j++) {
            unsigned o = swz(lr, lcB + 16*j);
            cp16(st + o,         pkh + 16*j, true);
            cp16(st + 16384 + o, pkl + 16*j, true);
        }
        int vr = tid >> 2, vc = (tid & 3) << 5;
        #pragma unroll
        for (int c = 0; c < 2; c++) {
            const char* pvh = (const char*)(vth + (size_t)vr * TLEN + kb*128 + c*64) + vc;
            const char* pvl = (const char*)(vtl + (size_t)vr * TLEN + kb*128 + c*64) + vc;
            unsigned vb = st + 32768 + (unsigned)c * 8192;
            #pragma unroll
            for (int j = 0; j < 2; j++) {
                unsigned o = swz(vr, vc + 16*j);
                cp16(vb + o,         pvh + 16*j, true);
                cp16(vb + 16384 + o, pvl + 16*j, true);
            }
        }
    };

    load_stage(0, 0);
    CP_COMMIT();
    CP_WAIT_1();
    __syncthreads();

    unsigned qfh[4][4], qfl[4][4];
    const int a_rin = lane & 15, a_cB = (lane >> 4) * 16;
    #pragma unroll
    for (int ks = 0; ks < 4; ks++) {
        unsigned o = swz(wid*16 + a_rin, ks*32 + a_cB);
        ldmx4(qfh[ks], sQ + o);
        ldmx4(qfl[ks], sQ + FA_QTILE + o);
    }

    float O[8][4];
    #pragma unroll
    for (int i = 0; i < 8; i++)
        #pragma unroll
        for (int t = 0; t < 4; t++) O[i][t] = 0.f;
    float mrun0 = -1e30f, mrun1 = -1e30f, lrun0 = 0.f, lrun1 = 0.f;

    const int b_sel = lane >> 3;
    const int b_rin = (b_sel >> 1)*8 + (lane & 7);
    const int b_cB  = (b_sel & 1)*16;
    const int g = lane >> 2, tig = lane & 3;

    for (int kb = 0; kb < nkb; kb++) {
        if (kb + 1 < nkb) { load_stage(kb + 1, (kb + 1) & 1); CP_COMMIT(); CP_WAIT_1(); }
        else CP_WAIT_0();
        __syncthreads();
        const unsigned st = sStage + (unsigned)(kb & 1) * FA_STAGE;

        float S[16][4];
        #pragma unroll
        for (int j = 0; j < 16; j++)
            #pragma unroll
            for (int t = 0; t < 4; t++) S[j][t] = 0.f;

        #pragma unroll
        for (int ks = 0; ks < 4; ks++) {
            #pragma unroll
            for (int jp = 0; jp < 8; jp++) {
                unsigned o = swz(jp*16 + b_rin, ks*32 + b_cB);
                unsigned rh[4], rl[4];
                ldmx4(rh, st + o);
                ldmx4(rl, st + 16384 + o);
                unsigned bh0[2] = {rh[0], rh[1]}, bh1[2] = {rh[2], rh[3]};
                unsigned bl0[2] = {rl[0], rl[1]}, bl1[2] = {rl[2], rl[3]};
                mma16816(S[2*jp],   qfh[ks], bh0);
                mma16816(S[2*jp],   qfl[ks], bh0);
                mma16816(S[2*jp],   qfh[ks], bl0);
                mma16816(S[2*jp+1], qfh[ks], bh1);
                mma16816(S[2*jp+1], qfl[ks], bh1);
                mma16816(S[2*jp+1], qfh[ks], bl1);
            }
        }
        #pragma unroll
        for (int j = 0; j < 16; j++)
            #pragma unroll
            for (int t = 0; t < 4; t++) S[j][t] *= 0.125f;

        if (kb == nkb - 1) {
            int row0 = m0 + wid*16 + g;
            int row1 = row0 + 8;
            #pragma unroll
            for (int j = 0; j < 16; j++) {
                int col = kb*128 + j*8 + tig*2;
                if (col     > row0) S[j][0] = -1e30f;
                if (col + 1 > row0) S[j][1] = -1e30f;
                if (col     > row1) S[j][2] = -1e30f;
                if (col + 1 > row1) S[j][3] = -1e30f;
            }
        }

        float mx0 = -1e30f, mx1 = -1e30f;
        #pragma unroll
        for (int j = 0; j < 16; j++) {
            mx0 = fmaxf(mx0, fmaxf(S[j][0], S[j][1]));
            mx1 = fmaxf(mx1, fmaxf(S[j][2], S[j][3]));
        }
        mx0 = fmaxf(mx0, __shfl_xor_sync(0xffffffffu, mx0, 1));
        mx0 = fmaxf(mx0, __shfl_xor_sync(0xffffffffu, mx0, 2));
        mx1 = fmaxf(mx1, __shfl_xor_sync(0xffffffffu, mx1, 1));
        mx1 = fmaxf(mx1, __shfl_xor_sync(0xffffffffu, mx1, 2));
        float nm0 = fmaxf(mrun0, mx0), nm1 = fmaxf(mrun1, mx1);
        float f0 = expf(mrun0 - nm0), f1 = expf(mrun1 - nm1);
        mrun0 = nm0; mrun1 = nm1;
        float rs0 = 0.f, rs1 = 0.f;
        #pragma unroll
        for (int j = 0; j < 16; j++) {
            S[j][0] = expf(S[j][0] - nm0);
            S[j][1] = expf(S[j][1] - nm0);
            S[j][2] = expf(S[j][2] - nm1);
            S[j][3] = expf(S[j][3] - nm1);
            rs0 += S[j][0] + S[j][1];
            rs1 += S[j][2] + S[j][3];
        }
        rs0 += __shfl_xor_sync(0xffffffffu, rs0, 1);
        rs0 += __shfl_xor_sync(0xffffffffu, rs0, 2);
        rs1 += __shfl_xor_sync(0xffffffffu, rs1, 1);
        rs1 += __shfl_xor_sync(0xffffffffu, rs1, 2);
        lrun0 = lrun0 * f0 + rs0;
        lrun1 = lrun1 * f1 + rs1;
        #pragma unroll
        for (int i = 0; i < 8; i++) {
            O[i][0] *= f0; O[i][1] *= f0;
            O[i][2] *= f1; O[i][3] *= f1;
        }

        #pragma unroll
        for (int c2 = 0; c2 < 2; c2++) {
            const unsigned vst = st + 32768 + (unsigned)c2 * 8192;
            #pragma unroll
            for (int ks = 0; ks < 4; ks++) {
                const int sI = c2*4 + ks;
                const float* e0 = S[2*sI];
                const float* e1 = S[2*sI + 1];
                unsigned ah[4], al[4];
                ah[0] = packbf(e0[0], e0[1]);
                ah[1] = packbf(e0[2], e0[3]);
                ah[2] = packbf(e1[0], e1[1]);
                ah[3] = packbf(e1[2], e1[3]);
                al[0] = packbf(e0[0] - __bfloat162float(__float2bfloat16(e0[0])),
                               e0[1] - __bfloat162float(__float2bfloat16(e0[1])));
                al[1] = packbf(e0[2] - __bfloat162float(__float2bfloat16(e0[2])),
                               e0[3] - __bfloat162float(__float2bfloat16(e0[3])));
                al[2] = packbf(e1[0] - __bfloat162float(__float2bfloat16(e1[0])),
                               e1[1] - __bfloat162float(__float2bfloat16(e1[1])));
                al[3] = packbf(e1[2] - __bfloat162float(__float2bfloat16(e1[2])),
                               e1[3] - __bfloat162float(__float2bfloat16(e1[3])));
                #pragma unroll
                for (int jp = 0; jp < 4; jp++) {
                    unsigned o = swz(jp*16 + b_rin, ks*32 + b_cB);
                    unsigned rh[4], rl[4];
                    ldmx4(rh, vst + o);
                    ldmx4(rl, vst + 16384 + o);
                    unsigned bh0[2] = {rh[0], rh[1]}, bh1[2] = {rh[2], rh[3]};
                    unsigned bl0[2] = {rl[0], rl[1]}, bl1[2] = {rl[2], rl[3]};
                    mma16816(O[2*jp],   ah, bh0);
                    mma16816(O[2*jp],   al, bh0);
                    mma16816(O[2*jp],   ah, bl0);
                    mma16816(O[2*jp+1], ah, bh1);
                    mma16816(O[2*jp+1], al, bh1);
                    mma16816(O[2*jp+1], ah, bl1);
                }
            }
        }
        __syncthreads();
    }

    float inv0 = 1.f / lrun0, inv1 = 1.f / lrun1;
    float* y0 = YH + ((size_t)bh * TLEN + m0 + wid*16 + g) * HD;
    float* y1 = y0 + 8 * HD;
    #pragma unroll
    for (int i = 0; i < 8; i++) {
        int d = i*8 + tig*2;
        y0[d]     = O[i][0] * inv0;
        y0[d + 1] = O[i][1] * inv0;
        y1[d]     = O[i][2] * inv1;
        y1[d + 1] = O[i][3] * inv1;
    }
}

// ======================== small kernels ======================================
__global__ void detect_idx_kernel(const unsigned int* w) {
    __shared__ unsigned int s;
    if (threadIdx.x == 0) s = 0u;
    __syncthreads();
    unsigned int v = 0u;
    for (int i = threadIdx.x; i < 1024; i += blockDim.x) v |= w[2*i + 1];
    atomicOr(&s, v);
    __syncthreads();
    if (threadIdx.x == 0) g_idx32 = (s != 0u) ? 1 : 0;
}

__global__ void embed_kernel(const void* idx, const float* __restrict__ wte,
                             const float* __restrict__ wpe, float* __restrict__ x) {
    int i = blockIdx.x * blockDim.x + threadIdx.x;
    if (i >= MTOK*CDIM) return;
    int c  = i % CDIM;
    int bt = i / CDIM;
    int t  = bt % TLEN;
    long long tok;
    if (g_idx32) tok = (long long)((const int*)idx)[bt];
    else         tok = ((const long long*)idx)[bt];
    x[i] = wte[tok*CDIM + c] + wpe[(long long)t*CDIM + c];
}

// layernorm -> fp16 hi/lo split (+ optional fused lora x@A^T)
__global__ void ln_lora_kernel(const float* __restrict__ x, const float* __restrict__ g,
                               const float* __restrict__ b,
                               const float* __restrict__ lA,
                               __half* __restrict__ oh, __half* __restrict__ ol,
                               float* __restrict__ tmp) {
    const int row = blockIdx.x;
    const float* xr = x + (long long)row * CDIM;
    __shared__ float sx[CDIM];
    __shared__ float red[128];
    __shared__ float s_mean, s_rstd;
    int tid = threadIdx.x;
    float s = 0.f;
    for (int c = tid; c < CDIM; c += 128) { float v = xr[c]; sx[c] = v; s += v; }
    red[tid] = s; __syncthreads();
    for (int st = 64; st > 0; st >>= 1) { if (tid < st) red[tid] += red[tid+st]; __syncthreads(); }
    if (tid == 0) s_mean = red[0] / (float)CDIM;
    __syncthreads();
    float mean = s_mean;
    float sq = 0.f;
    for (int c = tid; c < CDIM; c += 128) { float d = sx[c] - mean; sq += d*d; }
    red[tid] = sq; __syncthreads();
    for (int st = 64; st > 0; st >>= 1) { if (tid < st) red[tid] += red[tid+st]; __syncthreads(); }
    if (tid == 0) s_rstd = rsqrtf(red[0] / (float)CDIM + 1e-5f);
    __syncthreads();
    float mean2 = s_mean, rstd = s_rstd;
    for (int c = tid; c < CDIM; c += 128) {
        float v = (sx[c] - mean2) * rstd * g[c] + b[c];
        long long o = (long long)row*CDIM + c;
        __half hi, lo; hsplit(v, hi, lo);
        oh[o] = hi; ol[o] = lo;
        sx[c] = v;
    }
    __syncthreads();
    if (lA) {
        int w = tid >> 5, lane = tid & 31;
        #pragma unroll
        for (int rr = 0; rr < 2; ++rr) {
            int r = w*2 + rr;
            const float* Ar = lA + (long long)r * CDIM;
            float acc = 0.f;
            for (int c = lane; c < CDIM; c += 32) acc += sx[c] * Ar[c];
            #pragma unroll
            for (int off = 16; off > 0; off >>= 1) acc += __shfl_down_sync(0xffffffffu, acc, off);
            if (lane == 0) tmp[row*RANK + r] = acc;
        }
    }
}

// final layernorm -> single fp16 (for 1-MMA head)
__global__ void ln_f16_kernel(const float* __restrict__ x, const float* __restrict__ g,
                              const float* __restrict__ b, __half* __restrict__ oh) {
    const int row = blockIdx.x;
    const float* xr = x + (long long)row * CDIM;
    __shared__ float sx[CDIM];
    __shared__ float red[128];
    __shared__ float s_mean, s_rstd;
    int tid = threadIdx.x;
    float s = 0.f;
    for (int c = tid; c < CDIM; c += 128) { float v = xr[c]; sx[c] = v; s += v; }
    red[tid] = s; __syncthreads();
    for (int st = 64; st > 0; st >>= 1) { if (tid < st) red[tid] += red[tid+st]; __syncthreads(); }
    if (tid == 0) s_mean = red[0] / (float)CDIM;
    __syncthreads();
    float mean = s_mean;
    float sq = 0.f;
    for (int c = tid; c < CDIM; c += 128) { float d = sx[c] - mean; sq += d*d; }
    red[tid] = sq; __syncthreads();
    for (int st = 64; st > 0; st >>= 1) { if (tid < st) red[tid] += red[tid+st]; __syncthreads(); }
    if (tid == 0) s_rstd = rsqrtf(red[0] / (float)CDIM + 1e-5f);
    __syncthreads();
    float mean2 = s_mean, rstd = s_rstd;
    for (int c = tid; c < CDIM; c += 128) {
        float v = (sx[c] - mean2) * rstd * g[c] + b[c];
        oh[(long long)row*CDIM + c] = __float2half(v);
    }
}

// fp32 -> fp16 weight conversion (4 groups, vectorized)
__global__ void wcvt16_kernel(const float* __restrict__ wq, const float* __restrict__ wp,
                              const float* __restrict__ wf, const float* __restrict__ wm,
                              __half* __restrict__ q16, __half* __restrict__ p16,
                              __half* __restrict__ f16, __half* __restrict__ m16) {
    const int NQ = NLAYER*3*CDIM*CDIM, NP = NLAYER*CDIM*CDIM,
              NF = NLAYER*4*CDIM*CDIM, NM = NLAYER*CDIM*4*CDIM;
    int i4 = (blockIdx.x * 256 + threadIdx.x) * 4;
    const float* src; __half* dst; int k;
    if (i4 < NQ)                { src = wq; dst = q16; k = i4; }
    else if (i4 < NQ+NP)        { src = wp; dst = p16; k = i4 - NQ; }
    else if (i4 < NQ+NP+NF)     { src = wf; dst = f16; k = i4 - NQ - NP; }
    else if (i4 < NQ+NP+NF+NM)  { src = wm; dst = m16; k = i4 - NQ - NP - NF; }
    else return;
    float4 v = *reinterpret_cast<const float4*>(src + k);
    __half2 a = __floats2half2_rn(v.x, v.y);
    __half2 b = __floats2half2_rn(v.z, v.w);
    uint2 o;
    o.x = reinterpret_cast<unsigned&>(a);
    o.y = reinterpret_cast<unsigned&>(b);
    *reinterpret_cast<uint2*>(dst + k) = o;
}

__global__ void wsplit_f16_kernel(const float* __restrict__ w, __half* __restrict__ h, int n) {
    int i4 = (blockIdx.x * 256 + threadIdx.x) * 4;
    if (i4 >= n) return;
    float4 v = *reinterpret_cast<const float4*>(w + i4);
    __half2 a = __floats2half2_rn(v.x, v.y);
    __half2 b = __floats2half2_rn(v.z, v.w);
    uint2 o;
    o.x = reinterpret_cast<unsigned&>(a);
    o.y = reinterpret_cast<unsigned&>(b);
    *reinterpret_cast<uint2*>(h + i4) = o;
}

// merge heads -> fp16 hi/lo split + fused lora x@A^T
__global__ void merge_lora_kernel(const float* __restrict__ yh,
                                  const float* __restrict__ lA,
                                  __half* __restrict__ oh, __half* __restrict__ ol,
                                  float* __restrict__ tmp) {
    const int row = blockIdx.x;
    const int t = row & (TLEN - 1);
    const int b = row >> 10;
    __shared__ float sy[CDIM];
    int tid = threadIdx.x;
    for (int c = tid; c < CDIM; c += 128) {
        int h = c >> 6, d = c & 63;
        sy[c] = yh[(((long long)(b*NHEAD + h) * TLEN) + t) * HD + d];
    }
    __syncthreads();
    for (int c = tid; c < CDIM; c += 128) {
        long long o = (long long)row*CDIM + c;
        __half hi, lo; hsplit(sy[c], hi, lo);
        oh[o] = hi; ol[o] = lo;
    }
    int w = tid >> 5, lane = tid & 31;
    #pragma unroll
    for (int rr = 0; rr < 2; ++rr) {
        int r = w*2 + rr;
        const float* Ar = lA + (long long)r * CDIM;
        float acc = 0.f;
        for (int c = lane; c < CDIM; c += 32) acc += sy[c] * Ar[c];
        #pragma unroll
        for (int off = 16; off > 0; off >>= 1) acc += __shfl_down_sync(0xffffffffu, acc, off);
        if (lane == 0) tmp[row*RANK + r] = acc;
    }
}

// ======================== host driver ========================================
template<int MODE, int SPLITK>
static void launch_gemm_h(dim3 grid,
                          const __half* Ah, const __half* Al, const __half* Bm,
                          const float* bias, const float* loraT, const float* loraB,
                          float* Cm, int M, int N, int K) {
    cudaFuncSetAttribute(mma_gemm_h<MODE, SPLITK>,
                         cudaFuncAttributeMaxDynamicSharedMemorySize, LGEMM_SMEM);
    mma_gemm_h<MODE, SPLITK><<<grid, 256, LGEMM_SMEM>>>(
        Ah, Al, Bm, bias, loraT, loraB, Cm, M, N, K);
}

extern "C" void kernel_launch(void* const* d_in, const int* in_sizes, int n_in,
                              void* d_out, int out_size) {
    (void)in_sizes; (void)n_in; (void)out_size;
    const void*  idx     = d_in[0];
    const float* wte     = (const float*)d_in[1];
    const float* wpe     = (const float*)d_in[2];
    const float* ln1_g   = (const float*)d_in[3];
    const float* ln1_b   = (const float*)d_in[4];
    const float* attn_w  = (const float*)d_in[5];
    const float* attn_lA = (const float*)d_in[6];
    const float* attn_lB = (const float*)d_in[7];
    const float* proj_w  = (const float*)d_in[8];
    const float* proj_lA = (const float*)d_in[9];
    const float* proj_lB = (const float*)d_in[10];
    const float* ln2_g   = (const float*)d_in[11];
    const float* ln2_b   = (const float*)d_in[12];
    const float* fc_w    = (const float*)d_in[13];
    const float* fc_b    = (const float*)d_in[14];
    const float* mproj_w = (const float*)d_in[15];
    const float* mproj_b = (const float*)d_in[16];
    const float* lnf_g   = (const float*)d_in[17];
    const float* lnf_b   = (const float*)d_in[18];
    const float* head_w  = (const float*)d_in[19];
    float* out = (float*)d_out;

    float *X, *YH, *TMP, *QKVp;
    cudaGetSymbolAddress((void**)&X,    g_X);
    cudaGetSymbolAddress((void**)&YH,   g_YH);
    cudaGetSymbolAddress((void**)&TMP,  g_TMP);
    cudaGetSymbolAddress((void**)&QKVp, g_QKVp);

    __half *wqkv16, *wproj16, *wfc16, *wmp16, *whead16,
           *H16h, *H16l, *Y16h, *Y16l, *FCG16h, *FCG16l;
    __nv_bfloat16 *Qh, *Ql, *Kh, *Kl, *Vth, *Vtl;
    cudaGetSymbolAddress((void**)&wqkv16,  g_wqkv16);
    cudaGetSymbolAddress((void**)&wproj16, g_wproj16);
    cudaGetSymbolAddress((void**)&wfc16,   g_wfc16);
    cudaGetSymbolAddress((void**)&wmp16,   g_wmp16);
    cudaGetSymbolAddress((void**)&whead16, g_whead16);
    cudaGetSymbolAddress((void**)&H16h, g_H16h); cudaGetSymbolAddress((void**)&H16l, g_H16l);
    cudaGetSymbolAddress((void**)&Y16h, g_Y16h); cudaGetSymbolAddress((void**)&Y16l, g_Y16l);
    cudaGetSymbolAddress((void**)&FCG16h, g_FCG16h); cudaGetSymbolAddress((void**)&FCG16l, g_FCG16l);
    cudaGetSymbolAddress((void**)&Qh,   g_Qh);   cudaGetSymbolAddress((void**)&Ql,   g_Ql);
    cudaGetSymbolAddress((void**)&Kh,   g_Kh);   cudaGetSymbolAddress((void**)&Kl,   g_Kl);
    cudaGetSymbolAddress((void**)&Vth,  g_Vth);  cudaGetSymbolAddress((void**)&Vtl,  g_Vtl);

    cudaFuncSetAttribute(flash_attn, cudaFuncAttributeMaxDynamicSharedMemorySize, FA_SMEM);

    detect_idx_kernel<<<1, 256>>>((const unsigned int*)idx);
    embed_kernel<<<(MTOK*CDIM + 255)/256, 256>>>(idx, wte, wpe, X);
    {
        int nA = NLAYER*(3*CDIM*CDIM + CDIM*CDIM + 4*CDIM*CDIM + 4*CDIM*CDIM);
        wcvt16_kernel<<<(nA/4 + 255)/256, 256>>>(attn_w, proj_w, fc_w, mproj_w,
            wqkv16, wproj16, wfc16, wmp16);
        int nB = VOCAB*CDIM;
        wsplit_f16_kernel<<<(nB/4 + 255)/256, 256>>>(head_w, whead16, nB);
    }

    for (int l = 0; l < NLAYER; l++) {
        long long oq = (long long)l * 3*CDIM*CDIM;
        long long op = (long long)l * CDIM*CDIM;
        long long of = (long long)l * 4*CDIM*CDIM;
        long long om = (long long)l * CDIM*4*CDIM;
        const float* lA_q = attn_lA + (long long)l * RANK*CDIM;
        const float* lB_q = attn_lB + (long long)l * 3*CDIM*RANK;
        const float* lA_p = proj_lA + (long long)l * RANK*CDIM;
        const float* lB_p = proj_lB + (long long)l * CDIM*RANK;

        // ---- attention ----
        ln_lora_kernel<<<MTOK, 128>>>(X, ln1_g + l*CDIM, ln1_b + l*CDIM, lA_q, H16h, H16l, TMP);
        // qkv: split-K=2 into dual fp32 partial buffers
        launch_gemm_h<0, 1>(dim3(MTOK/128, 3*CDIM/128, 2),
            H16h, H16l, wqkv16 + oq, nullptr, TMP, lB_q, QKVp,
            MTOK, 3*CDIM, CDIM);
        split_qkv2_kernel<<<(NBATCH*TLEN*HD + 255)/256, 256>>>(QKVp);

        flash_attn<<<dim3(TLEN/128, NBATCH), 256, FA_SMEM>>>(Qh, Ql, Kh, Kl, Vth, Vtl, YH);
        merge_lora_kernel<<<MTOK, 128>>>(YH, lA_p, Y16h, Y16l, TMP);

        // proj: split-K=2 atomic residual into X
        launch_gemm_h<2, 1>(dim3(MTOK/128, CDIM/128, 2),
            Y16h, Y16l, wproj16 + op, nullptr, TMP, lB_p, X,
            MTOK, CDIM, CDIM);

        // ---- MLP ----
        ln_lora_kernel<<<MTOK, 128>>>(X, ln2_g + l*CDIM, ln2_b + l*CDIM, nullptr, H16h, H16l, TMP);
        launch_gemm_h<1, 0>(dim3(MTOK/128, 4*CDIM/128, 1),
            H16h, H16l, wfc16 + of, fc_b + (long long)l*4*CDIM, nullptr, nullptr, nullptr,
            MTOK, 4*CDIM, CDIM);
        // mproj: split-K=2 atomic residual into X
        launch_gemm_h<2, 1>(dim3(MTOK/128, CDIM/128, 2),
            FCG16h, FCG16l, wmp16 + om, mproj_b + (long long)l*CDIM, nullptr, nullptr, X,
            MTOK, CDIM, 4*CDIM);
    }

    // ---- final layernorm + fp16 1-MMA vocab head ----
    ln_f16_kernel<<<MTOK, 128>>>(X, lnf_g, lnf_b, H16h);
    cudaFuncSetAttribute(mma_gemm_f16, cudaFuncAttributeMaxDynamicSharedMemorySize, GEMM_SMEM_F16);
    mma_gemm_f16<<<dim3(MTOK/128, (VOCAB + 127)/128), 256, GEMM_SMEM_F16>>>(
        H16h, whead16, out, MTOK, VOCAB, CDIM);
}

// round 15
// speedup vs baseline: 1.5701x; 1.0551x over previous
#include <cuda_runtime.h>
#include <cuda_bf16.h>
#include <cuda_fp16.h>
#include <math.h>

// ---------------------------------------------------------------------------
// GPT_3959959847300 round 15: R14 + fp16 2-term flash attention (Q hi/lo fp16,
// K/V single fp16 -> 2 MMAs/tile, half the K/V stage traffic).
// ---------------------------------------------------------------------------

#define BSZ    2
#define TLEN   1024
#define CDIM   512
#define NHEAD  8
#define HD     64
#define NLAYER 4
#define VOCAB  50257
#define RANK   8
#define LSCALE 4.0f
#define MTOK   (BSZ*TLEN)
#define NBATCH (BSZ*NHEAD)

// ======================== PTX helpers ========================================
__device__ __forceinline__ unsigned smem_u32(const void* p) {
    unsigned a;
    asm("{ .reg .u64 t; cvta.to.shared.u64 t, %1; cvt.u32.u64 %0, t; }" : "=r"(a) : "l"(p));
    return a;
}
__device__ __forceinline__ void ldmx4(unsigned* r, unsigned addr) {
    asm volatile("ldmatrix.sync.aligned.m8n8.x4.shared.b16 {%0,%1,%2,%3}, [%4];"
                 : "=r"(r[0]), "=r"(r[1]), "=r"(r[2]), "=r"(r[3]) : "r"(addr));
}
__device__ __forceinline__ void mma16816h(float* d, const unsigned* a, const unsigned* b) {
    asm volatile(
        "mma.sync.aligned.m16n8k16.row.col.f32.f16.f16.f32 "
        "{%0,%1,%2,%3},{%4,%5,%6,%7},{%8,%9},{%0,%1,%2,%3};"
        : "+f"(d[0]), "+f"(d[1]), "+f"(d[2]), "+f"(d[3])
        : "r"(a[0]), "r"(a[1]), "r"(a[2]), "r"(a[3]), "r"(b[0]), "r"(b[1]));
}
__device__ __forceinline__ void cp16(unsigned dst, const void* src, bool pred) {
    int sz = pred ? 16 : 0;
    asm volatile("cp.async.cg.shared.global [%0], [%1], 16, %2;"
                 :: "r"(dst), "l"(src), "r"(sz) : "memory");
}
#define CP_COMMIT()  asm volatile("cp.async.commit_group;" ::: "memory")
#define CP_WAIT_1()  asm volatile("cp.async.wait_group 1;" ::: "memory")
#define CP_WAIT_0()  asm volatile("cp.async.wait_group 0;" ::: "memory")

__device__ __forceinline__ void hsplit(float x, __half& hi, __half& lo) {
    hi = __float2half(x);
    lo = __float2half(x - __half2float(hi));
}
__device__ __forceinline__ unsigned packh(float a, float b) {
    __half2 t = __floats2half2_rn(a, b);
    return reinterpret_cast<unsigned&>(t);
}

// ======================== scratch ============================================
__device__ float g_X  [MTOK*CDIM];
__device__ float g_YH [NBATCH*TLEN*HD];
__device__ float g_TMP[MTOK*RANK];
__device__ float g_QKVp[2ll*MTOK*3*CDIM];
__device__ int   g_idx32;

__device__ __half g_wqkv16[NLAYER*3*CDIM*CDIM];
__device__ __half g_wproj16[NLAYER*CDIM*CDIM];
__device__ __half g_wfc16 [NLAYER*4*CDIM*CDIM];
__device__ __half g_wmp16 [NLAYER*CDIM*4*CDIM];
__device__ __half g_whead16[VOCAB*CDIM];
__device__ __half g_H16h[MTOK*CDIM],  g_H16l[MTOK*CDIM];
__device__ __half g_Y16h[MTOK*CDIM],  g_Y16l[MTOK*CDIM];
__device__ __half g_FCG16h[MTOK*4*CDIM], g_FCG16l[MTOK*4*CDIM];
__device__ __half g_Q16h[NBATCH*TLEN*HD], g_Q16l[NBATCH*TLEN*HD];
__device__ __half g_K16 [NBATCH*TLEN*HD];
__device__ __half g_V16t[NBATCH*HD*TLEN];

// ======================== common tile helpers ================================
#define TILE_B    16384                 // 128x64 16-bit tile (128B rows, swizzled)
#define LSTAGE_B  (3*TILE_B)            // layer GEMM: Ah, Al, B
#define LGEMM_SMEM (2*LSTAGE_B)         // 98304
#define STAGE2_B  (2*TILE_B)            // fp16 head: A, B
#define GEMM_SMEM_F16 (2*STAGE2_B)      // 65536

__device__ __forceinline__ unsigned swz(int row, int colB) {
    unsigned o = (unsigned)(row * 128 + colB);
    return o ^ ((unsigned)(row & 7) << 4);
}

// ======================== fp16 2-term layer GEMM =============================
// MODE: 0 fp32 partial store (per-z buffers, +bias/lora on z==0)
//       1 gelu->fp16 hi/lo split; 2 residual += (atomicAdd if SPLITK)
template<int MODE, int SPLITK>
__global__ __launch_bounds__(256, 1)
void mma_gemm_h(const __half* __restrict__ Ah, const __half* __restrict__ Al,
                const __half* __restrict__ Bm,
                const float* __restrict__ bias,
                const float* __restrict__ loraT, const float* __restrict__ loraB,
                float* __restrict__ Cm,
                int M, int N, int K)
{
    extern __shared__ char smem_raw[];
    const int m0 = blockIdx.x * 128;
    const int n0 = blockIdx.y * 128;
    const int kz = SPLITK ? (int)blockIdx.z : 0;
    const int kslice = SPLITK ? (K >> 1) : K;
    const int koff = kz * kslice;

    const unsigned sbase = smem_u32(smem_raw);
    const int tid  = threadIdx.x;
    const int lane = tid & 31;
    const int wid  = tid >> 5;
    const int wm   = wid & 1;
    const int wn   = wid >> 1;
    const int lr   = tid >> 1;
    const int lcB  = (tid & 1) << 6;

    float acc[4][4][4];
    #pragma unroll
    for (int i = 0; i < 4; i++)
        #pragma unroll
        for (int j = 0; j < 4; j++)
            #pragma unroll
            for (int t = 0; t < 4; t++) acc[i][j][t] = 0.f;

    const int nc = kslice >> 6;

    auto stage3 = [&](unsigned sb, int k0) {
        {
            const char* pa = (const char*)(Ah + (size_t)(m0 + lr) * K + k0) + lcB;
            const char* pl = (const char*)(Al + (size_t)(m0 + lr) * K + k0) + lcB;
            #pragma unroll
            for (int j = 0; j < 4; j++) {
                unsigned o = swz(lr, lcB + 16*j);
                cp16(sb + o,          pa + 16*j, true);
                cp16(sb + TILE_B + o, pl + 16*j, true);
            }
        }
        {
            const char* pb = (const char*)(Bm + (size_t)(n0 + lr) * K + k0) + lcB;
            #pragma unroll
            for (int j = 0; j < 4; j++) {
                unsigned o = swz(lr, lcB + 16*j);
                cp16(sb + 2*TILE_B + o, pb + 16*j, true);
            }
        }
    };

    stage3(sbase, koff);
    CP_COMMIT();

    const int a_rin  = lane & 15;
    const int a_cB   = (lane >> 4) * 16;
    const int b_sel  = lane >> 3;
    const int b_rin  = (b_sel >> 1) * 8 + (lane & 7);
    const int b_cB   = (b_sel & 1) * 16;

    for (int cI = 0; cI < nc; ++cI) {
        const int s = cI & 1;
        if (cI + 1 < nc) {
            stage3(sbase + (unsigned)(1 - s) * LSTAGE_B, koff + ((cI + 1) << 6));
            CP_COMMIT();
            CP_WAIT_1();
        } else {
            CP_WAIT_0();
        }
        __syncthreads();

        const unsigned st = sbase + (unsigned)s * LSTAGE_B;
        #pragma unroll
        for (int ks = 0; ks < 4; ++ks) {
            unsigned ra_h[4][4], ra_l[4][4], rb[4][2];
            #pragma unroll
            for (int i = 0; i < 4; ++i) {
                int row = wm*64 + i*16 + a_rin;
                unsigned o = swz(row, ks*32 + a_cB);
                ldmx4(ra_h[i], st + o);
                ldmx4(ra_l[i], st + TILE_B + o);
            }
            #pragma unroll
            for (int jp = 0; jp < 2; ++jp) {
                int row = wn*32 + jp*16 + b_rin;
                unsigned o = swz(row, ks*32 + b_cB);
                unsigned r[4];
                ldmx4(r, st + 2*TILE_B + o);
                rb[2*jp][0] = r[0]; rb[2*jp][1] = r[1];
                rb[2*jp+1][0] = r[2]; rb[2*jp+1][1] = r[3];
            }
            #pragma unroll
            for (int i = 0; i < 4; ++i)
                #pragma unroll
                for (int j = 0; j < 4; ++j) {
                    mma16816h(acc[i][j], ra_h[i], rb[j]);
                    mma16816h(acc[i][j], ra_l[i], rb[j]);
                }
        }
        __syncthreads();
    }

    const int group = lane >> 2, tig = lane & 3;
    float* cbuf = (MODE == 0) ? (Cm + (size_t)kz * M * N) : Cm;
    #pragma unroll
    for (int i = 0; i < 4; ++i) {
        int m_lo = m0 + wm*64 + i*16 + group;
        #pragma unroll
        for (int j = 0; j < 4; ++j) {
            int nA = n0 + wn*32 + j*8 + tig*2;
            #pragma unroll
            for (int h = 0; h < 2; ++h) {
                int m = m_lo + h*8;
                #pragma unroll
                for (int e = 0; e < 2; ++e) {
                    int n = nA + e;
                    float v = acc[i][j][h*2 + e];
                    if (bias && kz == 0)  v += bias[n];
                    if (loraT && kz == 0) {
                        const float* t  = loraT + (size_t)m * RANK;
                        const float* bb = loraB + (size_t)n * RANK;
                        float s = 0.f;
                        #pragma unroll
                        for (int r = 0; r < RANK; r++) s += t[r] * bb[r];
                        v += LSCALE * s;
                    }
                    if (MODE == 0) {
                        cbuf[(long long)m * N + n] = v;
                    } else if (MODE == 2) {
                        if (SPLITK) atomicAdd(&Cm[(long long)m * N + n], v);
                        else        Cm[(long long)m * N + n] += v;
                    } else {
                        float gv = 0.5f * v * (1.f + tanhf(0.7978845608028654f * (v + 0.044715f * v*v*v)));
                        __half hi, lo; hsplit(gv, hi, lo);
                        g_FCG16h[(long long)m * N + n] = hi;
                        g_FCG16l[(long long)m * N + n] = lo;
                    }
                }
            }
        }
    }
}

// combine qkv split-K partials -> Q hi/lo fp16 (bhtd), K fp16 (bhtd), V^T fp16
__global__ void split_qkv2_kernel(const float* __restrict__ qkvp) {
    int i = blockIdx.x * 256 + threadIdx.x;
    if (i >= NBATCH*TLEN*HD) return;
    int d = i % HD;
    int t = (i / HD) % TLEN;
    int h = (i / (HD*TLEN)) % NHEAD;
    int b = i / (HD*TLEN*NHEAD);
    long long src = (long long)(b*TLEN + t) * (3*CDIM) + h*HD + d;
    const long long off = (long long)MTOK * 3*CDIM;
    float q = qkvp[src] + qkvp[src + off];
    float k = qkvp[src + CDIM] + qkvp[src + CDIM + off];
    float v = qkvp[src + 2*CDIM] + qkvp[src + 2*CDIM + off];
    __half hi, lo;
    hsplit(q, hi, lo); g_Q16h[i] = hi; g_Q16l[i] = lo;
    g_K16[i] = __float2half(k);
    long long vi = ((long long)(b*NHEAD + h) * HD + d) * TLEN + t;
    g_V16t[vi] = __float2half(v);
}

// ======================== fp16 1-MMA head GEMM (128x128, occ=2) ==============
__global__ __launch_bounds__(256, 2)
void mma_gemm_f16(const __half* __restrict__ Am, const __half* __restrict__ Bm,
                  float* __restrict__ Cm, int M, int N, int K)
{
    extern __shared__ char smem_raw[];
    const int m0 = blockIdx.x * 128;
    const int n0 = blockIdx.y * 128;

    const unsigned sbase = smem_u32(smem_raw);
    const int tid  = threadIdx.x;
    const int lane = tid & 31;
    const int wid  = tid >> 5;
    const int wm   = wid & 1;
    const int wn   = wid >> 1;
    const int lr   = tid >> 1;
    const int lcB  = (tid & 1) << 6;

    float acc[4][4][4];
    #pragma unroll
    for (int i = 0; i < 4; i++)
        #pragma unroll
        for (int j = 0; j < 4; j++)
            #pragma unroll
            for (int t = 0; t < 4; t++) acc[i][j][t] = 0.f;

    const int nc = K >> 6;

    auto stage2 = [&](unsigned sb, int k0) {
        {
            int gr = m0 + lr; bool ok = (gr < M); int r = ok ? gr : 0;
            const char* pa = (const char*)(Am + (size_t)r * K + k0) + lcB;
            #pragma unroll
            for (int j = 0; j < 4; j++) {
                unsigned o = swz(lr, lcB + 16*j);
                cp16(sb + o, pa + 16*j, ok);
            }
        }
        {
            int gr = n0 + lr; bool ok = (gr < N); int r = ok ? gr : 0;
            const char* pb = (const char*)(Bm + (size_t)r * K + k0) + lcB;
            #pragma unroll
            for (int j = 0; j < 4; j++) {
                unsigned o = swz(lr, lcB + 16*j);
                cp16(sb + TILE_B + o, pb + 16*j, ok);
            }
        }
    };

    stage2(sbase, 0);
    CP_COMMIT();

    const int a_rin  = lane & 15;
    const int a_cB   = (lane >> 4) * 16;
    const int b_sel  = lane >> 3;
    const int b_rin  = (b_sel >> 1) * 8 + (lane & 7);
    const int b_cB   = (b_sel & 1) * 16;

    for (int cI = 0; cI < nc; ++cI) {
        const int s = cI & 1;
        if (cI + 1 < nc) {
            stage2(sbase + (unsigned)(1 - s) * STAGE2_B, (cI + 1) << 6);
            CP_COMMIT();
            CP_WAIT_1();
        } else {
            CP_WAIT_0();
        }
        __syncthreads();

        const unsigned st = sbase + (unsigned)s * STAGE2_B;
        #pragma unroll
        for (int ks = 0; ks < 4; ++ks) {
            unsigned ra[4][4], rb[4][2];
            #pragma unroll
            for (int i = 0; i < 4; ++i) {
                int row = wm*64 + i*16 + a_rin;
                unsigned o = swz(row, ks*32 + a_cB);
                ldmx4(ra[i], st + o);
            }
            #pragma unroll
            for (int jp = 0; jp < 2; ++jp) {
                int row = wn*32 + jp*16 + b_rin;
                unsigned o = swz(row, ks*32 + b_cB);
                unsigned r[4];
                ldmx4(r, st + TILE_B + o);
                rb[2*jp][0] = r[0]; rb[2*jp][1] = r[1];
                rb[2*jp+1][0] = r[2]; rb[2*jp+1][1] = r[3];
            }
            #pragma unroll
            for (int i = 0; i < 4; ++i)
                #pragma unroll
                for (int j = 0; j < 4; ++j)
                    mma16816h(acc[i][j], ra[i], rb[j]);
        }
        __syncthreads();
    }

    const int group = lane >> 2, tig = lane & 3;
    #pragma unroll
    for (int i = 0; i < 4; ++i) {
        int m_lo = m0 + wm*64 + i*16 + group;
        #pragma unroll
        for (int j = 0; j < 4; ++j) {
            int nA = n0 + wn*32 + j*8 + tig*2;
            #pragma unroll
            for (int h = 0; h < 2; ++h) {
                int m = m_lo + h*8;
                if (m >= M) continue;
                float* crow = Cm + (long long)m * N;
                #pragma unroll
                for (int e = 0; e < 2; ++e) {
                    int n = nA + e;
                    if (n < N) crow[n] = acc[i][j][h*2 + e];
                }
            }
        }
    }
}

// ======================== fused flash attention (fp16 2-term) ================
#define FA_QTILE 16384
#define FA_STAGE 32768          // K 16K | V 16K (2x8K)
#define FA_SMEM  (2*FA_QTILE + 2*FA_STAGE)   // 98304

__global__ __launch_bounds__(256, 1)
void flash_attn(const __half* __restrict__ Qh, const __half* __restrict__ Ql,
                const __half* __restrict__ Km, const __half* __restrict__ Vt,
                float* __restrict__ YH)
{
    extern __shared__ char smem_raw[];
    const unsigned sbase = smem_u32(smem_raw);
    const int m0 = blockIdx.x * 128;
    const int bh = blockIdx.y;
    const int tid = threadIdx.x;
    const int lane = tid & 31;
    const int wid = tid >> 5;

    const __half* qh = Qh + (size_t)bh * TLEN * HD;
    const __half* ql = Ql + (size_t)bh * TLEN * HD;
    const __half* km = Km + (size_t)bh * TLEN * HD;
    const __half* vt = Vt + (size_t)bh * HD * TLEN;

    const unsigned sQ = sbase;
    const unsigned sStage = sbase + 2*FA_QTILE;

    {
        int lr = tid >> 1, lcB = (tid & 1) << 6;
        const char* pqh = (const char*)(qh + (size_t)(m0 + lr) * HD) + lcB;
        const char* pql = (const char*)(ql + (size_t)(m0 + lr) * HD) + lcB;
        #pragma unroll
        for (int j = 0; j < 4; j++) {
            unsigned o = swz(lr, lcB + 16*j);
            cp16(sQ + o,            pqh + 16*j, true);
            cp16(sQ + FA_QTILE + o, pql + 16*j, true);
        }
    }
    CP_COMMIT();

    const int nkb = blockIdx.x + 1;

    auto load_stage = [&](int kb, int s) {
        unsigned st = sStage + (unsigned)s * FA_STAGE;
        int lr = tid >> 1, lcB = (tid & 1) << 6;
        const char* pk = (const char*)(km + (size_t)(kb*128 + lr) * HD) + lcB;
        #pragma unroll
        for (int j = 0; j < 4; j++) {
            unsigned o = swz(lr, lcB + 16*j);
            cp16(st + o, pk + 16*j, true);
        }
        int vr = tid >> 2, vc = (tid & 3) << 5;
        #pragma unroll
        for (int c = 0; c < 2; c++) {
            const char* pv = (const char*)(vt + (size_t)vr * TLEN + kb*128 + c*64) + vc;
            unsigned vb = st + 16384 + (unsigned)c * 8192;
            #pragma unroll
            for (int j = 0; j < 2; j++) {
                unsigned o = swz(vr, vc + 16*j);
                cp16(vb + o, pv + 16*j, true);
            }
        }
    };

    load_stage(0, 0);
    CP_COMMIT();
    CP_WAIT_1();
    __syncthreads();

    unsigned qfh[4][4], qfl[4][4];
    const int a_rin = lane & 15, a_cB = (lane >> 4) * 16;
    #pragma unroll
    for (int ks = 0; ks < 4; ks++) {
        unsigned o = swz(wid*16 + a_rin, ks*32 + a_cB);
        ldmx4(qfh[ks], sQ + o);
        ldmx4(qfl[ks], sQ + FA_QTILE + o);
    }

    float O[8][4];
    #pragma unroll
    for (int i = 0; i < 8; i++)
        #pragma unroll
        for (int t = 0; t < 4; t++) O[i][t] = 0.f;
    float mrun0 = -1e30f, mrun1 = -1e30f, lrun0 = 0.f, lrun1 = 0.f;

    const int b_sel = lane >> 3;
    const int b_rin = (b_sel >> 1)*8 + (lane & 7);
    const int b_cB  = (b_sel & 1)*16;
    const int g = lane >> 2, tig = lane & 3;

    for (int kb = 0; kb < nkb; kb++) {
        if (kb + 1 < nkb) { load_stage(kb + 1, (kb + 1) & 1); CP_COMMIT(); CP_WAIT_1(); }
        else CP_WAIT_0();
        __syncthreads();
        const unsigned st = sStage + (unsigned)(kb & 1) * FA_STAGE;

        float S[16][4];
        #pragma unroll
        for (int j = 0; j < 16; j++)
            #pragma unroll
            for (int t = 0; t < 4; t++) S[j][t] = 0.f;

        #pragma unroll
        for (int ks = 0; ks < 4; ks++) {
            #pragma unroll
            for (int jp = 0; jp < 8; jp++) {
                unsigned o = swz(jp*16 + b_rin, ks*32 + b_cB);
                unsigned r[4];
                ldmx4(r, st + o);
                unsigned b0[2] = {r[0], r[1]}, b1[2] = {r[2], r[3]};
                mma16816h(S[2*jp],   qfh[ks], b0);
                mma16816h(S[2*jp],   qfl[ks], b0);
                mma16816h(S[2*jp+1], qfh[ks], b1);
                mma16816h(S[2*jp+1], qfl[ks], b1);
            }
        }
        #pragma unroll
        for (int j = 0; j < 16; j++)
            #pragma unroll
            for (int t = 0; t < 4; t++) S[j][t] *= 0.125f;

        if (kb == nkb - 1) {
            int row0 = m0 + wid*16 + g;
            int row1 = row0 + 8;
            #pragma unroll
            for (int j = 0; j < 16; j++) {
                int col = kb*128 + j*8 + tig*2;
                if (col     > row0) S[j][0] = -1e30f;
                if (col + 1 > row0) S[j][1] = -1e30f;
                if (col     > row1) S[j][2] = -1e30f;
                if (col + 1 > row1) S[j][3] = -1e30f;
            }
        }

        float mx0 = -1e30f, mx1 = -1e30f;
        #pragma unroll
        for (int j = 0; j < 16; j++) {
            mx0 = fmaxf(mx0, fmaxf(S[j][0], S[j][1]));
            mx1 = fmaxf(mx1, fmaxf(S[j][2], S[j][3]));
        }
        mx0 = fmaxf(mx0, __shfl_xor_sync(0xffffffffu, mx0, 1));
        mx0 = fmaxf(mx0, __shfl_xor_sync(0xffffffffu, mx0, 2));
        mx1 = fmaxf(mx1, __shfl_xor_sync(0xffffffffu, mx1, 1));
        mx1 = fmaxf(mx1, __shfl_xor_sync(0xffffffffu, mx1, 2));
        float nm0 = fmaxf(mrun0, mx0), nm1 = fmaxf(mrun1, mx1);
        float f0 = expf(mrun0 - nm0), f1 = expf(mrun1 - nm1);
        mrun0 = nm0; mrun1 = nm1;
        float rs0 = 0.f, rs1 = 0.f;
        #pragma unroll
        for (int j = 0; j < 16; j++) {
            S[j][0] = expf(S[j][0] - nm0);
            S[j][1] = expf(S[j][1] - nm0);
            S[j][2] = expf(S[j][2] - nm1);
            S[j][3] = expf(S[j][3] - nm1);
            rs0 += S[j][0] + S[j][1];
            rs1 += S[j][2] + S[j][3];
        }
        rs0 += __shfl_xor_sync(0xffffffffu, rs0, 1);
        rs0 += __shfl_xor_sync(0xffffffffu, rs0, 2);
        rs1 += __shfl_xor_sync(0xffffffffu, rs1, 1);
        rs1 += __shfl_xor_sync(0xffffffffu, rs1, 2);
        lrun0 = lrun0 * f0 + rs0;
        lrun1 = lrun1 * f1 + rs1;
        #pragma unroll
        for (int i = 0; i < 8; i++) {
            O[i][0] *= f0; O[i][1] *= f0;
            O[i][2] *= f1; O[i][3] *= f1;
        }

        #pragma unroll
        for (int c2 = 0; c2 < 2; c2++) {
            const unsigned vst = st + 16384 + (unsigned)c2 * 8192;
            #pragma unroll
            for (int ks = 0; ks < 4; ks++) {
                const int sI = c2*4 + ks;
                const float* e0 = S[2*sI];
                const float* e1 = S[2*sI + 1];
                unsigned ah[4], al[4];
                ah[0] = packh(e0[0], e0[1]);
                ah[1] = packh(e0[2], e0[3]);
                ah[2] = packh(e1[0], e1[1]);
                ah[3] = packh(e1[2], e1[3]);
                al[0] = packh(e0[0] - __half2float(__float2half(e0[0])),
                              e0[1] - __half2float(__float2half(e0[1])));
                al[1] = packh(e0[2] - __half2float(__float2half(e0[2])),
                              e0[3] - __half2float(__float2half(e0[3])));
                al[2] = packh(e1[0] - __half2float(__float2half(e1[0])),
                              e1[1] - __half2float(__float2half(e1[1])));
                al[3] = packh(e1[2] - __half2float(__float2half(e1[2])),
                              e1[3] - __half2float(__float2half(e1[3])));
                #pragma unroll
                for (int jp = 0; jp < 4; jp++) {
                    unsigned o = swz(jp*16 + b_rin, ks*32 + b_cB);
                    unsigned r[4];
                    ldmx4(r, vst + o);
                    unsigned b0[2] = {r[0], r[1]}, b1[2] = {r[2], r[3]};
                    mma16816h(O[2*jp],   ah, b0);
                    mma16816h(O[2*jp],   al, b0);
                    mma16816h(O[2*jp+1], ah, b1);
                    mma16816h(O[2*jp+1], al, b1);
                }
            }
        }
        __syncthreads();
    }

    float inv0 = 1.f / lrun0, inv1 = 1.f / lrun1;
    float* y0 = YH + ((size_t)bh * TLEN + m0 + wid*16 + g) * HD;
    float* y1 = y0 + 8 * HD;
    #pragma unroll
    for (int i = 0; i < 8; i++) {
        int d = i*8 + tig*2;
        y0[d]     = O[i][0] * inv0;
        y0[d + 1] = O[i][1] * inv0;
        y1[d]     = O[i][2] * inv1;
        y1[d + 1] = O[i][3] * inv1;
    }
}

// ======================== small kernels ======================================
__global__ void detect_idx_kernel(const unsigned int* w) {
    __shared__ unsigned int s;
    if (threadIdx.x == 0) s = 0u;
    __syncthreads();
    unsigned int v = 0u;
    for (int i = threadIdx.x; i < 1024; i += blockDim.x) v |= w[2*i + 1];
    atomicOr(&s, v);
    __syncthreads();
    if (threadIdx.x == 0) g_idx32 = (s != 0u) ? 1 : 0;
}

__global__ void embed_kernel(const void* idx, const float* __restrict__ wte,
                             const float* __restrict__ wpe, float* __restrict__ x) {
    int i = blockIdx.x * blockDim.x + threadIdx.x;
    if (i >= MTOK*CDIM) return;
    int c  = i % CDIM;
    int bt = i / CDIM;
    int t  = bt % TLEN;
    long long tok;
    if (g_idx32) tok = (long long)((const int*)idx)[bt];
    else         tok = ((const long long*)idx)[bt];
    x[i] = wte[tok*CDIM + c] + wpe[(long long)t*CDIM + c];
}

__global__ void ln_lora_kernel(const float* __restrict__ x, const float* __restrict__ g,
                               const float* __restrict__ b,
                               const float* __restrict__ lA,
                               __half* __restrict__ oh, __half* __restrict__ ol,
                               float* __restrict__ tmp) {
    const int row = blockIdx.x;
    const float* xr = x + (long long)row * CDIM;
    __shared__ float sx[CDIM];
    __shared__ float red[128];
    __shared__ float s_mean, s_rstd;
    int tid = threadIdx.x;
    float s = 0.f;
    for (int c = tid; c < CDIM; c += 128) { float v = xr[c]; sx[c] = v; s += v; }
    red[tid] = s; __syncthreads();
    for (int st = 64; st > 0; st >>= 1) { if (tid < st) red[tid] += red[tid+st]; __syncthreads(); }
    if (tid == 0) s_mean = red[0] / (float)CDIM;
    __syncthreads();
    float mean = s_mean;
    float sq = 0.f;
    for (int c = tid; c < CDIM; c += 128) { float d = sx[c] - mean; sq += d*d; }
    red[tid] = sq; __syncthreads();
    for (int st = 64; st > 0; st >>= 1) { if (tid < st) red[tid] += red[tid+st]; __syncthreads(); }
    if (tid == 0) s_rstd = rsqrtf(red[0] / (float)CDIM + 1e-5f);
    __syncthreads();
    float mean2 = s_mean, rstd = s_rstd;
    for (int c = tid; c < CDIM; c += 128) {
        float v = (sx[c] - mean2) * rstd * g[c] + b[c];
        long long o = (long long)row*CDIM + c;
        __half hi, lo; hsplit(v, hi, lo);
        oh[o] = hi; ol[o] = lo;
        sx[c] = v;
    }
    __syncthreads();
    if (lA) {
        int w = tid >> 5, lane = tid & 31;
        #pragma unroll
        for (int rr = 0; rr < 2; ++rr) {
            int r = w*2 + rr;
            const float* Ar = lA + (long long)r * CDIM;
            float acc = 0.f;
            for (int c = lane; c < CDIM; c += 32) acc += sx[c] * Ar[c];
            #pragma unroll
            for (int off = 16; off > 0; off >>= 1) acc += __shfl_down_sync(0xffffffffu, acc, off);
            if (lane == 0) tmp[row*RANK + r] = acc;
        }
    }
}

__global__ void ln_f16_kernel(const float* __restrict__ x, const float* __restrict__ g,
                              const float* __restrict__ b, __half* __restrict__ oh) {
    const int row = blockIdx.x;
    const float* xr = x + (long long)row * CDIM;
    __shared__ float sx[CDIM];
    __shared__ float red[128];
    __shared__ float s_mean, s_rstd;
    int tid = threadIdx.x;
    float s = 0.f;
    for (int c = tid; c < CDIM; c += 128) { float v = xr[c]; sx[c] = v; s += v; }
    red[tid] = s; __syncthreads();
    for (int st = 64; st > 0; st >>= 1) { if (tid < st) red[tid] += red[tid+st]; __syncthreads(); }
    if (tid == 0) s_mean = red[0] / (float)CDIM;
    __syncthreads();
    float mean = s_mean;
    float sq = 0.f;
    for (int c = tid; c < CDIM; c += 128) { float d = sx[c] - mean; sq += d*d; }
    red[tid] = sq; __syncthreads();
    for (int st = 64; st > 0; st >>= 1) { if (tid < st) red[tid] += red[tid+st]; __syncthreads(); }
    if (tid == 0) s_rstd = rsqrtf(red[0] / (float)CDIM + 1e-5f);
    __syncthreads();
    float mean2 = s_mean, rstd = s_rstd;
    for (int c = tid; c < CDIM; c += 128) {
        float v = (sx[c] - mean2) * rstd * g[c] + b[c];
        oh[(long long)row*CDIM + c] = __float2half(v);
    }
}

__global__ void wcvt16_kernel(const float* __restrict__ wq, const float* __restrict__ wp,
                              const float* __restrict__ wf, const float* __restrict__ wm,
                              __half* __restrict__ q16, __half* __restrict__ p16,
                              __half* __restrict__ f16, __half* __restrict__ m16) {
    const int NQ = NLAYER*3*CDIM*CDIM, NP = NLAYER*CDIM*CDIM,
              NF = NLAYER*4*CDIM*CDIM, NM = NLAYER*CDIM*4*CDIM;
    int i4 = (blockIdx.x * 256 + threadIdx.x) * 4;
    const float* src; __half* dst; int k;
    if (i4 < NQ)                { src = wq; dst = q16; k = i4; }
    else if (i4 < NQ+NP)        { src = wp; dst = p16; k = i4 - NQ; }
    else if (i4 < NQ+NP+NF)     { src = wf; dst = f16; k = i4 - NQ - NP; }
    else if (i4 < NQ+NP+NF+NM)  { src = wm; dst = m16; k = i4 - NQ - NP - NF; }
    else return;
    float4 v = *reinterpret_cast<const float4*>(src + k);
    __half2 a = __floats2half2_rn(v.x, v.y);
    __half2 b = __floats2half2_rn(v.z, v.w);
    uint2 o;
    o.x = reinterpret_cast<unsigned&>(a);
    o.y = reinterpret_cast<unsigned&>(b);
    *reinterpret_cast<uint2*>(dst + k) = o;
}

__global__ void wsplit_f16_kernel(const float* __restrict__ w, __half* __restrict__ h, int n) {
    int i4 = (blockIdx.x * 256 + threadIdx.x) * 4;
    if (i4 >= n) return;
    float4 v = *reinterpret_cast<const float4*>(w + i4);
    __half2 a = __floats2half2_rn(v.x, v.y);
    __half2 b = __floats2half2_rn(v.z, v.w);
    uint2 o;
    o.x = reinterpret_cast<unsigned&>(a);
    o.y = reinterpret_cast<unsigned&>(b);
    *reinterpret_cast<uint2*>(h + i4) = o;
}

__global__ void merge_lora_kernel(const float* __restrict__ yh,
                                  const float* __restrict__ lA,
                                  __half* __restrict__ oh, __half* __restrict__ ol,
                                  float* __restrict__ tmp) {
    const int row = blockIdx.x;
    const int t = row & (TLEN - 1);
    const int b = row >> 10;
    __shared__ float sy[CDIM];
    int tid = threadIdx.x;
    for (int c = tid; c < CDIM; c += 128) {
        int h = c >> 6, d = c & 63;
        sy[c] = yh[(((long long)(b*NHEAD + h) * TLEN) + t) * HD + d];
    }
    __syncthreads();
    for (int c = tid; c < CDIM; c += 128) {
        long long o = (long long)row*CDIM + c;
        __half hi, lo; hsplit(sy[c], hi, lo);
        oh[o] = hi; ol[o] = lo;
    }
    int w = tid >> 5, lane = tid & 31;
    #pragma unroll
    for (int rr = 0; rr < 2; ++rr) {
        int r = w*2 + rr;
        const float* Ar = lA + (long long)r * CDIM;
        float acc = 0.f;
        for (int c = lane; c < CDIM; c += 32) acc += sy[c] * Ar[c];
        #pragma unroll
        for (int off = 16; off > 0; off >>= 1) acc += __shfl_down_sync(0xffffffffu, acc, off);
        if (lane == 0) tmp[row*RANK + r] = acc;
    }
}

// ======================== host driver ========================================
template<int MODE, int SPLITK>
static void launch_gemm_h(dim3 grid,
                          const __half* Ah, const __half* Al, const __half* Bm,
                          const float* bias, const float* loraT, const float* loraB,
                          float* Cm, int M, int N, int K) {
    cudaFuncSetAttribute(mma_gemm_h<MODE, SPLITK>,
                         cudaFuncAttributeMaxDynamicSharedMemorySize, LGEMM_SMEM);
    mma_gemm_h<MODE, SPLITK><<<grid, 256, LGEMM_SMEM>>>(
        Ah, Al, Bm, bias, loraT, loraB, Cm, M, N, K);
}

extern "C" void kernel_launch(void* const* d_in, const int* in_sizes, int n_in,
                              void* d_out, int out_size) {
    (void)in_sizes; (void)n_in; (void)out_size;
    const void*  idx     = d_in[0];
    const float* wte     = (const float*)d_in[1];
    const float* wpe     = (const float*)d_in[2];
    const float* ln1_g   = (const float*)d_in[3];
    const float* ln1_b   = (const float*)d_in[4];
    const float* attn_w  = (const float*)d_in[5];
    const float* attn_lA = (const float*)d_in[6];
    const float* attn_lB = (const float*)d_in[7];
    const float* proj_w  = (const float*)d_in[8];
    const float* proj_lA = (const float*)d_in[9];
    const float* proj_lB = (const float*)d_in[10];
    const float* ln2_g   = (const float*)d_in[11];
    const float* ln2_b   = (const float*)d_in[12];
    const float* fc_w    = (const float*)d_in[13];
    const float* fc_b    = (const float*)d_in[14];
    const float* mproj_w = (const float*)d_in[15];
    const float* mproj_b = (const float*)d_in[16];
    const float* lnf_g   = (const float*)d_in[17];
    const float* lnf_b   = (const float*)d_in[18];
    const float* head_w  = (const float*)d_in[19];
    float* out = (float*)d_out;

    float *X, *YH, *TMP, *QKVp;
    cudaGetSymbolAddress((void**)&X,    g_X);
    cudaGetSymbolAddress((void**)&YH,   g_YH);
    cudaGetSymbolAddress((void**)&TMP,  g_TMP);
    cudaGetSymbolAddress((void**)&QKVp, g_QKVp);

    __half *wqkv16, *wproj16, *wfc16, *wmp16, *whead16,
           *H16h, *H16l, *Y16h, *Y16l, *FCG16h, *FCG16l,
           *Q16h, *Q16l, *K16, *V16t;
    cudaGetSymbolAddress((void**)&wqkv16,  g_wqkv16);
    cudaGetSymbolAddress((void**)&wproj16, g_wproj16);
    cudaGetSymbolAddress((void**)&wfc16,   g_wfc16);
    cudaGetSymbolAddress((void**)&wmp16,   g_wmp16);
    cudaGetSymbolAddress((void**)&whead16, g_whead16);
    cudaGetSymbolAddress((void**)&H16h, g_H16h); cudaGetSymbolAddress((void**)&H16l, g_H16l);
    cudaGetSymbolAddress((void**)&Y16h, g_Y16h); cudaGetSymbolAddress((void**)&Y16l, g_Y16l);
    cudaGetSymbolAddress((void**)&FCG16h, g_FCG16h); cudaGetSymbolAddress((void**)&FCG16l, g_FCG16l);
    cudaGetSymbolAddress((void**)&Q16h, g_Q16h); cudaGetSymbolAddress((void**)&Q16l, g_Q16l);
    cudaGetSymbolAddress((void**)&K16,  g_K16);  cudaGetSymbolAddress((void**)&V16t, g_V16t);

    cudaFuncSetAttribute(flash_attn, cudaFuncAttributeMaxDynamicSharedMemorySize, FA_SMEM);

    detect_idx_kernel<<<1, 256>>>((const unsigned int*)idx);
    embed_kernel<<<(MTOK*CDIM + 255)/256, 256>>>(idx, wte, wpe, X);
    {
        int nA = NLAYER*(3*CDIM*CDIM + CDIM*CDIM + 4*CDIM*CDIM + 4*CDIM*CDIM);
        wcvt16_kernel<<<(nA/4 + 255)/256, 256>>>(attn_w, proj_w, fc_w, mproj_w,
            wqkv16, wproj16, wfc16, wmp16);
        int nB = VOCAB*CDIM;
        wsplit_f16_kernel<<<(nB/4 + 255)/256, 256>>>(head_w, whead16, nB);
    }

    for (int l = 0; l < NLAYER; l++) {
        long long oq = (long long)l * 3*CDIM*CDIM;
        long long op = (long long)l * CDIM*CDIM;
        long long of = (long long)l * 4*CDIM*CDIM;
        long long om = (long long)l * CDIM*4*CDIM;
        const float* lA_q = attn_lA + (long long)l * RANK*CDIM;
        const float* lB_q = attn_lB + (long long)l * 3*CDIM*RANK;
        const float* lA_p = proj_lA + (long long)l * RANK*CDIM;
        const float* lB_p = proj_lB + (long long)l * CDIM*RANK;

        // ---- attention ----
        ln_lora_kernel<<<MTOK, 128>>>(X, ln1_g + l*CDIM, ln1_b + l*CDIM, lA_q, H16h, H16l, TMP);
        launch_gemm_h<0, 1>(dim3(MTOK/128, 3*CDIM/128, 2),
            H16h, H16l, wqkv16 + oq, nullptr, TMP, lB_q, QKVp,
            MTOK, 3*CDIM, CDIM);
        split_qkv2_kernel<<<(NBATCH*TLEN*HD + 255)/256, 256>>>(QKVp);

        flash_attn<<<dim3(TLEN/128, NBATCH), 256, FA_SMEM>>>(Q16h, Q16l, K16, V16t, YH);
        merge_lora_kernel<<<MTOK, 128>>>(YH, lA_p, Y16h, Y16l, TMP);

        launch_gemm_h<2, 1>(dim3(MTOK/128, CDIM/128, 2),
            Y16h, Y16l, wproj16 + op, nullptr, TMP, lB_p, X,
            MTOK, CDIM, CDIM);

        // ---- MLP ----
        ln_lora_kernel<<<MTOK, 128>>>(X, ln2_g + l*CDIM, ln2_b + l*CDIM, nullptr, H16h, H16l, TMP);
        launch_gemm_h<1, 0>(dim3(MTOK/128, 4*CDIM/128, 1),
            H16h, H16l, wfc16 + of, fc_b + (long long)l*4*CDIM, nullptr, nullptr, nullptr,
            MTOK, 4*CDIM, CDIM);
        launch_gemm_h<2, 1>(dim3(MTOK/128, CDIM/128, 2),
            FCG16h, FCG16l, wmp16 + om, mproj_b + (long long)l*CDIM, nullptr, nullptr, X,
            MTOK, CDIM, 4*CDIM);
    }

    // ---- final layernorm + fp16 1-MMA vocab head ----
    ln_f16_kernel<<<MTOK, 128>>>(X, lnf_g, lnf_b, H16h);
    cudaFuncSetAttribute(mma_gemm_f16, cudaFuncAttributeMaxDynamicSharedMemorySize, GEMM_SMEM_F16);
    mma_gemm_f16<<<dim3(MTOK/128, (VOCAB + 127)/128), 256, GEMM_SMEM_F16>>>(
        H16h, whead16, out, MTOK, VOCAB, CDIM);
}

// round 16
// speedup vs baseline: 1.6182x; 1.0307x over previous
#include <cuda_runtime.h>
#include <cuda_bf16.h>
#include <cuda_fp16.h>
#include <math.h>

// ---------------------------------------------------------------------------
// GPT_3959959847300 round 16: R15 + pure-fp16 flash attention (Q, K, V, P all
// single fp16 -> 1 MMA per tile). Layer GEMMs / head unchanged.
// ---------------------------------------------------------------------------

#define BSZ    2
#define TLEN   1024
#define CDIM   512
#define NHEAD  8
#define HD     64
#define NLAYER 4
#define VOCAB  50257
#define RANK   8
#define LSCALE 4.0f
#define MTOK   (BSZ*TLEN)
#define NBATCH (BSZ*NHEAD)

// ======================== PTX helpers ========================================
__device__ __forceinline__ unsigned smem_u32(const void* p) {
    unsigned a;
    asm("{ .reg .u64 t; cvta.to.shared.u64 t, %1; cvt.u32.u64 %0, t; }" : "=r"(a) : "l"(p));
    return a;
}
__device__ __forceinline__ void ldmx4(unsigned* r, unsigned addr) {
    asm volatile("ldmatrix.sync.aligned.m8n8.x4.shared.b16 {%0,%1,%2,%3}, [%4];"
                 : "=r"(r[0]), "=r"(r[1]), "=r"(r[2]), "=r"(r[3]) : "r"(addr));
}
__device__ __forceinline__ void mma16816h(float* d, const unsigned* a, const unsigned* b) {
    asm volatile(
        "mma.sync.aligned.m16n8k16.row.col.f32.f16.f16.f32 "
        "{%0,%1,%2,%3},{%4,%5,%6,%7},{%8,%9},{%0,%1,%2,%3};"
        : "+f"(d[0]), "+f"(d[1]), "+f"(d[2]), "+f"(d[3])
        : "r"(a[0]), "r"(a[1]), "r"(a[2]), "r"(a[3]), "r"(b[0]), "r"(b[1]));
}
__device__ __forceinline__ void cp16(unsigned dst, const void* src, bool pred) {
    int sz = pred ? 16 : 0;
    asm volatile("cp.async.cg.shared.global [%0], [%1], 16, %2;"
                 :: "r"(dst), "l"(src), "r"(sz) : "memory");
}
#define CP_COMMIT()  asm volatile("cp.async.commit_group;" ::: "memory")
#define CP_WAIT_1()  asm volatile("cp.async.wait_group 1;" ::: "memory")
#define CP_WAIT_0()  asm volatile("cp.async.wait_group 0;" ::: "memory")

__device__ __forceinline__ void hsplit(float x, __half& hi, __half& lo) {
    hi = __float2half(x);
    lo = __float2half(x - __half2float(hi));
}
__device__ __forceinline__ unsigned packh(float a, float b) {
    __half2 t = __floats2half2_rn(a, b);
    return reinterpret_cast<unsigned&>(t);
}

// ======================== scratch ============================================
__device__ float g_X  [MTOK*CDIM];
__device__ float g_YH [NBATCH*TLEN*HD];
__device__ float g_TMP[MTOK*RANK];
__device__ float g_QKVp[2ll*MTOK*3*CDIM];
__device__ int   g_idx32;

__device__ __half g_wqkv16[NLAYER*3*CDIM*CDIM];
__device__ __half g_wproj16[NLAYER*CDIM*CDIM];
__device__ __half g_wfc16 [NLAYER*4*CDIM*CDIM];
__device__ __half g_wmp16 [NLAYER*CDIM*4*CDIM];
__device__ __half g_whead16[VOCAB*CDIM];
__device__ __half g_H16h[MTOK*CDIM],  g_H16l[MTOK*CDIM];
__device__ __half g_Y16h[MTOK*CDIM],  g_Y16l[MTOK*CDIM];
__device__ __half g_FCG16h[MTOK*4*CDIM], g_FCG16l[MTOK*4*CDIM];
__device__ __half g_Q16[NBATCH*TLEN*HD];
__device__ __half g_K16[NBATCH*TLEN*HD];
__device__ __half g_V16t[NBATCH*HD*TLEN];

// ======================== common tile helpers ================================
#define TILE_B    16384                 // 128x64 16-bit tile (128B rows, swizzled)
#define LSTAGE_B  (3*TILE_B)            // layer GEMM: Ah, Al, B
#define LGEMM_SMEM (2*LSTAGE_B)         // 98304
#define STAGE2_B  (2*TILE_B)            // fp16 head: A, B
#define GEMM_SMEM_F16 (2*STAGE2_B)      // 65536

__device__ __forceinline__ unsigned swz(int row, int colB) {
    unsigned o = (unsigned)(row * 128 + colB);
    return o ^ ((unsigned)(row & 7) << 4);
}

// ======================== fp16 2-term layer GEMM =============================
// MODE: 0 fp32 partial store (per-z buffers, +bias/lora on z==0)
//       1 gelu->fp16 hi/lo split; 2 residual += (atomicAdd if SPLITK)
template<int MODE, int SPLITK>
__global__ __launch_bounds__(256, 1)
void mma_gemm_h(const __half* __restrict__ Ah, const __half* __restrict__ Al,
                const __half* __restrict__ Bm,
                const float* __restrict__ bias,
                const float* __restrict__ loraT, const float* __restrict__ loraB,
                float* __restrict__ Cm,
                int M, int N, int K)
{
    extern __shared__ char smem_raw[];
    const int m0 = blockIdx.x * 128;
    const int n0 = blockIdx.y * 128;
    const int kz = SPLITK ? (int)blockIdx.z : 0;
    const int kslice = SPLITK ? (K >> 1) : K;
    const int koff = kz * kslice;

    const unsigned sbase = smem_u32(smem_raw);
    const int tid  = threadIdx.x;
    const int lane = tid & 31;
    const int wid  = tid >> 5;
    const int wm   = wid & 1;
    const int wn   = wid >> 1;
    const int lr   = tid >> 1;
    const int lcB  = (tid & 1) << 6;

    float acc[4][4][4];
    #pragma unroll
    for (int i = 0; i < 4; i++)
        #pragma unroll
        for (int j = 0; j < 4; j++)
            #pragma unroll
            for (int t = 0; t < 4; t++) acc[i][j][t] = 0.f;

    const int nc = kslice >> 6;

    auto stage3 = [&](unsigned sb, int k0) {
        {
            const char* pa = (const char*)(Ah + (size_t)(m0 + lr) * K + k0) + lcB;
            const char* pl = (const char*)(Al + (size_t)(m0 + lr) * K + k0) + lcB;
            #pragma unroll
            for (int j = 0; j < 4; j++) {
                unsigned o = swz(lr, lcB + 16*j);
                cp16(sb + o,          pa + 16*j, true);
                cp16(sb + TILE_B + o, pl + 16*j, true);
            }
        }
        {
            const char* pb = (const char*)(Bm + (size_t)(n0 + lr) * K + k0) + lcB;
            #pragma unroll
            for (int j = 0; j < 4; j++) {
                unsigned o = swz(lr, lcB + 16*j);
                cp16(sb + 2*TILE_B + o, pb + 16*j, true);
            }
        }
    };

    stage3(sbase, koff);
    CP_COMMIT();

    const int a_rin  = lane & 15;
    const int a_cB   = (lane >> 4) * 16;
    const int b_sel  = lane >> 3;
    const int b_rin  = (b_sel >> 1) * 8 + (lane & 7);
    const int b_cB   = (b_sel & 1) * 16;

    for (int cI = 0; cI < nc; ++cI) {
        const int s = cI & 1;
        if (cI + 1 < nc) {
            stage3(sbase + (unsigned)(1 - s) * LSTAGE_B, koff + ((cI + 1) << 6));
            CP_COMMIT();
            CP_WAIT_1();
        } else {
            CP_WAIT_0();
        }
        __syncthreads();

        const unsigned st = sbase + (unsigned)s * LSTAGE_B;
        #pragma unroll
        for (int ks = 0; ks < 4; ++ks) {
            unsigned ra_h[4][4], ra_l[4][4], rb[4][2];
            #pragma unroll
            for (int i = 0; i < 4; ++i) {
                int row = wm*64 + i*16 + a_rin;
                unsigned o = swz(row, ks*32 + a_cB);
                ldmx4(ra_h[i], st + o);
                ldmx4(ra_l[i], st + TILE_B + o);
            }
            #pragma unroll
            for (int jp = 0; jp < 2; ++jp) {
                int row = wn*32 + jp*16 + b_rin;
                unsigned o = swz(row, ks*32 + b_cB);
                unsigned r[4];
                ldmx4(r, st + 2*TILE_B + o);
                rb[2*jp][0] = r[0]; rb[2*jp][1] = r[1];
                rb[2*jp+1][0] = r[2]; rb[2*jp+1][1] = r[3];
            }
            #pragma unroll
            for (int i = 0; i < 4; ++i)
                #pragma unroll
                for (int j = 0; j < 4; ++j) {
                    mma16816h(acc[i][j], ra_h[i], rb[j]);
                    mma16816h(acc[i][j], ra_l[i], rb[j]);
                }
        }
        __syncthreads();
    }

    const int group = lane >> 2, tig = lane & 3;
    float* cbuf = (MODE == 0) ? (Cm + (size_t)kz * M * N) : Cm;
    #pragma unroll
    for (int i = 0; i < 4; ++i) {
        int m_lo = m0 + wm*64 + i*16 + group;
        #pragma unroll
        for (int j = 0; j < 4; ++j) {
            int nA = n0 + wn*32 + j*8 + tig*2;
            #pragma unroll
            for (int h = 0; h < 2; ++h) {
                int m = m_lo + h*8;
                #pragma unroll
                for (int e = 0; e < 2; ++e) {
                    int n = nA + e;
                    float v = acc[i][j][h*2 + e];
                    if (bias && kz == 0)  v += bias[n];
                    if (loraT && kz == 0) {
                        const float* t  = loraT + (size_t)m * RANK;
                        const float* bb = loraB + (size_t)n * RANK;
                        float s = 0.f;
                        #pragma unroll
                        for (int r = 0; r < RANK; r++) s += t[r] * bb[r];
                        v += LSCALE * s;
                    }
                    if (MODE == 0) {
                        cbuf[(long long)m * N + n] = v;
                    } else if (MODE == 2) {
                        if (SPLITK) atomicAdd(&Cm[(long long)m * N + n], v);
                        else        Cm[(long long)m * N + n] += v;
                    } else {
                        float gv = 0.5f * v * (1.f + tanhf(0.7978845608028654f * (v + 0.044715f * v*v*v)));
                        __half hi, lo; hsplit(gv, hi, lo);
                        g_FCG16h[(long long)m * N + n] = hi;
                        g_FCG16l[(long long)m * N + n] = lo;
                    }
                }
            }
        }
    }
}

// combine qkv split-K partials -> Q fp16 (bhtd), K fp16 (bhtd), V^T fp16
__global__ void split_qkv2_kernel(const float* __restrict__ qkvp) {
    int i = blockIdx.x * 256 + threadIdx.x;
    if (i >= NBATCH*TLEN*HD) return;
    int d = i % HD;
    int t = (i / HD) % TLEN;
    int h = (i / (HD*TLEN)) % NHEAD;
    int b = i / (HD*TLEN*NHEAD);
    long long src = (long long)(b*TLEN + t) * (3*CDIM) + h*HD + d;
    const long long off = (long long)MTOK * 3*CDIM;
    float q = qkvp[src] + qkvp[src + off];
    float k = qkvp[src + CDIM] + qkvp[src + CDIM + off];
    float v = qkvp[src + 2*CDIM] + qkvp[src + 2*CDIM + off];
    g_Q16[i] = __float2half(q);
    g_K16[i] = __float2half(k);
    long long vi = ((long long)(b*NHEAD + h) * HD + d) * TLEN + t;
    g_V16t[vi] = __float2half(v);
}

// ======================== fp16 1-MMA head GEMM (128x128, occ=2) ==============
__global__ __launch_bounds__(256, 2)
void mma_gemm_f16(const __half* __restrict__ Am, const __half* __restrict__ Bm,
                  float* __restrict__ Cm, int M, int N, int K)
{
    extern __shared__ char smem_raw[];
    const int m0 = blockIdx.x * 128;
    const int n0 = blockIdx.y * 128;

    const unsigned sbase = smem_u32(smem_raw);
    const int tid  = threadIdx.x;
    const int lane = tid & 31;
    const int wid  = tid >> 5;
    const int wm   = wid & 1;
    const int wn   = wid >> 1;
    const int lr   = tid >> 1;
    const int lcB  = (tid & 1) << 6;

    float acc[4][4][4];
    #pragma unroll
    for (int i = 0; i < 4; i++)
        #pragma unroll
        for (int j = 0; j < 4; j++)
            #pragma unroll
            for (int t = 0; t < 4; t++) acc[i][j][t] = 0.f;

    const int nc = K >> 6;

    auto stage2 = [&](unsigned sb, int k0) {
        {
            int gr = m0 + lr; bool ok = (gr < M); int r = ok ? gr : 0;
            const char* pa = (const char*)(Am + (size_t)r * K + k0) + lcB;
            #pragma unroll
            for (int j = 0; j < 4; j++) {
                unsigned o = swz(lr, lcB + 16*j);
                cp16(sb + o, pa + 16*j, ok);
            }
        }
        {
            int gr = n0 + lr; bool ok = (gr < N); int r = ok ? gr : 0;
            const char* pb = (const char*)(Bm + (size_t)r * K + k0) + lcB;
            #pragma unroll
            for (int j = 0; j < 4; j++) {
                unsigned o = swz(lr, lcB + 16*j);
                cp16(sb + TILE_B + o, pb + 16*j, ok);
            }
        }
    };

    stage2(sbase, 0);
    CP_COMMIT();

    const int a_rin  = lane & 15;
    const int a_cB   = (lane >> 4) * 16;
    const int b_sel  = lane >> 3;
    const int b_rin  = (b_sel >> 1) * 8 + (lane & 7);
    const int b_cB   = (b_sel & 1) * 16;

    for (int cI = 0; cI < nc; ++cI) {
        const int s = cI & 1;
        if (cI + 1 < nc) {
            stage2(sbase + (unsigned)(1 - s) * STAGE2_B, (cI + 1) << 6);
            CP_COMMIT();
            CP_WAIT_1();
        } else {
            CP_WAIT_0();
        }
        __syncthreads();

        const unsigned st = sbase + (unsigned)s * STAGE2_B;
        #pragma unroll
        for (int ks = 0; ks < 4; ++ks) {
            unsigned ra[4][4], rb[4][2];
            #pragma unroll
            for (int i = 0; i < 4; ++i) {
                int row = wm*64 + i*16 + a_rin;
                unsigned o = swz(row, ks*32 + a_cB);
                ldmx4(ra[i], st + o);
            }
            #pragma unroll
            for (int jp = 0; jp < 2; ++jp) {
                int row = wn*32 + jp*16 + b_rin;
                unsigned o = swz(row, ks*32 + b_cB);
                unsigned r[4];
                ldmx4(r, st + TILE_B + o);
                rb[2*jp][0] = r[0]; rb[2*jp][1] = r[1];
                rb[2*jp+1][0] = r[2]; rb[2*jp+1][1] = r[3];
            }
            #pragma unroll
            for (int i = 0; i < 4; ++i)
                #pragma unroll
                for (int j = 0; j < 4; ++j)
                    mma16816h(acc[i][j], ra[i], rb[j]);
        }
        __syncthreads();
    }

    const int group = lane >> 2, tig = lane & 3;
    #pragma unroll
    for (int i = 0; i < 4; ++i) {
        int m_lo = m0 + wm*64 + i*16 + group;
        #pragma unroll
        for (int j = 0; j < 4; ++j) {
            int nA = n0 + wn*32 + j*8 + tig*2;
            #pragma unroll
            for (int h = 0; h < 2; ++h) {
                int m = m_lo + h*8;
                if (m >= M) continue;
                float* crow = Cm + (long long)m * N;
                #pragma unroll
                for (int e = 0; e < 2; ++e) {
                    int n = nA + e;
                    if (n < N) crow[n] = acc[i][j][h*2 + e];
                }
            }
        }
    }
}

// ======================== fused flash attention (pure fp16) ==================
#define FA_QTILE 16384
#define FA_STAGE 32768          // K 16K | V 16K (2x8K)
#define FA_SMEM  (FA_QTILE + 2*FA_STAGE)   // 81920

__global__ __launch_bounds__(256, 1)
void flash_attn(const __half* __restrict__ Qm, const __half* __restrict__ Km,
                const __half* __restrict__ Vt, float* __restrict__ YH)
{
    extern __shared__ char smem_raw[];
    const unsigned sbase = smem_u32(smem_raw);
    const int m0 = blockIdx.x * 128;
    const int bh = blockIdx.y;
    const int tid = threadIdx.x;
    const int lane = tid & 31;
    const int wid = tid >> 5;

    const __half* qm = Qm + (size_t)bh * TLEN * HD;
    const __half* km = Km + (size_t)bh * TLEN * HD;
    const __half* vt = Vt + (size_t)bh * HD * TLEN;

    const unsigned sQ = sbase;
    const unsigned sStage = sbase + FA_QTILE;

    {
        int lr = tid >> 1, lcB = (tid & 1) << 6;
        const char* pq = (const char*)(qm + (size_t)(m0 + lr) * HD) + lcB;
        #pragma unroll
        for (int j = 0; j < 4; j++) {
            unsigned o = swz(lr, lcB + 16*j);
            cp16(sQ + o, pq + 16*j, true);
        }
    }
    CP_COMMIT();

    const int nkb = blockIdx.x + 1;

    auto load_stage = [&](int kb, int s) {
        unsigned st = sStage + (unsigned)s * FA_STAGE;
        int lr = tid >> 1, lcB = (tid & 1) << 6;
        const char* pk = (const char*)(km + (size_t)(kb*128 + lr) * HD) + lcB;
        #pragma unroll
        for (int j = 0; j < 4; j++) {
            unsigned o = swz(lr, lcB + 16*j);
            cp16(st + o, pk + 16*j, true);
        }
        int vr = tid >> 2, vc = (tid & 3) << 5;
        #pragma unroll
        for (int c = 0; c < 2; c++) {
            const char* pv = (const char*)(vt + (size_t)vr * TLEN + kb*128 + c*64) + vc;
            unsigned vb = st + 16384 + (unsigned)c * 8192;
            #pragma unroll
            for (int j = 0; j < 2; j++) {
                unsigned o = swz(vr, vc + 16*j);
                cp16(vb + o, pv + 16*j, true);
            }
        }
    };

    load_stage(0, 0);
    CP_COMMIT();
    CP_WAIT_1();
    __syncthreads();

    unsigned qf[4][4];
    const int a_rin = lane & 15, a_cB = (lane >> 4) * 16;
    #pragma unroll
    for (int ks = 0; ks < 4; ks++) {
        unsigned o = swz(wid*16 + a_rin, ks*32 + a_cB);
        ldmx4(qf[ks], sQ + o);
    }

    float O[8][4];
    #pragma unroll
    for (int i = 0; i < 8; i++)
        #pragma unroll
        for (int t = 0; t < 4; t++) O[i][t] = 0.f;
    float mrun0 = -1e30f, mrun1 = -1e30f, lrun0 = 0.f, lrun1 = 0.f;

    const int b_sel = lane >> 3;
    const int b_rin = (b_sel >> 1)*8 + (lane & 7);
    const int b_cB  = (b_sel & 1)*16;
    const int g = lane >> 2, tig = lane & 3;

    for (int kb = 0; kb < nkb; kb++) {
        if (kb + 1 < nkb) { load_stage(kb + 1, (kb + 1) & 1); CP_COMMIT(); CP_WAIT_1(); }
        else CP_WAIT_0();
        __syncthreads();
        const unsigned st = sStage + (unsigned)(kb & 1) * FA_STAGE;

        float S[16][4];
        #pragma unroll
        for (int j = 0; j < 16; j++)
            #pragma unroll
            for (int t = 0; t < 4; t++) S[j][t] = 0.f;

        #pragma unroll
        for (int ks = 0; ks < 4; ks++) {
            #pragma unroll
            for (int jp = 0; jp < 8; jp++) {
                unsigned o = swz(jp*16 + b_rin, ks*32 + b_cB);
                unsigned r[4];
                ldmx4(r, st + o);
                unsigned b0[2] = {r[0], r[1]}, b1[2] = {r[2], r[3]};
                mma16816h(S[2*jp],   qf[ks], b0);
                mma16816h(S[2*jp+1], qf[ks], b1);
            }
        }
        #pragma unroll
        for (int j = 0; j < 16; j++)
            #pragma unroll
            for (int t = 0; t < 4; t++) S[j][t] *= 0.125f;

        if (kb == nkb - 1) {
            int row0 = m0 + wid*16 + g;
            int row1 = row0 + 8;
            #pragma unroll
            for (int j = 0; j < 16; j++) {
                int col = kb*128 + j*8 + tig*2;
                if (col     > row0) S[j][0] = -1e30f;
                if (col + 1 > row0) S[j][1] = -1e30f;
                if (col     > row1) S[j][2] = -1e30f;
                if (col + 1 > row1) S[j][3] = -1e30f;
            }
        }

        float mx0 = -1e30f, mx1 = -1e30f;
        #pragma unroll
        for (int j = 0; j < 16; j++) {
            mx0 = fmaxf(mx0, fmaxf(S[j][0], S[j][1]));
            mx1 = fmaxf(mx1, fmaxf(S[j][2], S[j][3]));
        }
        mx0 = fmaxf(mx0, __shfl_xor_sync(0xffffffffu, mx0, 1));
        mx0 = fmaxf(mx0, __shfl_xor_sync(0xffffffffu, mx0, 2));
        mx1 = fmaxf(mx1, __shfl_xor_sync(0xffffffffu, mx1, 1));
        mx1 = fmaxf(mx1, __shfl_xor_sync(0xffffffffu, mx1, 2));
        float nm0 = fmaxf(mrun0, mx0), nm1 = fmaxf(mrun1, mx1);
        float f0 = expf(mrun0 - nm0), f1 = expf(mrun1 - nm1);
        mrun0 = nm0; mrun1 = nm1;
        float rs0 = 0.f, rs1 = 0.f;
        #pragma unroll
        for (int j = 0; j < 16; j++) {
            S[j][0] = expf(S[j][0] - nm0);
            S[j][1] = expf(S[j][1] - nm0);
            S[j][2] = expf(S[j][2] - nm1);
            S[j][3] = expf(S[j][3] - nm1);
            rs0 += S[j][0] + S[j][1];
            rs1 += S[j][2] + S[j][3];
        }
        rs0 += __shfl_xor_sync(0xffffffffu, rs0, 1);
        rs0 += __shfl_xor_sync(0xffffffffu, rs0, 2);
        rs1 += __shfl_xor_sync(0xffffffffu, rs1, 1);
        rs1 += __shfl_xor_sync(0xffffffffu, rs1, 2);
        lrun0 = lrun0 * f0 + rs0;
        lrun1 = lrun1 * f1 + rs1;
        #pragma unroll
        for (int i = 0; i < 8; i++) {
            O[i][0] *= f0; O[i][1] *= f0;
            O[i][2] *= f1; O[i][3] *= f1;
        }

        #pragma unroll
        for (int c2 = 0; c2 < 2; c2++) {
            const unsigned vst = st + 16384 + (unsigned)c2 * 8192;
            #pragma unroll
            for (int ks = 0; ks < 4; ks++) {
                const int sI = c2*4 + ks;
                const float* e0 = S[2*sI];
                const float* e1 = S[2*sI + 1];
                unsigned ap[4];
                ap[0] = packh(e0[0], e0[1]);
                ap[1] = packh(e0[2], e0[3]);
                ap[2] = packh(e1[0], e1[1]);
                ap[3] = packh(e1[2], e1[3]);
                #pragma unroll
                for (int jp = 0; jp < 4; jp++) {
                    unsigned o = swz(jp*16 + b_rin, ks*32 + b_cB);
                    unsigned r[4];
                    ldmx4(r, vst + o);
                    unsigned b0[2] = {r[0], r[1]}, b1[2] = {r[2], r[3]};
                    mma16816h(O[2*jp],   ap, b0);
                    mma16816h(O[2*jp+1], ap, b1);
                }
            }
        }
        __syncthreads();
    }

    float inv0 = 1.f / lrun0, inv1 = 1.f / lrun1;
    float* y0 = YH + ((size_t)bh * TLEN + m0 + wid*16 + g) * HD;
    float* y1 = y0 + 8 * HD;
    #pragma unroll
    for (int i = 0; i < 8; i++) {
        int d = i*8 + tig*2;
        y0[d]     = O[i][0] * inv0;
        y0[d + 1] = O[i][1] * inv0;
        y1[d]     = O[i][2] * inv1;
        y1[d + 1] = O[i][3] * inv1;
    }
}

// ======================== small kernels ======================================
__global__ void detect_idx_kernel(const unsigned int* w) {
    __shared__ unsigned int s;
    if (threadIdx.x == 0) s = 0u;
    __syncthreads();
    unsigned int v = 0u;
    for (int i = threadIdx.x; i < 1024; i += blockDim.x) v |= w[2*i + 1];
    atomicOr(&s, v);
    __syncthreads();
    if (threadIdx.x == 0) g_idx32 = (s != 0u) ? 1 : 0;
}

__global__ void embed_kernel(const void* idx, const float* __restrict__ wte,
                             const float* __restrict__ wpe, float* __restrict__ x) {
    int i = blockIdx.x * blockDim.x + threadIdx.x;
    if (i >= MTOK*CDIM) return;
    int c  = i % CDIM;
    int bt = i / CDIM;
    int t  = bt % TLEN;
    long long tok;
    if (g_idx32) tok = (long long)((const int*)idx)[bt];
    else         tok = ((const long long*)idx)[bt];
    x[i] = wte[tok*CDIM + c] + wpe[(long long)t*CDIM + c];
}

__global__ void ln_lora_kernel(const float* __restrict__ x, const float* __restrict__ g,
                               const float* __restrict__ b,
                               const float* __restrict__ lA,
                               __half* __restrict__ oh, __half* __restrict__ ol,
                               float* __restrict__ tmp) {
    const int row = blockIdx.x;
    const float* xr = x + (long long)row * CDIM;
    __shared__ float sx[CDIM];
    __shared__ float red[128];
    __shared__ float s_mean, s_rstd;
    int tid = threadIdx.x;
    float s = 0.f;
    for (int c = tid; c < CDIM; c += 128) { float v = xr[c]; sx[c] = v; s += v; }
    red[tid] = s; __syncthreads();
    for (int st = 64; st > 0; st >>= 1) { if (tid < st) red[tid] += red[tid+st]; __syncthreads(); }
    if (tid == 0) s_mean = red[0] / (float)CDIM;
    __syncthreads();
    float mean = s_mean;
    float sq = 0.f;
    for (int c = tid; c < CDIM; c += 128) { float d = sx[c] - mean; sq += d*d; }
    red[tid] = sq; __syncthreads();
    for (int st = 64; st > 0; st >>= 1) { if (tid < st) red[tid] += red[tid+st]; __syncthreads(); }
    if (tid == 0) s_rstd = rsqrtf(red[0] / (float)CDIM + 1e-5f);
    __syncthreads();
    float mean2 = s_mean, rstd = s_rstd;
    for (int c = tid; c < CDIM; c += 128) {
        float v = (sx[c] - mean2) * rstd * g[c] + b[c];
        long long o = (long long)row*CDIM + c;
        __half hi, lo; hsplit(v, hi, lo);
        oh[o] = hi; ol[o] = lo;
        sx[c] = v;
    }
    __syncthreads();
    if (lA) {
        int w = tid >> 5, lane = tid & 31;
        #pragma unroll
        for (int rr = 0; rr < 2; ++rr) {
            int r = w*2 + rr;
            const float* Ar = lA + (long long)r * CDIM;
            float acc = 0.f;
            for (int c = lane; c < CDIM; c += 32) acc += sx[c] * Ar[c];
            #pragma unroll
            for (int off = 16; off > 0; off >>= 1) acc += __shfl_down_sync(0xffffffffu, acc, off);
            if (lane == 0) tmp[row*RANK + r] = acc;
        }
    }
}

__global__ void ln_f16_kernel(const float* __restrict__ x, const float* __restrict__ g,
                              const float* __restrict__ b, __half* __restrict__ oh) {
    const int row = blockIdx.x;
    const float* xr = x + (long long)row * CDIM;
    __shared__ float sx[CDIM];
    __shared__ float red[128];
    __shared__ float s_mean, s_rstd;
    int tid = threadIdx.x;
    float s = 0.f;
    for (int c = tid; c < CDIM; c += 128) { float v = xr[c]; sx[c] = v; s += v; }
    red[tid] = s; __syncthreads();
    for (int st = 64; st > 0; st >>= 1) { if (tid < st) red[tid] += red[tid+st]; __syncthreads(); }
    if (tid == 0) s_mean = red[0] / (float)CDIM;
    __syncthreads();
    float mean = s_mean;
    float sq = 0.f;
    for (int c = tid; c < CDIM; c += 128) { float d = sx[c] - mean; sq += d*d; }
    red[tid] = sq; __syncthreads();
    for (int st = 64; st > 0; st >>= 1) { if (tid < st) red[tid] += red[tid+st]; __syncthreads(); }
    if (tid == 0) s_rstd = rsqrtf(red[0] / (float)CDIM + 1e-5f);
    __syncthreads();
    float mean2 = s_mean, rstd = s_rstd;
    for (int c = tid; c < CDIM; c += 128) {
        float v = (sx[c] - mean2) * rstd * g[c] + b[c];
        oh[(long long)row*CDIM + c] = __float2half(v);
    }
}

__global__ void wcvt16_kernel(const float* __restrict__ wq, const float* __restrict__ wp,
                              const float* __restrict__ wf, const float* __restrict__ wm,
                              __half* __restrict__ q16, __half* __restrict__ p16,
                              __half* __restrict__ f16, __half* __restrict__ m16) {
    const int NQ = NLAYER*3*CDIM*CDIM, NP = NLAYER*CDIM*CDIM,
              NF = NLAYER*4*CDIM*CDIM, NM = NLAYER*CDIM*4*CDIM;
    int i4 = (blockIdx.x * 256 + threadIdx.x) * 4;
    const float* src; __half* dst; int k;
    if (i4 < NQ)                { src = wq; dst = q16; k = i4; }
    else if (i4 < NQ+NP)        { src = wp; dst = p16; k = i4 - NQ; }
    else if (i4 < NQ+NP+NF)     { src = wf; dst = f16; k = i4 - NQ - NP; }
    else if (i4 < NQ+NP+NF+NM)  { src = wm; dst = m16; k = i4 - NQ - NP - NF; }
    else return;
    float4 v = *reinterpret_cast<const float4*>(src + k);
    __half2 a = __floats2half2_rn(v.x, v.y);
    __half2 b = __floats2half2_rn(v.z, v.w);
    uint2 o;
    o.x = reinterpret_cast<unsigned&>(a);
    o.y = reinterpret_cast<unsigned&>(b);
    *reinterpret_cast<uint2*>(dst + k) = o;
}

__global__ void wsplit_f16_kernel(const float* __restrict__ w, __half* __restrict__ h, int n) {
    int i4 = (blockIdx.x * 256 + threadIdx.x) * 4;
    if (i4 >= n) return;
    float4 v = *reinterpret_cast<const float4*>(w + i4);
    __half2 a = __floats2half2_rn(v.x, v.y);
    __half2 b = __floats2half2_rn(v.z, v.w);
    uint2 o;
    o.x = reinterpret_cast<unsigned&>(a);
    o.y = reinterpret_cast<unsigned&>(b);
    *reinterpret_cast<uint2*>(h + i4) = o;
}

__global__ void merge_lora_kernel(const float* __restrict__ yh,
                                  const float* __restrict__ lA,
                                  __half* __restrict__ oh, __half* __restrict__ ol,
                                  float* __restrict__ tmp) {
    const int row = blockIdx.x;
    const int t = row & (TLEN - 1);
    const int b = row >> 10;
    __shared__ float sy[CDIM];
    int tid = threadIdx.x;
    for (int c = tid; c < CDIM; c += 128) {
        int h = c >> 6, d = c & 63;
        sy[c] = yh[(((long long)(b*NHEAD + h) * TLEN) + t) * HD + d];
    }
    __syncthreads();
    for (int c = tid; c < CDIM; c += 128) {
        long long o = (long long)row*CDIM + c;
        __half hi, lo; hsplit(sy[c], hi, lo);
        oh[o] = hi; ol[o] = lo;
    }
    int w = tid >> 5, lane = tid & 31;
    #pragma unroll
    for (int rr = 0; rr < 2; ++rr) {
        int r = w*2 + rr;
        const float* Ar = lA + (long long)r * CDIM;
        float acc = 0.f;
        for (int c = lane; c < CDIM; c += 32) acc += sy[c] * Ar[c];
        #pragma unroll
        for (int off = 16; off > 0; off >>= 1) acc += __shfl_down_sync(0xffffffffu, acc, off);
        if (lane == 0) tmp[row*RANK + r] = acc;
    }
}

// ======================== host driver ========================================
template<int MODE, int SPLITK>
static void launch_gemm_h(dim3 grid,
                          const __half* Ah, const __half* Al, const __half* Bm,
                          const float* bias, const float* loraT, const float* loraB,
                          float* Cm, int M, int N, int K) {
    cudaFuncSetAttribute(mma_gemm_h<MODE, SPLITK>,
                         cudaFuncAttributeMaxDynamicSharedMemorySize, LGEMM_SMEM);
    mma_gemm_h<MODE, SPLITK><<<grid, 256, LGEMM_SMEM>>>(
        Ah, Al, Bm, bias, loraT, loraB, Cm, M, N, K);
}

extern "C" void kernel_launch(void* const* d_in, const int* in_sizes, int n_in,
                              void* d_out, int out_size) {
    (void)in_sizes; (void)n_in; (void)out_size;
    const void*  idx     = d_in[0];
    const float* wte     = (const float*)d_in[1];
    const float* wpe     = (const float*)d_in[2];
    const float* ln1_g   = (const float*)d_in[3];
    const float* ln1_b   = (const float*)d_in[4];
    const float* attn_w  = (const float*)d_in[5];
    const float* attn_lA = (const float*)d_in[6];
    const float* attn_lB = (const float*)d_in[7];
    const float* proj_w  = (const float*)d_in[8];
    const float* proj_lA = (const float*)d_in[9];
    const float* proj_lB = (const float*)d_in[10];
    const float* ln2_g   = (const float*)d_in[11];
    const float* ln2_b   = (const float*)d_in[12];
    const float* fc_w    = (const float*)d_in[13];
    const float* fc_b    = (const float*)d_in[14];
    const float* mproj_w = (const float*)d_in[15];
    const float* mproj_b = (const float*)d_in[16];
    const float* lnf_g   = (const float*)d_in[17];
    const float* lnf_b   = (const float*)d_in[18];
    const float* head_w  = (const float*)d_in[19];
    float* out = (float*)d_out;

    float *X, *YH, *TMP, *QKVp;
    cudaGetSymbolAddress((void**)&X,    g_X);
    cudaGetSymbolAddress((void**)&YH,   g_YH);
    cudaGetSymbolAddress((void**)&TMP,  g_TMP);
    cudaGetSymbolAddress((void**)&QKVp, g_QKVp);

    __half *wqkv16, *wproj16, *wfc16, *wmp16, *whead16,
           *H16h, *H16l, *Y16h, *Y16l, *FCG16h, *FCG16l,
           *Q16, *K16, *V16t;
    cudaGetSymbolAddress((void**)&wqkv16,  g_wqkv16);
    cudaGetSymbolAddress((void**)&wproj16, g_wproj16);
    cudaGetSymbolAddress((void**)&wfc16,   g_wfc16);
    cudaGetSymbolAddress((void**)&wmp16,   g_wmp16);
    cudaGetSymbolAddress((void**)&whead16, g_whead16);
    cudaGetSymbolAddress((void**)&H16h, g_H16h); cudaGetSymbolAddress((void**)&H16l, g_H16l);
    cudaGetSymbolAddress((void**)&Y16h, g_Y16h); cudaGetSymbolAddress((void**)&Y16l, g_Y16l);
    cudaGetSymbolAddress((void**)&FCG16h, g_FCG16h); cudaGetSymbolAddress((void**)&FCG16l, g_FCG16l);
    cudaGetSymbolAddress((void**)&Q16, g_Q16);
    cudaGetSymbolAddress((void**)&K16, g_K16);
    cudaGetSymbolAddress((void**)&V16t, g_V16t);

    cudaFuncSetAttribute(flash_attn, cudaFuncAttributeMaxDynamicSharedMemorySize, FA_SMEM);

    detect_idx_kernel<<<1, 256>>>((const unsigned int*)idx);
    embed_kernel<<<(MTOK*CDIM + 255)/256, 256>>>(idx, wte, wpe, X);
    {
        int nA = NLAYER*(3*CDIM*CDIM + CDIM*CDIM + 4*CDIM*CDIM + 4*CDIM*CDIM);
        wcvt16_kernel<<<(nA/4 + 255)/256, 256>>>(attn_w, proj_w, fc_w, mproj_w,
            wqkv16, wproj16, wfc16, wmp16);
        int nB = VOCAB*CDIM;
        wsplit_f16_kernel<<<(nB/4 + 255)/256, 256>>>(head_w, whead16, nB);
    }

    for (int l = 0; l < NLAYER; l++) {
        long long oq = (long long)l * 3*CDIM*CDIM;
        long long op = (long long)l * CDIM*CDIM;
        long long of = (long long)l * 4*CDIM*CDIM;
        long long om = (long long)l * CDIM*4*CDIM;
        const float* lA_q = attn_lA + (long long)l * RANK*CDIM;
        const float* lB_q = attn_lB + (long long)l * 3*CDIM*RANK;
        const float* lA_p = proj_lA + (long long)l * RANK*CDIM;
        const float* lB_p = proj_lB + (long long)l * CDIM*RANK;

        // ---- attention ----
        ln_lora_kernel<<<MTOK, 128>>>(X, ln1_g + l*CDIM, ln1_b + l*CDIM, lA_q, H16h, H16l, TMP);
        launch_gemm_h<0, 1>(dim3(MTOK/128, 3*CDIM/128, 2),
            H16h, H16l, wqkv16 + oq, nullptr, TMP, lB_q, QKVp,
            MTOK, 3*CDIM, CDIM);
        split_qkv2_kernel<<<(NBATCH*TLEN*HD + 255)/256, 256>>>(QKVp);

        flash_attn<<<dim3(TLEN/128, NBATCH), 256, FA_SMEM>>>(Q16, K16, V16t, YH);
        merge_lora_kernel<<<MTOK, 128>>>(YH, lA_p, Y16h, Y16l, TMP);

        launch_gemm_h<2, 1>(dim3(MTOK/128, CDIM/128, 2),
            Y16h, Y16l, wproj16 + op, nullptr, TMP, lB_p, X,
            MTOK, CDIM, CDIM);

        // ---- MLP ----
        ln_lora_kernel<<<MTOK, 128>>>(X, ln2_g + l*CDIM, ln2_b + l*CDIM, nullptr, H16h, H16l, TMP);
        launch_gemm_h<1, 0>(dim3(MTOK/128, 4*CDIM/128, 1),
            H16h, H16l, wfc16 + of, fc_b + (long long)l*4*CDIM, nullptr, nullptr, nullptr,
            MTOK, 4*CDIM, CDIM);
        launch_gemm_h<2, 1>(dim3(MTOK/128, CDIM/128, 2),
            FCG16h, FCG16l, wmp16 + om, mproj_b + (long long)l*CDIM, nullptr, nullptr, X,
            MTOK, CDIM, 4*CDIM);
    }

    // ---- final layernorm + fp16 1-MMA vocab head ----
    ln_f16_kernel<<<MTOK, 128>>>(X, lnf_g, lnf_b, H16h);
    cudaFuncSetAttribute(mma_gemm_f16, cudaFuncAttributeMaxDynamicSharedMemorySize, GEMM_SMEM_F16);
    mma_gemm_f16<<<dim3(MTOK/128, (VOCAB + 127)/128), 256, GEMM_SMEM_F16>>>(
        H16h, whead16, out, MTOK, VOCAB, CDIM);
}

// round 17
// speedup vs baseline: 1.7909x; 1.1067x over previous
#include <cuda_runtime.h>
#include <cuda_bf16.h>
#include <cuda_fp16.h>
#include <math.h>

// ---------------------------------------------------------------------------
// GPT_3959959847300 round 17: R16 + 1-term fp16 fc/mproj GEMMs (drop the
// activation-lo MMA; 2 smem tiles/stage). qkv/proj stay 2-term; attention and
// head unchanged.
// ---------------------------------------------------------------------------

#define BSZ    2
#define TLEN   1024
#define CDIM   512
#define NHEAD  8
#define HD     64
#define NLAYER 4
#define VOCAB  50257
#define RANK   8
#define LSCALE 4.0f
#define MTOK   (BSZ*TLEN)
#define NBATCH (BSZ*NHEAD)

// ======================== PTX helpers ========================================
__device__ __forceinline__ unsigned smem_u32(const void* p) {
    unsigned a;
    asm("{ .reg .u64 t; cvta.to.shared.u64 t, %1; cvt.u32.u64 %0, t; }" : "=r"(a) : "l"(p));
    return a;
}
__device__ __forceinline__ void ldmx4(unsigned* r, unsigned addr) {
    asm volatile("ldmatrix.sync.aligned.m8n8.x4.shared.b16 {%0,%1,%2,%3}, [%4];"
                 : "=r"(r[0]), "=r"(r[1]), "=r"(r[2]), "=r"(r[3]) : "r"(addr));
}
__device__ __forceinline__ void mma16816h(float* d, const unsigned* a, const unsigned* b) {
    asm volatile(
        "mma.sync.aligned.m16n8k16.row.col.f32.f16.f16.f32 "
        "{%0,%1,%2,%3},{%4,%5,%6,%7},{%8,%9},{%0,%1,%2,%3};"
        : "+f"(d[0]), "+f"(d[1]), "+f"(d[2]), "+f"(d[3])
        : "r"(a[0]), "r"(a[1]), "r"(a[2]), "r"(a[3]), "r"(b[0]), "r"(b[1]));
}
__device__ __forceinline__ void cp16(unsigned dst, const void* src, bool pred) {
    int sz = pred ? 16 : 0;
    asm volatile("cp.async.cg.shared.global [%0], [%1], 16, %2;"
                 :: "r"(dst), "l"(src), "r"(sz) : "memory");
}
#define CP_COMMIT()  asm volatile("cp.async.commit_group;" ::: "memory")
#define CP_WAIT_1()  asm volatile("cp.async.wait_group 1;" ::: "memory")
#define CP_WAIT_0()  asm volatile("cp.async.wait_group 0;" ::: "memory")

__device__ __forceinline__ void hsplit(float x, __half& hi, __half& lo) {
    hi = __float2half(x);
    lo = __float2half(x - __half2float(hi));
}
__device__ __forceinline__ unsigned packh(float a, float b) {
    __half2 t = __floats2half2_rn(a, b);
    return reinterpret_cast<unsigned&>(t);
}

// ======================== scratch ============================================
__device__ float g_X  [MTOK*CDIM];
__device__ float g_YH [NBATCH*TLEN*HD];
__device__ float g_TMP[MTOK*RANK];
__device__ float g_QKVp[2ll*MTOK*3*CDIM];
__device__ int   g_idx32;

__device__ __half g_wqkv16[NLAYER*3*CDIM*CDIM];
__device__ __half g_wproj16[NLAYER*CDIM*CDIM];
__device__ __half g_wfc16 [NLAYER*4*CDIM*CDIM];
__device__ __half g_wmp16 [NLAYER*CDIM*4*CDIM];
__device__ __half g_whead16[VOCAB*CDIM];
__device__ __half g_H16h[MTOK*CDIM],  g_H16l[MTOK*CDIM];
__device__ __half g_Y16h[MTOK*CDIM],  g_Y16l[MTOK*CDIM];
__device__ __half g_FCG16h[MTOK*4*CDIM];
__device__ __half g_Q16[NBATCH*TLEN*HD];
__device__ __half g_K16[NBATCH*TLEN*HD];
__device__ __half g_V16t[NBATCH*HD*TLEN];

// ======================== common tile helpers ================================
#define TILE_B    16384                 // 128x64 16-bit tile (128B rows, swizzled)
#define STAGE2_B  (2*TILE_B)
#define GEMM_SMEM_F16 (2*STAGE2_B)      // 65536

__device__ __forceinline__ unsigned swz(int row, int colB) {
    unsigned o = (unsigned)(row * 128 + colB);
    return o ^ ((unsigned)(row & 7) << 4);
}

// ======================== fp16 layer GEMM (1 or 2 terms) =====================
// MODE: 0 fp32 partial store (per-z buffers, +bias/lora on z==0)
//       1 gelu->fp16 hi store; 2 residual += (atomicAdd if SPLITK)
// SPLITK: 0 normal; 1 K halved across blockIdx.z
// TERMS: 1 (A only) or 2 (A hi + A lo)
template<int MODE, int SPLITK, int TERMS>
__global__ __launch_bounds__(256, 1)
void mma_gemm_h(const __half* __restrict__ Ah, const __half* __restrict__ Al,
                const __half* __restrict__ Bm,
                const float* __restrict__ bias,
                const float* __restrict__ loraT, const float* __restrict__ loraB,
                float* __restrict__ Cm,
                int M, int N, int K)
{
    constexpr unsigned LSTAGE = (TERMS + 1) * TILE_B;
    extern __shared__ char smem_raw[];
    const int m0 = blockIdx.x * 128;
    const int n0 = blockIdx.y * 128;
    const int kz = SPLITK ? (int)blockIdx.z : 0;
    const int kslice = SPLITK ? (K >> 1) : K;
    const int koff = kz * kslice;

    const unsigned sbase = smem_u32(smem_raw);
    const int tid  = threadIdx.x;
    const int lane = tid & 31;
    const int wid  = tid >> 5;
    const int wm   = wid & 1;
    const int wn   = wid >> 1;
    const int lr   = tid >> 1;
    const int lcB  = (tid & 1) << 6;

    float acc[4][4][4];
    #pragma unroll
    for (int i = 0; i < 4; i++)
        #pragma unroll
        for (int j = 0; j < 4; j++)
            #pragma unroll
            for (int t = 0; t < 4; t++) acc[i][j][t] = 0.f;

    const int nc = kslice >> 6;

    auto stage_ld = [&](unsigned sb, int k0) {
        {
            const char* pa = (const char*)(Ah + (size_t)(m0 + lr) * K + k0) + lcB;
            #pragma unroll
            for (int j = 0; j < 4; j++) {
                unsigned o = swz(lr, lcB + 16*j);
                cp16(sb + o, pa + 16*j, true);
            }
            if (TERMS == 2) {
                const char* pl = (const char*)(Al + (size_t)(m0 + lr) * K + k0) + lcB;
                #pragma unroll
                for (int j = 0; j < 4; j++) {
                    unsigned o = swz(lr, lcB + 16*j);
                    cp16(sb + TILE_B + o, pl + 16*j, true);
                }
            }
        }
        {
            const char* pb = (const char*)(Bm + (size_t)(n0 + lr) * K + k0) + lcB;
            #pragma unroll
            for (int j = 0; j < 4; j++) {
                unsigned o = swz(lr, lcB + 16*j);
                cp16(sb + TERMS*TILE_B + o, pb + 16*j, true);
            }
        }
    };

    stage_ld(sbase, koff);
    CP_COMMIT();

    const int a_rin  = lane & 15;
    const int a_cB   = (lane >> 4) * 16;
    const int b_sel  = lane >> 3;
    const int b_rin  = (b_sel >> 1) * 8 + (lane & 7);
    const int b_cB   = (b_sel & 1) * 16;

    for (int cI = 0; cI < nc; ++cI) {
        const int s = cI & 1;
        if (cI + 1 < nc) {
            stage_ld(sbase + (unsigned)(1 - s) * LSTAGE, koff + ((cI + 1) << 6));
            CP_COMMIT();
            CP_WAIT_1();
        } else {
            CP_WAIT_0();
        }
        __syncthreads();

        const unsigned st = sbase + (unsigned)s * LSTAGE;
        #pragma unroll
        for (int ks = 0; ks < 4; ++ks) {
            unsigned ra_h[4][4], ra_l[4][4], rb[4][2];
            #pragma unroll
            for (int i = 0; i < 4; ++i) {
                int row = wm*64 + i*16 + a_rin;
                unsigned o = swz(row, ks*32 + a_cB);
                ldmx4(ra_h[i], st + o);
                if (TERMS == 2) ldmx4(ra_l[i], st + TILE_B + o);
            }
            #pragma unroll
            for (int jp = 0; jp < 2; ++jp) {
                int row = wn*32 + jp*16 + b_rin;
                unsigned o = swz(row, ks*32 + b_cB);
                unsigned r[4];
                ldmx4(r, st + TERMS*TILE_B + o);
                rb[2*jp][0] = r[0]; rb[2*jp][1] = r[1];
                rb[2*jp+1][0] = r[2]; rb[2*jp+1][1] = r[3];
            }
            #pragma unroll
            for (int i = 0; i < 4; ++i)
                #pragma unroll
                for (int j = 0; j < 4; ++j) {
                    mma16816h(acc[i][j], ra_h[i], rb[j]);
                    if (TERMS == 2) mma16816h(acc[i][j], ra_l[i], rb[j]);
                }
        }
        __syncthreads();
    }

    const int group = lane >> 2, tig = lane & 3;
    float* cbuf = (MODE == 0) ? (Cm + (size_t)kz * M * N) : Cm;
    #pragma unroll
    for (int i = 0; i < 4; ++i) {
        int m_lo = m0 + wm*64 + i*16 + group;
        #pragma unroll
        for (int j = 0; j < 4; ++j) {
            int nA = n0 + wn*32 + j*8 + tig*2;
            #pragma unroll
            for (int h = 0; h < 2; ++h) {
                int m = m_lo + h*8;
                #pragma unroll
                for (int e = 0; e < 2; ++e) {
                    int n = nA + e;
                    float v = acc[i][j][h*2 + e];
                    if (bias && kz == 0)  v += bias[n];
                    if (loraT && kz == 0) {
                        const float* t  = loraT + (size_t)m * RANK;
                        const float* bb = loraB + (size_t)n * RANK;
                        float s = 0.f;
                        #pragma unroll
                        for (int r = 0; r < RANK; r++) s += t[r] * bb[r];
                        v += LSCALE * s;
                    }
                    if (MODE == 0) {
                        cbuf[(long long)m * N + n] = v;
                    } else if (MODE == 2) {
                        if (SPLITK) atomicAdd(&Cm[(long long)m * N + n], v);
                        else        Cm[(long long)m * N + n] += v;
                    } else {
                        float gv = 0.5f * v * (1.f + tanhf(0.7978845608028654f * (v + 0.044715f * v*v*v)));
                        g_FCG16h[(long long)m * N + n] = __float2half(gv);
                    }
                }
            }
        }
    }
}

// combine qkv split-K partials -> Q fp16 (bhtd), K fp16 (bhtd), V^T fp16
__global__ void split_qkv2_kernel(const float* __restrict__ qkvp) {
    int i = blockIdx.x * 256 + threadIdx.x;
    if (i >= NBATCH*TLEN*HD) return;
    int d = i % HD;
    int t = (i / HD) % TLEN;
    int h = (i / (HD*TLEN)) % NHEAD;
    int b = i / (HD*TLEN*NHEAD);
    long long src = (long long)(b*TLEN + t) * (3*CDIM) + h*HD + d;
    const long long off = (long long)MTOK * 3*CDIM;
    float q = qkvp[src] + qkvp[src + off];
    float k = qkvp[src + CDIM] + qkvp[src + CDIM + off];
    float v = qkvp[src + 2*CDIM] + qkvp[src + 2*CDIM + off];
    g_Q16[i] = __float2half(q);
    g_K16[i] = __float2half(k);
    long long vi = ((long long)(b*NHEAD + h) * HD + d) * TLEN + t;
    g_V16t[vi] = __float2half(v);
}

// ======================== fp16 1-MMA head GEMM (128x128, occ=2) ==============
__global__ __launch_bounds__(256, 2)
void mma_gemm_f16(const __half* __restrict__ Am, const __half* __restrict__ Bm,
                  float* __restrict__ Cm, int M, int N, int K)
{
    extern __shared__ char smem_raw[];
    const int m0 = blockIdx.x * 128;
    const int n0 = blockIdx.y * 128;

    const unsigned sbase = smem_u32(smem_raw);
    const int tid  = threadIdx.x;
    const int lane = tid & 31;
    const int wid  = tid >> 5;
    const int wm   = wid & 1;
    const int wn   = wid >> 1;
    const int lr   = tid >> 1;
    const int lcB  = (tid & 1) << 6;

    float acc[4][4][4];
    #pragma unroll
    for (int i = 0; i < 4; i++)
        #pragma unroll
        for (int j = 0; j < 4; j++)
            #pragma unroll
            for (int t = 0; t < 4; t++) acc[i][j][t] = 0.f;

    const int nc = K >> 6;

    auto stage2 = [&](unsigned sb, int k0) {
        {
            int gr = m0 + lr; bool ok = (gr < M); int r = ok ? gr : 0;
            const char* pa = (const char*)(Am + (size_t)r * K + k0) + lcB;
            #pragma unroll
            for (int j = 0; j < 4; j++) {
                unsigned o = swz(lr, lcB + 16*j);
                cp16(sb + o, pa + 16*j, ok);
            }
        }
        {
            int gr = n0 + lr; bool ok = (gr < N); int r = ok ? gr : 0;
            const char* pb = (const char*)(Bm + (size_t)r * K + k0) + lcB;
            #pragma unroll
            for (int j = 0; j < 4; j++) {
                unsigned o = swz(lr, lcB + 16*j);
                cp16(sb + TILE_B + o, pb + 16*j, ok);
            }
        }
    };

    stage2(sbase, 0);
    CP_COMMIT();

    const int a_rin  = lane & 15;
    const int a_cB   = (lane >> 4) * 16;
    const int b_sel  = lane >> 3;
    const int b_rin  = (b_sel >> 1) * 8 + (lane & 7);
    const int b_cB   = (b_sel & 1) * 16;

    for (int cI = 0; cI < nc; ++cI) {
        const int s = cI & 1;
        if (cI + 1 < nc) {
            stage2(sbase + (unsigned)(1 - s) * STAGE2_B, (cI + 1) << 6);
            CP_COMMIT();
            CP_WAIT_1();
        } else {
            CP_WAIT_0();
        }
        __syncthreads();

        const unsigned st = sbase + (unsigned)s * STAGE2_B;
        #pragma unroll
        for (int ks = 0; ks < 4; ++ks) {
            unsigned ra[4][4], rb[4][2];
            #pragma unroll
            for (int i = 0; i < 4; ++i) {
                int row = wm*64 + i*16 + a_rin;
                unsigned o = swz(row, ks*32 + a_cB);
                ldmx4(ra[i], st + o);
            }
            #pragma unroll
            for (int jp = 0; jp < 2; ++jp) {
                int row = wn*32 + jp*16 + b_rin;
                unsigned o = swz(row, ks*32 + b_cB);
                unsigned r[4];
                ldmx4(r, st + TILE_B + o);
                rb[2*jp][0] = r[0]; rb[2*jp][1] = r[1];
                rb[2*jp+1][0] = r[2]; rb[2*jp+1][1] = r[3];
            }
            #pragma unroll
            for (int i = 0; i < 4; ++i)
                #pragma unroll
                for (int j = 0; j < 4; ++j)
                    mma16816h(acc[i][j], ra[i], rb[j]);
        }
        __syncthreads();
    }

    const int group = lane >> 2, tig = lane & 3;
    #pragma unroll
    for (int i = 0; i < 4; ++i) {
        int m_lo = m0 + wm*64 + i*16 + group;
        #pragma unroll
        for (int j = 0; j < 4; ++j) {
            int nA = n0 + wn*32 + j*8 + tig*2;
            #pragma unroll
            for (int h = 0; h < 2; ++h) {
                int m = m_lo + h*8;
                if (m >= M) continue;
                float* crow = Cm + (long long)m * N;
                #pragma unroll
                for (int e = 0; e < 2; ++e) {
                    int n = nA + e;
                    if (n < N) crow[n] = acc[i][j][h*2 + e];
                }
            }
        }
    }
}

// ======================== fused flash attention (pure fp16) ==================
#define FA_QTILE 16384
#define FA_STAGE 32768          // K 16K | V 16K (2x8K)
#define FA_SMEM  (FA_QTILE + 2*FA_STAGE)   // 81920

__global__ __launch_bounds__(256, 1)
void flash_attn(const __half* __restrict__ Qm, const __half* __restrict__ Km,
                const __half* __restrict__ Vt, float* __restrict__ YH)
{
    extern __shared__ char smem_raw[];
    const unsigned sbase = smem_u32(smem_raw);
    const int m0 = blockIdx.x * 128;
    const int bh = blockIdx.y;
    const int tid = threadIdx.x;
    const int lane = tid & 31;
    const int wid = tid >> 5;

    const __half* qm = Qm + (size_t)bh * TLEN * HD;
    const __half* km = Km + (size_t)bh * TLEN * HD;
    const __half* vt = Vt + (size_t)bh * HD * TLEN;

    const unsigned sQ = sbase;
    const unsigned sStage = sbase + FA_QTILE;

    {
        int lr = tid >> 1, lcB = (tid & 1) << 6;
        const char* pq = (const char*)(qm + (size_t)(m0 + lr) * HD) + lcB;
        #pragma unroll
        for (int j = 0; j < 4; j++) {
            unsigned o = swz(lr, lcB + 16*j);
            cp16(sQ + o, pq + 16*j, true);
        }
    }
    CP_COMMIT();

    const int nkb = blockIdx.x + 1;

    auto load_stage = [&](int kb, int s) {
        unsigned st = sStage + (unsigned)s * FA_STAGE;
        int lr = tid >> 1, lcB = (tid & 1) << 6;
        const char* pk = (const char*)(km + (size_t)(kb*128 + lr) * HD) + lcB;
        #pragma unroll
        for (int j = 0; j < 4; j++) {
            unsigned o = swz(lr, lcB + 16*j);
            cp16(st + o, pk + 16*j, true);
        }
        int vr = tid >> 2, vc = (tid & 3) << 5;
        #pragma unroll
        for (int c = 0; c < 2; c++) {
            const char* pv = (const char*)(vt + (size_t)vr * TLEN + kb*128 + c*64) + vc;
            unsigned vb = st + 16384 + (unsigned)c * 8192;
            #pragma unroll
            for (int j = 0; j < 2; j++) {
                unsigned o = swz(vr, vc + 16*j);
                cp16(vb + o, pv + 16*j, true);
            }
        }
    };

    load_stage(0, 0);
    CP_COMMIT();
    CP_WAIT_1();
    __syncthreads();

    unsigned qf[4][4];
    const int a_rin = lane & 15, a_cB = (lane >> 4) * 16;
    #pragma unroll
    for (int ks = 0; ks < 4; ks++) {
        unsigned o = swz(wid*16 + a_rin, ks*32 + a_cB);
        ldmx4(qf[ks], sQ + o);
    }

    float O[8][4];
    #pragma unroll
    for (int i = 0; i < 8; i++)
        #pragma unroll
        for (int t = 0; t < 4; t++) O[i][t] = 0.f;
    float mrun0 = -1e30f, mrun1 = -1e30f, lrun0 = 0.f, lrun1 = 0.f;

    const int b_sel = lane >> 3;
    const int b_rin = (b_sel >> 1)*8 + (lane & 7);
    const int b_cB  = (b_sel & 1)*16;
    const int g = lane >> 2, tig = lane & 3;

    for (int kb = 0; kb < nkb; kb++) {
        if (kb + 1 < nkb) { load_stage(kb + 1, (kb + 1) & 1); CP_COMMIT(); CP_WAIT_1(); }
        else CP_WAIT_0();
        __syncthreads();
        const unsigned st = sStage + (unsigned)(kb & 1) * FA_STAGE;

        float S[16][4];
        #pragma unroll
        for (int j = 0; j < 16; j++)
            #pragma unroll
            for (int t = 0; t < 4; t++) S[j][t] = 0.f;

        #pragma unroll
        for (int ks = 0; ks < 4; ks++) {
            #pragma unroll
            for (int jp = 0; jp < 8; jp++) {
                unsigned o = swz(jp*16 + b_rin, ks*32 + b_cB);
                unsigned r[4];
                ldmx4(r, st + o);
                unsigned b0[2] = {r[0], r[1]}, b1[2] = {r[2], r[3]};
                mma16816h(S[2*jp],   qf[ks], b0);
                mma16816h(S[2*jp+1], qf[ks], b1);
            }
        }
        #pragma unroll
        for (int j = 0; j < 16; j++)
            #pragma unroll
            for (int t = 0; t < 4; t++) S[j][t] *= 0.125f;

        if (kb == nkb - 1) {
            int row0 = m0 + wid*16 + g;
            int row1 = row0 + 8;
            #pragma unroll
            for (int j = 0; j < 16; j++) {
                int col = kb*128 + j*8 + tig*2;
                if (col     > row0) S[j][0] = -1e30f;
                if (col + 1 > row0) S[j][1] = -1e30f;
                if (col     > row1) S[j][2] = -1e30f;
                if (col + 1 > row1) S[j][3] = -1e30f;
            }
        }

        float mx0 = -1e30f, mx1 = -1e30f;
        #pragma unroll
        for (int j = 0; j < 16; j++) {
            mx0 = fmaxf(mx0, fmaxf(S[j][0], S[j][1]));
            mx1 = fmaxf(mx1, fmaxf(S[j][2], S[j][3]));
        }
        mx0 = fmaxf(mx0, __shfl_xor_sync(0xffffffffu, mx0, 1));
        mx0 = fmaxf(mx0, __shfl_xor_sync(0xffffffffu, mx0, 2));
        mx1 = fmaxf(mx1, __shfl_xor_sync(0xffffffffu, mx1, 1));
        mx1 = fmaxf(mx1, __shfl_xor_sync(0xffffffffu, mx1, 2));
        float nm0 = fmaxf(mrun0, mx0), nm1 = fmaxf(mrun1, mx1);
        float f0 = expf(mrun0 - nm0), f1 = expf(mrun1 - nm1);
        mrun0 = nm0; mrun1 = nm1;
        float rs0 = 0.f, rs1 = 0.f;
        #pragma unroll
        for (int j = 0; j < 16; j++) {
            S[j][0] = expf(S[j][0] - nm0);
            S[j][1] = expf(S[j][1] - nm0);
            S[j][2] = expf(S[j][2] - nm1);
            S[j][3] = expf(S[j][3] - nm1);
            rs0 += S[j][0] + S[j][1];
            rs1 += S[j][2] + S[j][3];
        }
        rs0 += __shfl_xor_sync(0xffffffffu, rs0, 1);
        rs0 += __shfl_xor_sync(0xffffffffu, rs0, 2);
        rs1 += __shfl_xor_sync(0xffffffffu, rs1, 1);
        rs1 += __shfl_xor_sync(0xffffffffu, rs1, 2);
        lrun0 = lrun0 * f0 + rs0;
        lrun1 = lrun1 * f1 + rs1;
        #pragma unroll
        for (int i = 0; i < 8; i++) {
            O[i][0] *= f0; O[i][1] *= f0;
            O[i][2] *= f1; O[i][3] *= f1;
        }

        #pragma unroll
        for (int c2 = 0; c2 < 2; c2++) {
            const unsigned vst = st + 16384 + (unsigned)c2 * 8192;
            #pragma unroll
            for (int ks = 0; ks < 4; ks++) {
                const int sI = c2*4 + ks;
                const float* e0 = S[2*sI];
                const float* e1 = S[2*sI + 1];
                unsigned ap[4];
                ap[0] = packh(e0[0], e0[1]);
                ap[1] = packh(e0[2], e0[3]);
                ap[2] = packh(e1[0], e1[1]);
                ap[3] = packh(e1[2], e1[3]);
                #pragma unroll
                for (int jp = 0; jp < 4; jp++) {
                    unsigned o = swz(jp*16 + b_rin, ks*32 + b_cB);
                    unsigned r[4];
                    ldmx4(r, vst + o);
                    unsigned b0[2] = {r[0], r[1]}, b1[2] = {r[2], r[3]};
                    mma16816h(O[2*jp],   ap, b0);
                    mma16816h(O[2*jp+1], ap, b1);
                }
            }
        }
        __syncthreads();
    }

    float inv0 = 1.f / lrun0, inv1 = 1.f / lrun1;
    float* y0 = YH + ((size_t)bh * TLEN + m0 + wid*16 + g) * HD;
    float* y1 = y0 + 8 * HD;
    #pragma unroll
    for (int i = 0; i < 8; i++) {
        int d = i*8 + tig*2;
        y0[d]     = O[i][0] * inv0;
        y0[d + 1] = O[i][1] * inv0;
        y1[d]     = O[i][2] * inv1;
        y1[d + 1] = O[i][3] * inv1;
    }
}

// ======================== small kernels ======================================
__global__ void detect_idx_kernel(const unsigned int* w) {
    __shared__ unsigned int s;
    if (threadIdx.x == 0) s = 0u;
    __syncthreads();
    unsigned int v = 0u;
    for (int i = threadIdx.x; i < 1024; i += blockDim.x) v |= w[2*i + 1];
    atomicOr(&s, v);
    __syncthreads();
    if (threadIdx.x == 0) g_idx32 = (s != 0u) ? 1 : 0;
}

__global__ void embed_kernel(const void* idx, const float* __restrict__ wte,
                             const float* __restrict__ wpe, float* __restrict__ x) {
    int i = blockIdx.x * blockDim.x + threadIdx.x;
    if (i >= MTOK*CDIM) return;
    int c  = i % CDIM;
    int bt = i / CDIM;
    int t  = bt % TLEN;
    long long tok;
    if (g_idx32) tok = (long long)((const int*)idx)[bt];
    else         tok = ((const long long*)idx)[bt];
    x[i] = wte[tok*CDIM + c] + wpe[(long long)t*CDIM + c];
}

// layernorm -> fp16 hi (+ optional lo) split (+ optional fused lora x@A^T)
__global__ void ln_lora_kernel(const float* __restrict__ x, const float* __restrict__ g,
                               const float* __restrict__ b,
                               const float* __restrict__ lA,
                               __half* __restrict__ oh, __half* __restrict__ ol,
                               float* __restrict__ tmp) {
    const int row = blockIdx.x;
    const float* xr = x + (long long)row * CDIM;
    __shared__ float sx[CDIM];
    __shared__ float red[128];
    __shared__ float s_mean, s_rstd;
    int tid = threadIdx.x;
    float s = 0.f;
    for (int c = tid; c < CDIM; c += 128) { float v = xr[c]; sx[c] = v; s += v; }
    red[tid] = s; __syncthreads();
    for (int st = 64; st > 0; st >>= 1) { if (tid < st) red[tid] += red[tid+st]; __syncthreads(); }
    if (tid == 0) s_mean = red[0] / (float)CDIM;
    __syncthreads();
    float mean = s_mean;
    float sq = 0.f;
    for (int c = tid; c < CDIM; c += 128) { float d = sx[c] - mean; sq += d*d; }
    red[tid] = sq; __syncthreads();
    for (int st = 64; st > 0; st >>= 1) { if (tid < st) red[tid] += red[tid+st]; __syncthreads(); }
    if (tid == 0) s_rstd = rsqrtf(red[0] / (float)CDIM + 1e-5f);
    __syncthreads();
    float mean2 = s_mean, rstd = s_rstd;
    for (int c = tid; c < CDIM; c += 128) {
        float v = (sx[c] - mean2) * rstd * g[c] + b[c];
        long long o = (long long)row*CDIM + c;
        __half hi, lo; hsplit(v, hi, lo);
        oh[o] = hi;
        if (ol) ol[o] = lo;
        sx[c] = v;
    }
    __syncthreads();
    if (lA) {
        int w = tid >> 5, lane = tid & 31;
        #pragma unroll
        for (int rr = 0; rr < 2; ++rr) {
            int r = w*2 + rr;
            const float* Ar = lA + (long long)r * CDIM;
            float acc = 0.f;
            for (int c = lane; c < CDIM; c += 32) acc += sx[c] * Ar[c];
            #pragma unroll
            for (int off = 16; off > 0; off >>= 1) acc += __shfl_down_sync(0xffffffffu, acc, off);
            if (lane == 0) tmp[row*RANK + r] = acc;
        }
    }
}

__global__ void ln_f16_kernel(const float* __restrict__ x, const float* __restrict__ g,
                              const float* __restrict__ b, __half* __restrict__ oh) {
    const int row = blockIdx.x;
    const float* xr = x + (long long)row * CDIM;
    __shared__ float sx[CDIM];
    __shared__ float red[128];
    __shared__ float s_mean, s_rstd;
    int tid = threadIdx.x;
    float s = 0.f;
    for (int c = tid; c < CDIM; c += 128) { float v = xr[c]; sx[c] = v; s += v; }
    red[tid] = s; __syncthreads();
    for (int st = 64; st > 0; st >>= 1) { if (tid < st) red[tid] += red[tid+st]; __syncthreads(); }
    if (tid == 0) s_mean = red[0] / (float)CDIM;
    __syncthreads();
    float mean = s_mean;
    float sq = 0.f;
    for (int c = tid; c < CDIM; c += 128) { float d = sx[c] - mean; sq += d*d; }
    red[tid] = sq; __syncthreads();
    for (int st = 64; st > 0; st >>= 1) { if (tid < st) red[tid] += red[tid+st]; __syncthreads(); }
    if (tid == 0) s_rstd = rsqrtf(red[0] / (float)CDIM + 1e-5f);
    __syncthreads();
    float mean2 = s_mean, rstd = s_rstd;
    for (int c = tid; c < CDIM; c += 128) {
        float v = (sx[c] - mean2) * rstd * g[c] + b[c];
        oh[(long long)row*CDIM + c] = __float2half(v);
    }
}

__global__ void wcvt16_kernel(const float* __restrict__ wq, const float* __restrict__ wp,
                              const float* __restrict__ wf, const float* __restrict__ wm,
                              __half* __restrict__ q16, __half* __restrict__ p16,
                              __half* __restrict__ f16, __half* __restrict__ m16) {
    const int NQ = NLAYER*3*CDIM*CDIM, NP = NLAYER*CDIM*CDIM,
              NF = NLAYER*4*CDIM*CDIM, NM = NLAYER*CDIM*4*CDIM;
    int i4 = (blockIdx.x * 256 + threadIdx.x) * 4;
    const float* src; __half* dst; int k;
    if (i4 < NQ)                { src = wq; dst = q16; k = i4; }
    else if (i4 < NQ+NP)        { src = wp; dst = p16; k = i4 - NQ; }
    else if (i4 < NQ+NP+NF)     { src = wf; dst = f16; k = i4 - NQ - NP; }
    else if (i4 < NQ+NP+NF+NM)  { src = wm; dst = m16; k = i4 - NQ - NP - NF; }
    else return;
    float4 v = *reinterpret_cast<const float4*>(src + k);
    __half2 a = __floats2half2_rn(v.x, v.y);
    __half2 b = __floats2half2_rn(v.z, v.w);
    uint2 o;
    o.x = reinterpret_cast<unsigned&>(a);
    o.y = reinterpret_cast<unsigned&>(b);
    *reinterpret_cast<uint2*>(dst + k) = o;
}

__global__ void wsplit_f16_kernel(const float* __restrict__ w, __half* __restrict__ h, int n) {
    int i4 = (blockIdx.x * 256 + threadIdx.x) * 4;
    if (i4 >= n) return;
    float4 v = *reinterpret_cast<const float4*>(w + i4);
    __half2 a = __floats2half2_rn(v.x, v.y);
    __half2 b = __floats2half2_rn(v.z, v.w);
    uint2 o;
    o.x = reinterpret_cast<unsigned&>(a);
    o.y = reinterpret_cast<unsigned&>(b);
    *reinterpret_cast<uint2*>(h + i4) = o;
}

__global__ void merge_lora_kernel(const float* __restrict__ yh,
                                  const float* __restrict__ lA,
                                  __half* __restrict__ oh, __half* __restrict__ ol,
                                  float* __restrict__ tmp) {
    const int row = blockIdx.x;
    const int t = row & (TLEN - 1);
    const int b = row >> 10;
    __shared__ float sy[CDIM];
    int tid = threadIdx.x;
    for (int c = tid; c < CDIM; c += 128) {
        int h = c >> 6, d = c & 63;
        sy[c] = yh[(((long long)(b*NHEAD + h) * TLEN) + t) * HD + d];
    }
    __syncthreads();
    for (int c = tid; c < CDIM; c += 128) {
        long long o = (long long)row*CDIM + c;
        __half hi, lo; hsplit(sy[c], hi, lo);
        oh[o] = hi; ol[o] = lo;
    }
    int w = tid >> 5, lane = tid & 31;
    #pragma unroll
    for (int rr = 0; rr < 2; ++rr) {
        int r = w*2 + rr;
        const float* Ar = lA + (long long)r * CDIM;
        float acc = 0.f;
        for (int c = lane; c < CDIM; c += 32) acc += sy[c] * Ar[c];
        #pragma unroll
        for (int off = 16; off > 0; off >>= 1) acc += __shfl_down_sync(0xffffffffu, acc, off);
        if (lane == 0) tmp[row*RANK + r] = acc;
    }
}

// ======================== host driver ========================================
template<int MODE, int SPLITK, int TERMS>
static void launch_gemm_h(dim3 grid,
                          const __half* Ah, const __half* Al, const __half* Bm,
                          const float* bias, const float* loraT, const float* loraB,
                          float* Cm, int M, int N, int K) {
    const int smem = 2 * (TERMS + 1) * TILE_B;
    cudaFuncSetAttribute(mma_gemm_h<MODE, SPLITK, TERMS>,
                         cudaFuncAttributeMaxDynamicSharedMemorySize, smem);
    mma_gemm_h<MODE, SPLITK, TERMS><<<grid, 256, smem>>>(
        Ah, Al, Bm, bias, loraT, loraB, Cm, M, N, K);
}

extern "C" void kernel_launch(void* const* d_in, const int* in_sizes, int n_in,
                              void* d_out, int out_size) {
    (void)in_sizes; (void)n_in; (void)out_size;
    const void*  idx     = d_in[0];
    const float* wte     = (const float*)d_in[1];
    const float* wpe     = (const float*)d_in[2];
    const float* ln1_g   = (const float*)d_in[3];
    const float* ln1_b   = (const float*)d_in[4];
    const float* attn_w  = (const float*)d_in[5];
    const float* attn_lA = (const float*)d_in[6];
    const float* attn_lB = (const float*)d_in[7];
    const float* proj_w  = (const float*)d_in[8];
    const float* proj_lA = (const float*)d_in[9];
    const float* proj_lB = (const float*)d_in[10];
    const float* ln2_g   = (const float*)d_in[11];
    const float* ln2_b   = (const float*)d_in[12];
    const float* fc_w    = (const float*)d_in[13];
    const float* fc_b    = (const float*)d_in[14];
    const float* mproj_w = (const float*)d_in[15];
    const float* mproj_b = (const float*)d_in[16];
    const float* lnf_g   = (const float*)d_in[17];
    const float* lnf_b   = (const float*)d_in[18];
    const float* head_w  = (const float*)d_in[19];
    float* out = (float*)d_out;

    float *X, *YH, *TMP, *QKVp;
    cudaGetSymbolAddress((void**)&X,    g_X);
    cudaGetSymbolAddress((void**)&YH,   g_YH);
    cudaGetSymbolAddress((void**)&TMP,  g_TMP);
    cudaGetSymbolAddress((void**)&QKVp, g_QKVp);

    __half *wqkv16, *wproj16, *wfc16, *wmp16, *whead16,
           *H16h, *H16l, *Y16h, *Y16l, *FCG16h,
           *Q16, *K16, *V16t;
    cudaGetSymbolAddress((void**)&wqkv16,  g_wqkv16);
    cudaGetSymbolAddress((void**)&wproj16, g_wproj16);
    cudaGetSymbolAddress((void**)&wfc16,   g_wfc16);
    cudaGetSymbolAddress((void**)&wmp16,   g_wmp16);
    cudaGetSymbolAddress((void**)&whead16, g_whead16);
    cudaGetSymbolAddress((void**)&H16h, g_H16h); cudaGetSymbolAddress((void**)&H16l, g_H16l);
    cudaGetSymbolAddress((void**)&Y16h, g_Y16h); cudaGetSymbolAddress((void**)&Y16l, g_Y16l);
    cudaGetSymbolAddress((void**)&FCG16h, g_FCG16h);
    cudaGetSymbolAddress((void**)&Q16, g_Q16);
    cudaGetSymbolAddress((void**)&K16, g_K16);
    cudaGetSymbolAddress((void**)&V16t, g_V16t);

    cudaFuncSetAttribute(flash_attn, cudaFuncAttributeMaxDynamicSharedMemorySize, FA_SMEM);

    detect_idx_kernel<<<1, 256>>>((const unsigned int*)idx);
    embed_kernel<<<(MTOK*CDIM + 255)/256, 256>>>(idx, wte, wpe, X);
    {
        int nA = NLAYER*(3*CDIM*CDIM + CDIM*CDIM + 4*CDIM*CDIM + 4*CDIM*CDIM);
        wcvt16_kernel<<<(nA/4 + 255)/256, 256>>>(attn_w, proj_w, fc_w, mproj_w,
            wqkv16, wproj16, wfc16, wmp16);
        int nB = VOCAB*CDIM;
        wsplit_f16_kernel<<<(nB/4 + 255)/256, 256>>>(head_w, whead16, nB);
    }

    for (int l = 0; l < NLAYER; l++) {
        long long oq = (long long)l * 3*CDIM*CDIM;
        long long op = (long long)l * CDIM*CDIM;
        long long of = (long long)l * 4*CDIM*CDIM;
        long long om = (long long)l * CDIM*4*CDIM;
        const float* lA_q = attn_lA + (long long)l * RANK*CDIM;
        const float* lB_q = attn_lB + (long long)l * 3*CDIM*RANK;
        const float* lA_p = proj_lA + (long long)l * RANK*CDIM;
        const float* lB_p = proj_lB + (long long)l * CDIM*RANK;

        // ---- attention ----
        ln_lora_kernel<<<MTOK, 128>>>(X, ln1_g + l*CDIM, ln1_b + l*CDIM, lA_q, H16h, H16l, TMP);
        // qkv: 2-term, split-K=2 into dual fp32 partial buffers
        launch_gemm_h<0, 1, 2>(dim3(MTOK/128, 3*CDIM/128, 2),
            H16h, H16l, wqkv16 + oq, nullptr, TMP, lB_q, QKVp,
            MTOK, 3*CDIM, CDIM);
        split_qkv2_kernel<<<(NBATCH*TLEN*HD + 255)/256, 256>>>(QKVp);

        flash_attn<<<dim3(TLEN/128, NBATCH), 256, FA_SMEM>>>(Q16, K16, V16t, YH);
        merge_lora_kernel<<<MTOK, 128>>>(YH, lA_p, Y16h, Y16l, TMP);

        // proj: 2-term, split-K=2 atomic residual into X
        launch_gemm_h<2, 1, 2>(dim3(MTOK/128, CDIM/128, 2),
            Y16h, Y16l, wproj16 + op, nullptr, TMP, lB_p, X,
            MTOK, CDIM, CDIM);

        // ---- MLP ----
        ln_lora_kernel<<<MTOK, 128>>>(X, ln2_g + l*CDIM, ln2_b + l*CDIM, nullptr, H16h, nullptr, TMP);
        // fc: 1-term (A hi only)
        launch_gemm_h<1, 0, 1>(dim3(MTOK/128, 4*CDIM/128, 1),
            H16h, nullptr, wfc16 + of, fc_b + (long long)l*4*CDIM, nullptr, nullptr, nullptr,
            MTOK, 4*CDIM, CDIM);
        // mproj: 1-term, split-K=2 atomic residual into X
        launch_gemm_h<2, 1, 1>(dim3(MTOK/128, CDIM/128, 2),
            FCG16h, nullptr, wmp16 + om, mproj_b + (long long)l*CDIM, nullptr, nullptr, X,
            MTOK, CDIM, 4*CDIM);
    }

    // ---- final layernorm + fp16 1-MMA vocab head ----
    ln_f16_kernel<<<MTOK, 128>>>(X, lnf_g, lnf_b, H16h);
    cudaFuncSetAttribute(mma_gemm_f16, cudaFuncAttributeMaxDynamicSharedMemorySize, GEMM_SMEM_F16);
    mma_gemm_f16<<<dim3(MTOK/128, (VOCAB + 127)/128), 256, GEMM_SMEM_F16>>>(
        H16h, whead16, out, MTOK, VOCAB, CDIM);
}